// round 8
// baseline (speedup 1.0000x reference)
#include <cuda_runtime.h>
#include <math.h>
#include <stdint.h>

#define MAXN 50000
#define MAXE 100000
#define MAXG 4096

typedef unsigned long long ull;

extern __shared__ __align__(1024) char smem_raw[];

// ---------------- device scratch -------------------------------------------
__device__ float g_h[MAXN * 64];
__device__ float g_agg[MAXN * 64];   // zeroed at load; node_mma re-zeroes after consume
__device__ float g_rdeg[MAXN];
__device__ float g_cnt[MAXG];
__device__ ull   g_pk_node[14336];
__device__ ull   g_pk_init[6144];
__device__ float g_bias_node[320];
__device__ float g_bias_init[128];

__device__ __forceinline__ float sigf_(float x)   { return 1.0f / (1.0f + __expf(-x)); }
__device__ __forceinline__ float tanhf_(float x)  { return 2.0f * sigf_(2.0f * x) - 1.0f; }
__device__ __forceinline__ float leakyf_(float x) { return x > 0.0f ? x : 0.01f * x; }

__device__ __forceinline__ uint32_t tf32_(float x) {
    uint32_t r; asm("cvt.rna.tf32.f32 %0, %1;" : "=r"(r) : "f"(x)); return r;
}
__device__ __forceinline__ void barp_(int id) {
    asm volatile("bar.sync %0, 64;" :: "r"(id) : "memory");
}

// m16n8k8 tf32 MMA (portable PTX)
__device__ __forceinline__ void mma8(float* c, const uint32_t* a, ull b) {
    uint32_t b0 = (uint32_t)b, b1 = (uint32_t)(b >> 32);
    asm volatile(
        "mma.sync.aligned.m16n8k8.row.col.f32.tf32.tf32.f32 "
        "{%0,%1,%2,%3}, {%4,%5,%6,%7}, {%8,%9}, {%0,%1,%2,%3};"
        : "+f"(c[0]), "+f"(c[1]), "+f"(c[2]), "+f"(c[3])
        : "r"(a[0]), "r"(a[1]), "r"(a[2]), "r"(a[3]), "r"(b0), "r"(b1));
}

__device__ __forceinline__ int pos_(int f) {
    return (f & ~7) | ((f & 3) << 1) | ((f >> 2) & 1);
}
__device__ __forceinline__ void load_afrag2(uint32_t* a, const ull* base, int arow, int kq, int strideq) {
    ull p0 = base[arow * strideq + kq];
    ull p1 = base[(arow + 8) * strideq + kq];
    a[0] = (uint32_t)p0; a[2] = (uint32_t)(p0 >> 32);
    a[1] = (uint32_t)p1; a[3] = (uint32_t)(p1 >> 32);
}

#define A_ROOT 0
#define A_IHR  1
#define A_HHR  2
#define A_IHZ  3
#define A_HHZ  4
#define A_IHN  5
#define A_HHN  6
#define PK_FLOATS   28672                      // 14336 ull
#define NODE_SMEM   ((PK_FLOATS + 16896 + 320) * 4)
#define INIT_SMEM   (37760 * 4)

// ---------------- pack kernel ------------------------------------------------
__global__ void pack_kernel(
    const float* __restrict__ root, const float* __restrict__ cb,
    const float* __restrict__ wih, const float* __restrict__ whh,
    const float* __restrict__ bih, const float* __restrict__ bhh,
    const float* __restrict__ w1, const float* __restrict__ b1,
    const float* __restrict__ w2, const float* __restrict__ b2)
{
    for (int i = blockIdx.x * blockDim.x + threadIdx.x; i < 21024; i += gridDim.x * blockDim.x) {
        if (i < 14336) {
            int arr = i >> 11, rem = i & 2047;
            int hf = rem >> 10, nt = (rem >> 8) & 3, kk = (rem >> 5) & 7, ln = rem & 31;
            int k0 = kk * 8 + (ln & 3), k1 = k0 + 4;
            int nn = hf * 32 + nt * 8 + (ln >> 2);
            float w0, w1v;
            switch (arr) {
                case A_ROOT: w0 = root[k0 * 64 + nn];         w1v = root[k1 * 64 + nn];         break;
                case A_IHR:  w0 = wih[nn * 64 + k0];          w1v = wih[nn * 64 + k1];          break;
                case A_HHR:  w0 = whh[nn * 64 + k0];          w1v = whh[nn * 64 + k1];          break;
                case A_IHZ:  w0 = wih[(64 + nn) * 64 + k0];   w1v = wih[(64 + nn) * 64 + k1];   break;
                case A_HHZ:  w0 = whh[(64 + nn) * 64 + k0];   w1v = whh[(64 + nn) * 64 + k1];   break;
                case A_IHN:  w0 = wih[(128 + nn) * 64 + k0];  w1v = wih[(128 + nn) * 64 + k1];  break;
                default:     w0 = whh[(128 + nn) * 64 + k0];  w1v = whh[(128 + nn) * 64 + k1];  break;
            }
            g_pk_node[i] = (ull)tf32_(w0) | ((ull)tf32_(w1v) << 32);
        } else if (i < 18432) {
            int j = i - 14336;
            int hf = j >> 11, nt = (j >> 9) & 3, kk = (j >> 5) & 15, ln = j & 31;
            int k0 = kk * 8 + (ln & 3), nn = hf * 32 + nt * 8 + (ln >> 2);
            g_pk_init[j] = (ull)tf32_(w1[nn * 128 + k0]) | ((ull)tf32_(w1[nn * 128 + k0 + 4]) << 32);
        } else if (i < 20480) {
            int j = i - 18432;
            int hf = j >> 10, nt = (j >> 8) & 3, kk = (j >> 5) & 7, ln = j & 31;
            int k0 = kk * 8 + (ln & 3), nn = hf * 32 + nt * 8 + (ln >> 2);
            g_pk_init[4096 + j] = (ull)tf32_(w2[nn * 64 + k0]) | ((ull)tf32_(w2[nn * 64 + k0 + 4]) << 32);
        } else if (i < 20800) {
            int j = i - 20480;
            float v;
            if (j < 128)      v = bih[j] + bhh[j];
            else if (j < 192) v = bih[128 + (j - 128)];
            else if (j < 256) v = bhh[128 + (j - 192)];
            else              v = cb[j - 256];
            g_bias_node[j] = v;
        } else {
            int j = i - 20800;
            g_bias_init[j] = (j < 64) ? b1[j] : b2[j - 64];
        }
    }
}

// ---------------- degree ----------------------------------------------------
__global__ void deg_kernel(const int* __restrict__ ei, float* __restrict__ deg, int E) {
    int e = blockIdx.x * blockDim.x + threadIdx.x;
    if (e < E) atomicAdd(&deg[ei[E + e]], 1.0f);
}
__global__ void rdeg_kernel(float* deg, int n) {
    int i = blockIdx.x * blockDim.x + threadIdx.x;
    if (i < n) deg[i] = 1.0f / fmaxf(deg[i], 1.0f);
}

// ---------------- init MLP: warp-pair mma.sync tf32 ---------------------------
__global__ void __launch_bounds__(512, 1) init_mma(
    const int* __restrict__ x, const int* __restrict__ batch,
    const float* __restrict__ vec, const float* __restrict__ blockemb,
    float* __restrict__ h, int n)
{
    float* smf = (float*)smem_raw;
    ull* w1pk = (ull*)smf;                          // [4096]
    ull* w2pk = w1pk + 4096;                        // [2048]
    uint32_t* in_u = (uint32_t*)smf + 12288;        // [8][16][132]
    uint32_t* o1_u = in_u + 16896;                  // [8][16][66]
    float* b1s = smf + 37632;
    float* b2s = b1s + 64;

    const int tid  = threadIdx.x;
    const int w    = tid >> 5;
    const int lane = tid & 31;
    const int p    = w & 7;
    const int half = w >> 3;
    const int n0   = half * 32;
    const int arow = lane >> 2;

    for (int i = tid; i < 6144; i += 512) w1pk[i] = g_pk_init[i];
    if (tid < 128) b1s[tid] = g_bias_init[tid];
    __syncthreads();

    uint32_t* inp = in_u + p * 2112;
    uint32_t* o1p = o1_u + p * 1056;
    const ull* inq = (const ull*)inp;
    const ull* o1q = (const ull*)o1p;
    const int bar = p + 1;

    const int nchunks = (n + 15) >> 4;
    for (int c = blockIdx.x * 8 + p; c < nchunks; c += gridDim.x * 8) {
        const int gb = c << 4;

        // each warp loads 8 rows (local rows half*8..+8), 128 cols
        {
            int lr = half * 8 + (lane >> 2), gr = gb + lr;
            int cpart = (lane & 3) * 32;
            uint32_t* ir = inp + lr * 132;
            if (gr < n) {
                const float* src = (cpart < 64)
                    ? (blockemb + (size_t)x[gr] * 64 + cpart)
                    : (vec + (size_t)batch[gr] * 64 + (cpart - 64));
                #pragma unroll
                for (int ci = 0; ci < 8; ci++) {
                    float4 q = ((const float4*)src)[ci];
                    int f = cpart + ci * 4;
                    ir[pos_(f)]     = tf32_(q.x);
                    ir[pos_(f + 1)] = tf32_(q.y);
                    ir[pos_(f + 2)] = tf32_(q.z);
                    ir[pos_(f + 3)] = tf32_(q.w);
                }
            } else {
                #pragma unroll
                for (int ci = 0; ci < 32; ci++) ir[pos_(cpart + ci)] = 0u;
            }
        }
        barp_(bar);

        float racc[16];
        #pragma unroll
        for (int t = 0; t < 16; t++) racc[t] = 0.0f;
        #pragma unroll
        for (int kk = 0; kk < 16; kk++) {
            uint32_t a[4];
            load_afrag2(a, inq, arow, kk * 4 + (lane & 3), 66);
            #pragma unroll
            for (int nt = 0; nt < 4; nt++)
                mma8(racc + nt * 4, a, w1pk[half * 2048 + nt * 512 + kk * 32 + lane]);
        }
        #pragma unroll
        for (int nt = 0; nt < 4; nt++) {
            int colb = n0 + nt * 8 + (lane & 3) * 2;
            float c0 = b1s[colb], c1 = b1s[colb + 1];
            #pragma unroll
            for (int q = 0; q < 2; q++) {
                int row = arow + q * 8;
                o1p[row * 66 + pos_(colb)]     = tf32_(leakyf_(racc[nt * 4 + q * 2]     + c0));
                o1p[row * 66 + pos_(colb + 1)] = tf32_(leakyf_(racc[nt * 4 + q * 2 + 1] + c1));
            }
        }
        barp_(bar);

        float acc2[16];
        #pragma unroll
        for (int t = 0; t < 16; t++) acc2[t] = 0.0f;
        #pragma unroll
        for (int kk = 0; kk < 8; kk++) {
            uint32_t a[4];
            load_afrag2(a, o1q, arow, kk * 4 + (lane & 3), 33);
            #pragma unroll
            for (int nt = 0; nt < 4; nt++)
                mma8(acc2 + nt * 4, a, w2pk[half * 1024 + nt * 256 + kk * 32 + lane]);
        }
        #pragma unroll
        for (int nt = 0; nt < 4; nt++) {
            int colb = n0 + nt * 8 + (lane & 3) * 2;
            float c0 = b2s[colb], c1 = b2s[colb + 1];
            #pragma unroll
            for (int q = 0; q < 2; q++) {
                int gr = gb + arow + q * 8;
                if (gr < n)
                    *(float2*)(h + (size_t)gr * 64 + colb) =
                        make_float2(acc2[nt * 4 + q * 2] + c0, acc2[nt * 4 + q * 2 + 1] + c1);
            }
        }
        barp_(bar);   // protect in/o1 regions before next chunk
    }
}

// ---------------- edge kernel: 4 lanes/edge ------------------------------------
__global__ void edge_kernel(const int* __restrict__ ei, const int* __restrict__ ea,
                            const float* __restrict__ bond, const float* __restrict__ h,
                            const float* __restrict__ rdeg,
                            float* __restrict__ agg, int E)
{
    int idx = blockIdx.x * blockDim.x + threadIdx.x;
    int e = idx >> 2;
    int l = idx & 3;
    bool valid = (e < E);
    int ec = valid ? e : (E - 1);
    int src = ei[ec], dst = ei[E + ec];
    int a0  = ea[2 * ec], a1 = ea[2 * ec + 1];
    const float4* hp = (const float4*)(h + (size_t)src * 64 + 16 * l);
    const float4* b0 = (const float4*)(bond + (size_t)a0 * 64 + 16 * l);
    float s = 0.0f;
    #pragma unroll
    for (int c = 0; c < 4; c++) {
        float4 hv = hp[c], e0 = b0[c];
        s += hv.x * e0.x + hv.y * e0.y + hv.z * e0.z + hv.w * e0.w;
    }
    s += __shfl_xor_sync(0xffffffffu, s, 1);
    s += __shfl_xor_sync(0xffffffffu, s, 2);
    s *= __ldg(&rdeg[dst]);
    const float4* b1 = (const float4*)(bond + (size_t)a1 * 64 + 16 * l);
    if (valid) {
        float* ap = agg + (size_t)dst * 64 + 16 * l;
        #pragma unroll
        for (int c = 0; c < 4; c++) {
            float4 ev = b1[c];
            asm volatile("red.global.add.v4.f32 [%0], {%1,%2,%3,%4};"
                         :: "l"(ap + 4 * c), "f"(s * ev.x), "f"(s * ev.y), "f"(s * ev.z), "f"(s * ev.w)
                         : "memory");
        }
    }
}

// ---------------- node kernel: warp-pair mma.sync tf32 -------------------------
__global__ void __launch_bounds__(512, 1) node_mma(
    float* __restrict__ agg,
    float* __restrict__ h, int n)
{
    float* smf = (float*)smem_raw;
    ull*   pk  = (ull*)smf;
    uint32_t* h_u = (uint32_t*)smf + PK_FLOATS;   // [8][16][66]
    uint32_t* m_u = h_u + 8448;                   // [8][16][66]
    float* br_s  = smf + PK_FLOATS + 16896;
    float* bz_s  = br_s + 64;
    float* bin_s = bz_s + 64;
    float* bhn_s = bin_s + 64;
    float* cb_s  = bhn_s + 64;

    const int tid  = threadIdx.x;
    const int w    = tid >> 5;
    const int lane = tid & 31;
    const int p    = w & 7;
    const int half = w >> 3;
    const int n0   = half * 32;
    const int arow = lane >> 2;

    for (int i = tid; i < 14336; i += 512) pk[i] = g_pk_node[i];
    if (tid < 320) br_s[tid] = g_bias_node[tid];
    __syncthreads();

    uint32_t* hp_u = h_u + p * 1056;
    uint32_t* mp_u = m_u + p * 1056;
    const ull* hq = (const ull*)hp_u;
    const ull* mq = (const ull*)mp_u;
    const int bar = p + 1;

    const int nchunks = (n + 15) >> 4;
    for (int c = blockIdx.x * 8 + p; c < nchunks; c += gridDim.x * 8) {
        const int gb = c << 4;

        // each warp loads 8 rows (local rows half*8..+8)
        {
            int lr = half * 8 + (lane >> 2), gr = gb + lr;
            int cbase = (lane & 3) * 16;
            uint32_t* hr = hp_u + lr * 66;
            if (gr < n) {
                const float4* pp = (const float4*)(h + (size_t)gr * 64 + cbase);
                #pragma unroll
                for (int ci = 0; ci < 4; ci++) {
                    float4 q = pp[ci];
                    int f = cbase + ci * 4;
                    hr[pos_(f)]     = tf32_(q.x);
                    hr[pos_(f + 1)] = tf32_(q.y);
                    hr[pos_(f + 2)] = tf32_(q.z);
                    hr[pos_(f + 3)] = tf32_(q.w);
                }
            } else {
                #pragma unroll
                for (int t = 0; t < 16; t++) hr[pos_(cbase + t)] = 0u;
            }
        }
        barp_(bar);

        // prefetch agg (fp32) + zero for next step
        float2 agf[8];
        #pragma unroll
        for (int nt = 0; nt < 4; nt++) {
            int colb = n0 + nt * 8 + (lane & 3) * 2;
            #pragma unroll
            for (int q = 0; q < 2; q++) {
                int gr = gb + arow + q * 8;
                if (gr < n) {
                    float2* ap = (float2*)(agg + (size_t)gr * 64 + colb);
                    agf[nt * 2 + q] = *ap;
                    *ap = make_float2(0.0f, 0.0f);
                } else {
                    agf[nt * 2 + q] = make_float2(0.0f, 0.0f);
                }
            }
        }

        // GEMM1: R = H @ root
        float racc[16];
        #pragma unroll
        for (int t = 0; t < 16; t++) racc[t] = 0.0f;
        #pragma unroll
        for (int kk = 0; kk < 8; kk++) {
            uint32_t a[4];
            load_afrag2(a, hq, arow, kk * 4 + (lane & 3), 33);
            #pragma unroll
            for (int nt = 0; nt < 4; nt++)
                mma8(racc + nt * 4, a, pk[A_ROOT * 2048 + half * 1024 + nt * 256 + kk * 32 + lane]);
        }
        #pragma unroll
        for (int nt = 0; nt < 4; nt++) {
            int colb = n0 + nt * 8 + (lane & 3) * 2;
            float cb0 = cb_s[colb], cb1 = cb_s[colb + 1];
            #pragma unroll
            for (int q = 0; q < 2; q++) {
                int row = arow + q * 8;
                float2 ag = agf[nt * 2 + q];
                mp_u[row * 66 + pos_(colb)]     = tf32_(leakyf_(racc[nt * 4 + q * 2]     + ag.x + cb0));
                mp_u[row * 66 + pos_(colb + 1)] = tf32_(leakyf_(racc[nt * 4 + q * 2 + 1] + ag.y + cb1));
            }
        }
        barp_(bar);

        // prefetch h_old (fp32)
        float2 hof[8];
        #pragma unroll
        for (int nt = 0; nt < 4; nt++) {
            int colb = n0 + nt * 8 + (lane & 3) * 2;
            #pragma unroll
            for (int q = 0; q < 2; q++) {
                int gr = gb + arow + q * 8;
                hof[nt * 2 + q] = (gr < n) ? *(const float2*)(h + (size_t)gr * 64 + colb)
                                           : make_float2(0.0f, 0.0f);
            }
        }

        // GEMM2: gates
        float rg[16], zg[16], ig[16], hg[16];
        #pragma unroll
        for (int t = 0; t < 16; t++) { rg[t] = zg[t] = ig[t] = hg[t] = 0.0f; }
        #pragma unroll
        for (int kk = 0; kk < 8; kk++) {
            uint32_t aM[4], aH[4];
            int kq = kk * 4 + (lane & 3);
            load_afrag2(aM, mq, arow, kq, 33);
            load_afrag2(aH, hq, arow, kq, 33);
            int pkb = half * 1024 + kk * 32 + lane;
            #pragma unroll
            for (int nt = 0; nt < 4; nt++) {
                int o = pkb + nt * 256;
                mma8(rg + nt * 4, aM, pk[A_IHR * 2048 + o]);
                mma8(rg + nt * 4, aH, pk[A_HHR * 2048 + o]);
                mma8(zg + nt * 4, aM, pk[A_IHZ * 2048 + o]);
                mma8(zg + nt * 4, aH, pk[A_HHZ * 2048 + o]);
                mma8(ig + nt * 4, aM, pk[A_IHN * 2048 + o]);
                mma8(hg + nt * 4, aH, pk[A_HHN * 2048 + o]);
            }
        }

        // epilogue: GRU gate math
        #pragma unroll
        for (int nt = 0; nt < 4; nt++) {
            int colb = n0 + nt * 8 + (lane & 3) * 2;
            float br0 = br_s[colb], br1 = br_s[colb + 1];
            float bz0 = bz_s[colb], bz1 = bz_s[colb + 1];
            float bi0 = bin_s[colb], bi1 = bin_s[colb + 1];
            float bh0 = bhn_s[colb], bh1 = bhn_s[colb + 1];
            #pragma unroll
            for (int q = 0; q < 2; q++) {
                int gr = gb + arow + q * 8;
                if (gr < n) {
                    int idx = nt * 4 + q * 2;
                    float2 ho = hof[nt * 2 + q];
                    float r0v = sigf_(rg[idx]     + br0);
                    float r1v = sigf_(rg[idx + 1] + br1);
                    float z0v = sigf_(zg[idx]     + bz0);
                    float z1v = sigf_(zg[idx + 1] + bz1);
                    float n0v = tanhf_(ig[idx]     + bi0 + r0v * (hg[idx]     + bh0));
                    float n1v = tanhf_(ig[idx + 1] + bi1 + r1v * (hg[idx + 1] + bh1));
                    float2 o;
                    o.x = (1.0f - z0v) * n0v + z0v * ho.x;
                    o.y = (1.0f - z1v) * n1v + z1v * ho.y;
                    *(float2*)(h + (size_t)gr * 64 + colb) = o;
                }
            }
        }
        barp_(bar);   // protect h/m regions before next chunk overwrite
    }
}

// ---------------- pooling ------------------------------------------------------
__global__ void pool_kernel(const float* __restrict__ h, const int* __restrict__ batch,
                            float* __restrict__ out, float* __restrict__ cnt, int n)
{
    int idx = blockIdx.x * blockDim.x + threadIdx.x;
    int nn = idx >> 4, l = idx & 15;
    if (nn >= n) return;
    int g = batch[nn];
    float4 v = *(const float4*)(h + (size_t)nn * 64 + 4 * l);
    float* op = out + (size_t)g * 64 + 4 * l;
    asm volatile("red.global.add.v4.f32 [%0], {%1,%2,%3,%4};"
                 :: "l"(op), "f"(v.x), "f"(v.y), "f"(v.z), "f"(v.w) : "memory");
    if (l == 0) atomicAdd(&cnt[g], 1.0f);
}
__global__ void div_kernel(float* out, const float* __restrict__ cnt, int total)
{
    int i = blockIdx.x * blockDim.x + threadIdx.x;
    if (i < total) out[i] /= fmaxf(cnt[i >> 6], 1.0f);
}

// ---------------- launch --------------------------------------------------------
extern "C" void kernel_launch(void* const* d_in, const int* in_sizes, int n_in,
                              void* d_out, int out_size)
{
    const int*   x        = (const int*)d_in[0];
    const int*   ei       = (const int*)d_in[1];
    const int*   ea       = (const int*)d_in[2];
    const int*   batch    = (const int*)d_in[3];
    const float* vec      = (const float*)d_in[4];
    const float* blockemb = (const float*)d_in[5];
    const float* bondemb  = (const float*)d_in[6];
    const float* w1       = (const float*)d_in[7];
    const float* b1       = (const float*)d_in[8];
    const float* w2       = (const float*)d_in[9];
    const float* b2       = (const float*)d_in[10];
    const float* root     = (const float*)d_in[11];
    const float* cb       = (const float*)d_in[12];
    const float* wih      = (const float*)d_in[13];
    const float* whh      = (const float*)d_in[14];
    const float* bih      = (const float*)d_in[15];
    const float* bhh      = (const float*)d_in[16];

    const int n = in_sizes[0];
    const int E = in_sizes[1] / 2;
    const int G = in_sizes[4] / 64;

    float *h_p, *agg_p, *rdeg_p, *cnt_p;
    cudaGetSymbolAddress((void**)&h_p,    g_h);
    cudaGetSymbolAddress((void**)&agg_p,  g_agg);
    cudaGetSymbolAddress((void**)&rdeg_p, g_rdeg);
    cudaGetSymbolAddress((void**)&cnt_p,  g_cnt);

    cudaFuncSetAttribute(init_mma, cudaFuncAttributeMaxDynamicSharedMemorySize, INIT_SMEM);
    cudaFuncSetAttribute(node_mma, cudaFuncAttributeMaxDynamicSharedMemorySize, NODE_SMEM);

    cudaMemsetAsync(rdeg_p, 0, (size_t)n * sizeof(float));
    cudaMemsetAsync(cnt_p,  0, (size_t)G * sizeof(float));
    cudaMemsetAsync(d_out,  0, (size_t)out_size * sizeof(float));

    pack_kernel<<<42, 512>>>(root, cb, wih, whh, bih, bhh, w1, b1, w2, b2);
    deg_kernel<<<(E + 255) / 256, 256>>>(ei, rdeg_p, E);
    rdeg_kernel<<<(n + 255) / 256, 256>>>(rdeg_p, n);

    init_mma<<<148, 512, INIT_SMEM>>>(x, batch, vec, blockemb, h_p, n);

    for (int s = 0; s < 4; s++) {
        edge_kernel<<<(E * 4 + 255) / 256, 256>>>(ei, ea, bondemb, h_p, rdeg_p, agg_p, E);
        node_mma<<<148, 512, NODE_SMEM>>>(agg_p, h_p, n);
    }

    pool_kernel<<<(n * 16 + 255) / 256, 256>>>(h_p, batch, (float*)d_out, cnt_p, n);
    div_kernel<<<(G * 64 + 255) / 256, 256>>>((float*)d_out, cnt_p, G * 64);
}

// round 9
// speedup vs baseline: 1.0005x; 1.0005x over previous
#include <cuda_runtime.h>
#include <math.h>
#include <stdint.h>

#define MAXN 50000
#define MAXE 100000
#define MAXG 4096

typedef unsigned long long ull;

extern __shared__ __align__(1024) char smem_raw[];

// ---------------- device scratch -------------------------------------------
__device__ float g_h[MAXN * 64];
__device__ float g_agg[MAXN * 64];   // zeroed at load; node_mma re-zeroes after consume
__device__ float g_rdeg[MAXN];
__device__ float g_cnt[MAXG];
__device__ ull   g_pk_node[14336];
__device__ ull   g_pk_init[6144];
__device__ float g_bias_node[320];
__device__ float g_bias_init[128];

__device__ __forceinline__ float sigf_(float x)   { return 1.0f / (1.0f + __expf(-x)); }
__device__ __forceinline__ float tanhf_(float x)  { return 2.0f * sigf_(2.0f * x) - 1.0f; }
__device__ __forceinline__ float leakyf_(float x) { return x > 0.0f ? x : 0.01f * x; }

__device__ __forceinline__ uint32_t tf32_(float x) {
    uint32_t r; asm("cvt.rna.tf32.f32 %0, %1;" : "=r"(r) : "f"(x)); return r;
}

// m16n8k8 tf32 MMA (portable PTX)
__device__ __forceinline__ void mma8(float* c, const uint32_t* a, ull b) {
    uint32_t b0 = (uint32_t)b, b1 = (uint32_t)(b >> 32);
    asm volatile(
        "mma.sync.aligned.m16n8k8.row.col.f32.tf32.tf32.f32 "
        "{%0,%1,%2,%3}, {%4,%5,%6,%7}, {%8,%9}, {%0,%1,%2,%3};"
        : "+f"(c[0]), "+f"(c[1]), "+f"(c[2]), "+f"(c[3])
        : "r"(a[0]), "r"(a[1]), "r"(a[2]), "r"(a[3]), "r"(b0), "r"(b1));
}

__device__ __forceinline__ int pos_(int f) {
    return (f & ~7) | ((f & 3) << 1) | ((f >> 2) & 1);
}
__device__ __forceinline__ void load_afrag2(uint32_t* a, const ull* base, int arow, int kq, int strideq) {
    ull p0 = base[arow * strideq + kq];
    ull p1 = base[(arow + 8) * strideq + kq];
    a[0] = (uint32_t)p0; a[2] = (uint32_t)(p0 >> 32);
    a[1] = (uint32_t)p1; a[3] = (uint32_t)(p1 >> 32);
}

#define A_ROOT 0
#define A_IHR  1
#define A_HHR  2
#define A_IHZ  3
#define A_HHZ  4
#define A_IHN  5
#define A_HHN  6
#define PK_FLOATS   28672                       // 14336 ull
#define NODE_SMEM   ((PK_FLOATS + 2 * 128 * 66 + 320) * 4)
#define INIT_SMEM   (37760 * 4)

// ---------------- pack kernel ------------------------------------------------
__global__ void pack_kernel(
    const float* __restrict__ root, const float* __restrict__ cb,
    const float* __restrict__ wih, const float* __restrict__ whh,
    const float* __restrict__ bih, const float* __restrict__ bhh,
    const float* __restrict__ w1, const float* __restrict__ b1,
    const float* __restrict__ w2, const float* __restrict__ b2)
{
    for (int i = blockIdx.x * blockDim.x + threadIdx.x; i < 21024; i += gridDim.x * blockDim.x) {
        if (i < 14336) {
            int arr = i >> 11, rem = i & 2047;
            int hf = rem >> 10, nt = (rem >> 8) & 3, kk = (rem >> 5) & 7, ln = rem & 31;
            int k0 = kk * 8 + (ln & 3), k1 = k0 + 4;
            int nn = hf * 32 + nt * 8 + (ln >> 2);
            float w0, w1v;
            switch (arr) {
                case A_ROOT: w0 = root[k0 * 64 + nn];         w1v = root[k1 * 64 + nn];         break;
                case A_IHR:  w0 = wih[nn * 64 + k0];          w1v = wih[nn * 64 + k1];          break;
                case A_HHR:  w0 = whh[nn * 64 + k0];          w1v = whh[nn * 64 + k1];          break;
                case A_IHZ:  w0 = wih[(64 + nn) * 64 + k0];   w1v = wih[(64 + nn) * 64 + k1];   break;
                case A_HHZ:  w0 = whh[(64 + nn) * 64 + k0];   w1v = whh[(64 + nn) * 64 + k1];   break;
                case A_IHN:  w0 = wih[(128 + nn) * 64 + k0];  w1v = wih[(128 + nn) * 64 + k1];  break;
                default:     w0 = whh[(128 + nn) * 64 + k0];  w1v = whh[(128 + nn) * 64 + k1];  break;
            }
            g_pk_node[i] = (ull)tf32_(w0) | ((ull)tf32_(w1v) << 32);
        } else if (i < 18432) {
            int j = i - 14336;
            int hf = j >> 11, nt = (j >> 9) & 3, kk = (j >> 5) & 15, ln = j & 31;
            int k0 = kk * 8 + (ln & 3), nn = hf * 32 + nt * 8 + (ln >> 2);
            g_pk_init[j] = (ull)tf32_(w1[nn * 128 + k0]) | ((ull)tf32_(w1[nn * 128 + k0 + 4]) << 32);
        } else if (i < 20480) {
            int j = i - 18432;
            int hf = j >> 10, nt = (j >> 8) & 3, kk = (j >> 5) & 7, ln = j & 31;
            int k0 = kk * 8 + (ln & 3), nn = hf * 32 + nt * 8 + (ln >> 2);
            g_pk_init[4096 + j] = (ull)tf32_(w2[nn * 64 + k0]) | ((ull)tf32_(w2[nn * 64 + k0 + 4]) << 32);
        } else if (i < 20800) {
            int j = i - 20480;
            float v;
            if (j < 128)      v = bih[j] + bhh[j];
            else if (j < 192) v = bih[128 + (j - 128)];
            else if (j < 256) v = bhh[128 + (j - 192)];
            else              v = cb[j - 256];
            g_bias_node[j] = v;
        } else {
            int j = i - 20800;
            g_bias_init[j] = (j < 64) ? b1[j] : b2[j - 64];
        }
    }
}

// ---------------- degree ----------------------------------------------------
__global__ void deg_kernel(const int* __restrict__ ei, float* __restrict__ deg, int E) {
    int e = blockIdx.x * blockDim.x + threadIdx.x;
    if (e < E) atomicAdd(&deg[ei[E + e]], 1.0f);
}
__global__ void rdeg_kernel(float* deg, int n) {
    int i = blockIdx.x * blockDim.x + threadIdx.x;
    if (i < n) deg[i] = 1.0f / fmaxf(deg[i], 1.0f);
}

// ---------------- init MLP: 1024 thr, 32 warps (8 row-strips x 4 col-quarters)
__global__ void __launch_bounds__(1024, 1) init_mma(
    const int* __restrict__ x, const int* __restrict__ batch,
    const float* __restrict__ vec, const float* __restrict__ blockemb,
    float* __restrict__ h, int n)
{
    float* smf = (float*)smem_raw;
    ull* w1pk = (ull*)smf;                          // [4096]
    ull* w2pk = w1pk + 4096;                        // [2048]
    uint32_t* in_u = (uint32_t*)smf + 12288;        // [128][132] tf32
    uint32_t* o1_u = (uint32_t*)smf + 29184;        // [128][66]  tf32
    float* b1s = smf + 37632;
    float* b2s = b1s + 64;

    const int tid  = threadIdx.x;
    const int w    = tid >> 5;
    const int lane = tid & 31;
    const int p    = w & 7;                // row strip
    const int q    = w >> 3;               // column quarter 0..3
    const int hf   = q >> 1;
    const int ntb  = (q & 1) * 2;
    const int n0   = q * 16;
    const int arow = p * 16 + (lane >> 2);

    for (int i = tid; i < 6144; i += 1024) w1pk[i] = g_pk_init[i];
    if (tid < 128) b1s[tid] = g_bias_init[tid];
    __syncthreads();

    const ull* inq = (const ull*)in_u;
    const ull* o1q = (const ull*)o1_u;

    const int ntiles = (n + 127) >> 7;
    for (int tile = blockIdx.x; tile < ntiles; tile += gridDim.x) {
        const int nb0 = tile << 7;

        // gather [emb | vec] -> permuted tf32 smem: 1024 thr, 16 cols each
        {
            int row = tid >> 3, cpart = (tid & 7) * 16, gr = nb0 + row;
            uint32_t* ir = in_u + row * 132;
            if (gr < n) {
                const float* src = (cpart < 64)
                    ? (blockemb + (size_t)x[gr] * 64 + cpart)
                    : (vec + (size_t)batch[gr] * 64 + (cpart - 64));
                #pragma unroll
                for (int c = 0; c < 4; c++) {
                    float4 qv = ((const float4*)src)[c];
                    int f = cpart + c * 4;
                    ir[pos_(f)]     = tf32_(qv.x);
                    ir[pos_(f + 1)] = tf32_(qv.y);
                    ir[pos_(f + 2)] = tf32_(qv.z);
                    ir[pos_(f + 3)] = tf32_(qv.w);
                }
            } else {
                #pragma unroll
                for (int c = 0; c < 16; c++) ir[pos_(cpart + c)] = 0u;
            }
        }
        __syncthreads();

        // GEMM1: o1 = leaky(in @ w1^T + b1); per warp 16x16
        float racc[8];
        #pragma unroll
        for (int t = 0; t < 8; t++) racc[t] = 0.0f;
        #pragma unroll
        for (int kk = 0; kk < 16; kk++) {
            uint32_t a[4];
            load_afrag2(a, inq, arow, kk * 4 + (lane & 3), 66);
            #pragma unroll
            for (int nt = 0; nt < 2; nt++)
                mma8(racc + nt * 4, a, w1pk[hf * 2048 + (ntb + nt) * 512 + kk * 32 + lane]);
        }
        #pragma unroll
        for (int nt = 0; nt < 2; nt++) {
            int colb = n0 + nt * 8 + (lane & 3) * 2;
            float c0 = b1s[colb], c1 = b1s[colb + 1];
            #pragma unroll
            for (int qq = 0; qq < 2; qq++) {
                int row = arow + qq * 8;
                o1_u[row * 66 + pos_(colb)]     = tf32_(leakyf_(racc[nt * 4 + qq * 2]     + c0));
                o1_u[row * 66 + pos_(colb + 1)] = tf32_(leakyf_(racc[nt * 4 + qq * 2 + 1] + c1));
            }
        }
        __syncthreads();

        // GEMM2: h0 = o1 @ w2^T + b2
        float acc2[8];
        #pragma unroll
        for (int t = 0; t < 8; t++) acc2[t] = 0.0f;
        #pragma unroll
        for (int kk = 0; kk < 8; kk++) {
            uint32_t a[4];
            load_afrag2(a, o1q, arow, kk * 4 + (lane & 3), 33);
            #pragma unroll
            for (int nt = 0; nt < 2; nt++)
                mma8(acc2 + nt * 4, a, w2pk[hf * 1024 + (ntb + nt) * 256 + kk * 32 + lane]);
        }
        #pragma unroll
        for (int nt = 0; nt < 2; nt++) {
            int colb = n0 + nt * 8 + (lane & 3) * 2;
            float c0 = b2s[colb], c1 = b2s[colb + 1];
            #pragma unroll
            for (int qq = 0; qq < 2; qq++) {
                int gr = nb0 + arow + qq * 8;
                if (gr < n)
                    *(float2*)(h + (size_t)gr * 64 + colb) =
                        make_float2(acc2[nt * 4 + qq * 2] + c0, acc2[nt * 4 + qq * 2 + 1] + c1);
            }
        }
        __syncthreads();
    }
}

// ---------------- edge kernel: quarter-warp/edge, vec4 red (R7 form) ---------
__global__ void edge_kernel(const int* __restrict__ ei, const int* __restrict__ ea,
                            const float* __restrict__ bond, const float* __restrict__ h,
                            const float* __restrict__ rdeg,
                            float* __restrict__ agg, int E)
{
    int idx = blockIdx.x * blockDim.x + threadIdx.x;
    int e = idx >> 4;
    int l = idx & 15;
    bool valid = (e < E);
    int ec = valid ? e : (E - 1);
    int src = ei[ec], dst = ei[E + ec];
    int a0  = ea[2 * ec], a1 = ea[2 * ec + 1];
    float4 hv = *(const float4*)(h + (size_t)src * 64 + 4 * l);
    float4 e0 = *(const float4*)(bond + (size_t)a0 * 64 + 4 * l);
    float s = hv.x * e0.x + hv.y * e0.y + hv.z * e0.z + hv.w * e0.w;
    #pragma unroll
    for (int o = 8; o; o >>= 1) s += __shfl_xor_sync(0xffffffffu, s, o);
    s *= __ldg(&rdeg[dst]);
    float4 ev = *(const float4*)(bond + (size_t)a1 * 64 + 4 * l);
    if (valid) {
        float* ap = agg + (size_t)dst * 64 + 4 * l;
        asm volatile("red.global.add.v4.f32 [%0], {%1,%2,%3,%4};"
                     :: "l"(ap), "f"(s * ev.x), "f"(s * ev.y), "f"(s * ev.z), "f"(s * ev.w)
                     : "memory");
    }
}

// ---------------- node kernel: 1024 thr, 32 warps ------------------------------
__global__ void __launch_bounds__(1024, 1) node_mma(
    float* __restrict__ agg,
    float* __restrict__ h, int n)
{
    float* smf = (float*)smem_raw;
    ull*   pk  = (ull*)smf;
    uint32_t* h_u = (uint32_t*)smf + PK_FLOATS;   // [128][66]
    uint32_t* m_u = h_u + 128 * 66;               // [128][66]
    float* br_s  = smf + PK_FLOATS + 2 * 128 * 66;
    float* bz_s  = br_s + 64;
    float* bin_s = bz_s + 64;
    float* bhn_s = bin_s + 64;
    float* cb_s  = bhn_s + 64;

    const int tid  = threadIdx.x;
    const int w    = tid >> 5;
    const int lane = tid & 31;
    const int p    = w & 7;
    const int q    = w >> 3;
    const int hf   = q >> 1;
    const int ntb  = (q & 1) * 2;
    const int n0   = q * 16;
    const int arow = p * 16 + (lane >> 2);

    for (int i = tid; i < 14336; i += 1024) pk[i] = g_pk_node[i];
    if (tid < 320) br_s[tid] = g_bias_node[tid];
    __syncthreads();

    const ull* hq = (const ull*)h_u;
    const ull* mq = (const ull*)m_u;

    const int ntiles = (n + 127) >> 7;
    for (int tile = blockIdx.x; tile < ntiles; tile += gridDim.x) {
        const int nb0 = tile << 7;

        // H tile -> permuted tf32 smem: 1024 thr, 8 cols each
        {
            int row = tid >> 3, cbase = (tid & 7) * 8, gr = nb0 + row;
            uint32_t* hr = h_u + row * 66;
            if (gr < n) {
                const float4* pp = (const float4*)(h + (size_t)gr * 64 + cbase);
                #pragma unroll
                for (int c = 0; c < 2; c++) {
                    float4 qv = pp[c];
                    int f = cbase + c * 4;
                    hr[pos_(f)]     = tf32_(qv.x);
                    hr[pos_(f + 1)] = tf32_(qv.y);
                    hr[pos_(f + 2)] = tf32_(qv.z);
                    hr[pos_(f + 3)] = tf32_(qv.w);
                }
            } else {
                #pragma unroll
                for (int t = 0; t < 8; t++) hr[pos_(cbase + t)] = 0u;
            }
        }
        __syncthreads();

        // prefetch agg (fp32) + zero for next step (per warp 16x16)
        float2 agf[4];
        #pragma unroll
        for (int nt = 0; nt < 2; nt++) {
            int colb = n0 + nt * 8 + (lane & 3) * 2;
            #pragma unroll
            for (int qq = 0; qq < 2; qq++) {
                int gr = nb0 + arow + qq * 8;
                if (gr < n) {
                    float2* ap = (float2*)(agg + (size_t)gr * 64 + colb);
                    agf[nt * 2 + qq] = *ap;
                    *ap = make_float2(0.0f, 0.0f);
                } else {
                    agf[nt * 2 + qq] = make_float2(0.0f, 0.0f);
                }
            }
        }

        // GEMM1: R = H @ root
        float racc[8];
        #pragma unroll
        for (int t = 0; t < 8; t++) racc[t] = 0.0f;
        #pragma unroll
        for (int kk = 0; kk < 8; kk++) {
            uint32_t a[4];
            load_afrag2(a, hq, arow, kk * 4 + (lane & 3), 33);
            #pragma unroll
            for (int nt = 0; nt < 2; nt++)
                mma8(racc + nt * 4, a, pk[A_ROOT * 2048 + hf * 1024 + (ntb + nt) * 256 + kk * 32 + lane]);
        }
        #pragma unroll
        for (int nt = 0; nt < 2; nt++) {
            int colb = n0 + nt * 8 + (lane & 3) * 2;
            float cb0 = cb_s[colb], cb1 = cb_s[colb + 1];
            #pragma unroll
            for (int qq = 0; qq < 2; qq++) {
                int row = arow + qq * 8;
                float2 ag = agf[nt * 2 + qq];
                m_u[row * 66 + pos_(colb)]     = tf32_(leakyf_(racc[nt * 4 + qq * 2]     + ag.x + cb0));
                m_u[row * 66 + pos_(colb + 1)] = tf32_(leakyf_(racc[nt * 4 + qq * 2 + 1] + ag.y + cb1));
            }
        }
        __syncthreads();

        // prefetch h_old (fp32)
        float2 hof[4];
        #pragma unroll
        for (int nt = 0; nt < 2; nt++) {
            int colb = n0 + nt * 8 + (lane & 3) * 2;
            #pragma unroll
            for (int qq = 0; qq < 2; qq++) {
                int gr = nb0 + arow + qq * 8;
                hof[nt * 2 + qq] = (gr < n) ? *(const float2*)(h + (size_t)gr * 64 + colb)
                                            : make_float2(0.0f, 0.0f);
            }
        }

        // GEMM2: gates (per warp 16x16, 6 B arrays)
        float rg[8], zg[8], ig[8], hg[8];
        #pragma unroll
        for (int t = 0; t < 8; t++) { rg[t] = zg[t] = ig[t] = hg[t] = 0.0f; }
        #pragma unroll
        for (int kk = 0; kk < 8; kk++) {
            uint32_t aM[4], aH[4];
            int kq = kk * 4 + (lane & 3);
            load_afrag2(aM, mq, arow, kq, 33);
            load_afrag2(aH, hq, arow, kq, 33);
            int pkb = hf * 1024 + kk * 32 + lane;
            #pragma unroll
            for (int nt = 0; nt < 2; nt++) {
                int o = pkb + (ntb + nt) * 256;
                mma8(rg + nt * 4, aM, pk[A_IHR * 2048 + o]);
                mma8(rg + nt * 4, aH, pk[A_HHR * 2048 + o]);
                mma8(zg + nt * 4, aM, pk[A_IHZ * 2048 + o]);
                mma8(zg + nt * 4, aH, pk[A_HHZ * 2048 + o]);
                mma8(ig + nt * 4, aM, pk[A_IHN * 2048 + o]);
                mma8(hg + nt * 4, aH, pk[A_HHN * 2048 + o]);
            }
        }

        // epilogue: GRU gate math
        #pragma unroll
        for (int nt = 0; nt < 2; nt++) {
            int colb = n0 + nt * 8 + (lane & 3) * 2;
            float br0 = br_s[colb], br1 = br_s[colb + 1];
            float bz0 = bz_s[colb], bz1 = bz_s[colb + 1];
            float bi0 = bin_s[colb], bi1 = bin_s[colb + 1];
            float bh0 = bhn_s[colb], bh1 = bhn_s[colb + 1];
            #pragma unroll
            for (int qq = 0; qq < 2; qq++) {
                int gr = nb0 + arow + qq * 8;
                if (gr < n) {
                    int idx = nt * 4 + qq * 2;
                    float2 ho = hof[nt * 2 + qq];
                    float r0v = sigf_(rg[idx]     + br0);
                    float r1v = sigf_(rg[idx + 1] + br1);
                    float z0v = sigf_(zg[idx]     + bz0);
                    float z1v = sigf_(zg[idx + 1] + bz1);
                    float n0v = tanhf_(ig[idx]     + bi0 + r0v * (hg[idx]     + bh0));
                    float n1v = tanhf_(ig[idx + 1] + bi1 + r1v * (hg[idx + 1] + bh1));
                    float2 o;
                    o.x = (1.0f - z0v) * n0v + z0v * ho.x;
                    o.y = (1.0f - z1v) * n1v + z1v * ho.y;
                    *(float2*)(h + (size_t)gr * 64 + colb) = o;
                }
            }
        }
        __syncthreads();
    }
}

// ---------------- pooling ------------------------------------------------------
__global__ void pool_kernel(const float* __restrict__ h, const int* __restrict__ batch,
                            float* __restrict__ out, float* __restrict__ cnt, int n)
{
    int idx = blockIdx.x * blockDim.x + threadIdx.x;
    int nn = idx >> 4, l = idx & 15;
    if (nn >= n) return;
    int g = batch[nn];
    float4 v = *(const float4*)(h + (size_t)nn * 64 + 4 * l);
    float* op = out + (size_t)g * 64 + 4 * l;
    asm volatile("red.global.add.v4.f32 [%0], {%1,%2,%3,%4};"
                 :: "l"(op), "f"(v.x), "f"(v.y), "f"(v.z), "f"(v.w) : "memory");
    if (l == 0) atomicAdd(&cnt[g], 1.0f);
}
__global__ void div_kernel(float* out, const float* __restrict__ cnt, int total)
{
    int i = blockIdx.x * blockDim.x + threadIdx.x;
    if (i < total) out[i] /= fmaxf(cnt[i >> 6], 1.0f);
}

// ---------------- launch --------------------------------------------------------
extern "C" void kernel_launch(void* const* d_in, const int* in_sizes, int n_in,
                              void* d_out, int out_size)
{
    const int*   x        = (const int*)d_in[0];
    const int*   ei       = (const int*)d_in[1];
    const int*   ea       = (const int*)d_in[2];
    const int*   batch    = (const int*)d_in[3];
    const float* vec      = (const float*)d_in[4];
    const float* blockemb = (const float*)d_in[5];
    const float* bondemb  = (const float*)d_in[6];
    const float* w1       = (const float*)d_in[7];
    const float* b1       = (const float*)d_in[8];
    const float* w2       = (const float*)d_in[9];
    const float* b2       = (const float*)d_in[10];
    const float* root     = (const float*)d_in[11];
    const float* cb       = (const float*)d_in[12];
    const float* wih      = (const float*)d_in[13];
    const float* whh      = (const float*)d_in[14];
    const float* bih      = (const float*)d_in[15];
    const float* bhh      = (const float*)d_in[16];

    const int n = in_sizes[0];
    const int E = in_sizes[1] / 2;
    const int G = in_sizes[4] / 64;

    float *h_p, *agg_p, *rdeg_p, *cnt_p;
    cudaGetSymbolAddress((void**)&h_p,    g_h);
    cudaGetSymbolAddress((void**)&agg_p,  g_agg);
    cudaGetSymbolAddress((void**)&rdeg_p, g_rdeg);
    cudaGetSymbolAddress((void**)&cnt_p,  g_cnt);

    cudaFuncSetAttribute(init_mma, cudaFuncAttributeMaxDynamicSharedMemorySize, INIT_SMEM);
    cudaFuncSetAttribute(node_mma, cudaFuncAttributeMaxDynamicSharedMemorySize, NODE_SMEM);

    cudaMemsetAsync(rdeg_p, 0, (size_t)n * sizeof(float));
    cudaMemsetAsync(cnt_p,  0, (size_t)G * sizeof(float));
    cudaMemsetAsync(d_out,  0, (size_t)out_size * sizeof(float));

    pack_kernel<<<42, 512>>>(root, cb, wih, whh, bih, bhh, w1, b1, w2, b2);
    deg_kernel<<<(E + 255) / 256, 256>>>(ei, rdeg_p, E);
    rdeg_kernel<<<(n + 255) / 256, 256>>>(rdeg_p, n);

    init_mma<<<148, 1024, INIT_SMEM>>>(x, batch, vec, blockemb, h_p, n);

    for (int s = 0; s < 4; s++) {
        edge_kernel<<<(E * 16 + 255) / 256, 256>>>(ei, ea, bondemb, h_p, rdeg_p, agg_p, E);
        node_mma<<<148, 1024, NODE_SMEM>>>(agg_p, h_p, n);
    }

    pool_kernel<<<(n * 16 + 255) / 256, 256>>>(h_p, batch, (float*)d_out, cnt_p, n);
    div_kernel<<<(G * 64 + 255) / 256, 256>>>((float*)d_out, cnt_p, G * 64);
}

// round 10
// speedup vs baseline: 1.1931x; 1.1926x over previous
#include <cuda_runtime.h>
#include <math.h>
#include <stdint.h>

#define MAXN 50000
#define MAXE 100000
#define MAXG 4096

typedef unsigned long long ull;

extern __shared__ __align__(1024) char smem_raw[];

// ---------------- device scratch -------------------------------------------
__device__ float g_h[MAXN * 64];
__device__ float g_agg[MAXN * 64];   // zeroed at load; node_mma re-zeroes after consume
__device__ float g_rdeg[MAXN];
__device__ float g_cnt[MAXG];
__device__ ull   g_pk_node[14336];
__device__ ull   g_pk_init[6144];
__device__ float g_bias_node[320];
__device__ float g_bias_init[128];

__device__ __forceinline__ float sigf_(float x)   { return 1.0f / (1.0f + __expf(-x)); }
__device__ __forceinline__ float tanhf_(float x)  { return 2.0f * sigf_(2.0f * x) - 1.0f; }
__device__ __forceinline__ float leakyf_(float x) { return x > 0.0f ? x : 0.01f * x; }

__device__ __forceinline__ uint32_t tf32_(float x) {
    uint32_t r; asm("cvt.rna.tf32.f32 %0, %1;" : "=r"(r) : "f"(x)); return r;
}

// m16n8k8 tf32 MMA (portable PTX)
__device__ __forceinline__ void mma8(float* c, const uint32_t* a, ull b) {
    uint32_t b0 = (uint32_t)b, b1 = (uint32_t)(b >> 32);
    asm volatile(
        "mma.sync.aligned.m16n8k8.row.col.f32.tf32.tf32.f32 "
        "{%0,%1,%2,%3}, {%4,%5,%6,%7}, {%8,%9}, {%0,%1,%2,%3};"
        : "+f"(c[0]), "+f"(c[1]), "+f"(c[2]), "+f"(c[3])
        : "r"(a[0]), "r"(a[1]), "r"(a[2]), "r"(a[3]), "r"(b0), "r"(b1));
}

// ---- fragment-order tile layout ----
// A-strip (16 rows x 8k-features per kk): ull index = kk*64 + half*32 + lane.
// ull at (kk, half, lane) holds features (kk*8 + (lane&3), +4) of row half*8 + (lane>>2).
// Warp loads are CONTIGUOUS -> conflict-free LDS.64.
__device__ __forceinline__ void load_fragF(uint32_t* a, const ull* strip, int kk, int lane) {
    ull p0 = strip[kk * 64 + lane];
    ull p1 = strip[kk * 64 + 32 + lane];
    a[0] = (uint32_t)p0; a[2] = (uint32_t)(p0 >> 32);
    a[1] = (uint32_t)p1; a[3] = (uint32_t)(p1 >> 32);
}
// scatter one fp32->tf32 value into fragment order: sub = f&7
__device__ __forceinline__ void frag_store(uint32_t* sf, int kk, int hlf, int lane4, int sub, uint32_t v) {
    sf[((kk * 2 + hlf) * 32 + lane4 + (sub & 3)) * 2 + (sub >> 2)] = v;
}

#define A_ROOT 0
#define A_IHR  1
#define A_HHR  2
#define A_IHZ  3
#define A_HHZ  4
#define A_IHN  5
#define A_HHN  6
// node smem: pk 14336 ull | h_f 8*512 ull | m_f 8*512 ull | bias 320 f
#define NODE_SMEM   ((14336 + 4096 + 4096) * 8 + 320 * 4)
// init smem: pk 6144 ull | in_f 8*1024 ull | o1_f 8*512 ull | bias 128 f
#define INIT_SMEM   ((6144 + 8192 + 4096) * 8 + 128 * 4)

// ---------------- pack kernel ------------------------------------------------
__global__ void pack_kernel(
    const float* __restrict__ root, const float* __restrict__ cb,
    const float* __restrict__ wih, const float* __restrict__ whh,
    const float* __restrict__ bih, const float* __restrict__ bhh,
    const float* __restrict__ w1, const float* __restrict__ b1,
    const float* __restrict__ w2, const float* __restrict__ b2)
{
    for (int i = blockIdx.x * blockDim.x + threadIdx.x; i < 21024; i += gridDim.x * blockDim.x) {
        if (i < 14336) {
            int arr = i >> 11, rem = i & 2047;
            int hf = rem >> 10, nt = (rem >> 8) & 3, kk = (rem >> 5) & 7, ln = rem & 31;
            int k0 = kk * 8 + (ln & 3), k1 = k0 + 4;
            int nn = hf * 32 + nt * 8 + (ln >> 2);
            float w0, w1v;
            switch (arr) {
                case A_ROOT: w0 = root[k0 * 64 + nn];         w1v = root[k1 * 64 + nn];         break;
                case A_IHR:  w0 = wih[nn * 64 + k0];          w1v = wih[nn * 64 + k1];          break;
                case A_HHR:  w0 = whh[nn * 64 + k0];          w1v = whh[nn * 64 + k1];          break;
                case A_IHZ:  w0 = wih[(64 + nn) * 64 + k0];   w1v = wih[(64 + nn) * 64 + k1];   break;
                case A_HHZ:  w0 = whh[(64 + nn) * 64 + k0];   w1v = whh[(64 + nn) * 64 + k1];   break;
                case A_IHN:  w0 = wih[(128 + nn) * 64 + k0];  w1v = wih[(128 + nn) * 64 + k1];  break;
                default:     w0 = whh[(128 + nn) * 64 + k0];  w1v = whh[(128 + nn) * 64 + k1];  break;
            }
            g_pk_node[i] = (ull)tf32_(w0) | ((ull)tf32_(w1v) << 32);
        } else if (i < 18432) {
            int j = i - 14336;
            int hf = j >> 11, nt = (j >> 9) & 3, kk = (j >> 5) & 15, ln = j & 31;
            int k0 = kk * 8 + (ln & 3), nn = hf * 32 + nt * 8 + (ln >> 2);
            g_pk_init[j] = (ull)tf32_(w1[nn * 128 + k0]) | ((ull)tf32_(w1[nn * 128 + k0 + 4]) << 32);
        } else if (i < 20480) {
            int j = i - 18432;
            int hf = j >> 10, nt = (j >> 8) & 3, kk = (j >> 5) & 7, ln = j & 31;
            int k0 = kk * 8 + (ln & 3), nn = hf * 32 + nt * 8 + (ln >> 2);
            g_pk_init[4096 + j] = (ull)tf32_(w2[nn * 64 + k0]) | ((ull)tf32_(w2[nn * 64 + k0 + 4]) << 32);
        } else if (i < 20800) {
            int j = i - 20480;
            float v;
            if (j < 128)      v = bih[j] + bhh[j];
            else if (j < 192) v = bih[128 + (j - 128)];
            else if (j < 256) v = bhh[128 + (j - 192)];
            else              v = cb[j - 256];
            g_bias_node[j] = v;
        } else {
            int j = i - 20800;
            g_bias_init[j] = (j < 64) ? b1[j] : b2[j - 64];
        }
    }
}

// ---------------- degree ----------------------------------------------------
__global__ void deg_kernel(const int* __restrict__ ei, float* __restrict__ deg, int E) {
    int e = blockIdx.x * blockDim.x + threadIdx.x;
    if (e < E) atomicAdd(&deg[ei[E + e]], 1.0f);
}
__global__ void rdeg_kernel(float* deg, int n) {
    int i = blockIdx.x * blockDim.x + threadIdx.x;
    if (i < n) deg[i] = 1.0f / fmaxf(deg[i], 1.0f);
}

// ---------------- init MLP: fragment-order smem, 512 thr ---------------------
__global__ void __launch_bounds__(512, 1) init_mma(
    const int* __restrict__ x, const int* __restrict__ batch,
    const float* __restrict__ vec, const float* __restrict__ blockemb,
    float* __restrict__ h, int n)
{
    ull* pk   = (ull*)smem_raw;        // [6144]: w1pk 4096 | w2pk 2048
    ull* in_f = pk + 6144;             // [8][1024]
    ull* o1_f = in_f + 8192;           // [8][512]
    float* b1s = (float*)(o1_f + 4096);
    float* b2s = b1s + 64;

    const int tid  = threadIdx.x;
    const int w    = tid >> 5;
    const int lane = tid & 31;
    const int p    = w & 7;            // row strip
    const int half = w >> 3;           // column half
    const int n0   = half * 32;

    for (int i = tid; i < 6144; i += 512) pk[i] = g_pk_init[i];
    if (tid < 128) b1s[tid] = g_bias_init[tid];
    __syncthreads();

    const ull* w1pk = pk;
    const ull* w2pk = pk + 4096;

    const int ntiles = (n + 127) >> 7;
    for (int tile = blockIdx.x; tile < ntiles; tile += gridDim.x) {
        const int nb0 = tile << 7;

        // gather [emb | vec] -> fragment-order tf32 smem (128 rows x 128 feats)
        {
            int row = tid >> 2, cpart = (tid & 3) * 32, gr = nb0 + row;
            int strip = row >> 4, rr = row & 15, hlf = rr >> 3, lane4 = (rr & 7) * 4;
            uint32_t* sf = (uint32_t*)(in_f + strip * 1024);
            if (gr < n) {
                const float* src = (cpart < 64)
                    ? (blockemb + (size_t)x[gr] * 64 + cpart)
                    : (vec + (size_t)batch[gr] * 64 + (cpart - 64));
                #pragma unroll
                for (int c = 0; c < 8; c++) {
                    float4 qv = ((const float4*)src)[c];
                    int f = cpart + c * 4;
                    frag_store(sf, f >> 3, hlf, lane4, f & 7, tf32_(qv.x));
                    frag_store(sf, (f + 1) >> 3, hlf, lane4, (f + 1) & 7, tf32_(qv.y));
                    frag_store(sf, (f + 2) >> 3, hlf, lane4, (f + 2) & 7, tf32_(qv.z));
                    frag_store(sf, (f + 3) >> 3, hlf, lane4, (f + 3) & 7, tf32_(qv.w));
                }
            } else {
                #pragma unroll
                for (int d = 0; d < 32; d++) {
                    int f = cpart + d;
                    frag_store(sf, f >> 3, hlf, lane4, f & 7, 0u);
                }
            }
        }
        __syncthreads();

        // GEMM1: o1 = leaky(in @ w1^T + b1); per warp 16x32
        float racc[16];
        #pragma unroll
        for (int t = 0; t < 16; t++) racc[t] = 0.0f;
        const ull* istrip = in_f + p * 1024;
        #pragma unroll
        for (int kk = 0; kk < 16; kk++) {
            uint32_t a[4];
            load_fragF(a, istrip, kk, lane);
            #pragma unroll
            for (int nt = 0; nt < 4; nt++)
                mma8(racc + nt * 4, a, w1pk[half * 2048 + nt * 512 + kk * 32 + lane]);
        }
        {
            uint32_t* of = (uint32_t*)(o1_f + p * 512);
            int lane4 = (lane >> 2) * 4;
            #pragma unroll
            for (int nt = 0; nt < 4; nt++) {
                int colb = n0 + nt * 8 + (lane & 3) * 2;
                int kk = half * 4 + nt;
                float c0 = b1s[colb], c1 = b1s[colb + 1];
                int sub0 = (lane & 3) * 2;
                #pragma unroll
                for (int qq = 0; qq < 2; qq++) {
                    frag_store(of, kk, qq, lane4, sub0,     tf32_(leakyf_(racc[nt * 4 + qq * 2]     + c0)));
                    frag_store(of, kk, qq, lane4, sub0 + 1, tf32_(leakyf_(racc[nt * 4 + qq * 2 + 1] + c1)));
                }
            }
        }
        __syncthreads();

        // GEMM2: h0 = o1 @ w2^T + b2
        float acc2[16];
        #pragma unroll
        for (int t = 0; t < 16; t++) acc2[t] = 0.0f;
        const ull* ostrip = o1_f + p * 512;
        #pragma unroll
        for (int kk = 0; kk < 8; kk++) {
            uint32_t a[4];
            load_fragF(a, ostrip, kk, lane);
            #pragma unroll
            for (int nt = 0; nt < 4; nt++)
                mma8(acc2 + nt * 4, a, w2pk[half * 1024 + nt * 256 + kk * 32 + lane]);
        }
        #pragma unroll
        for (int nt = 0; nt < 4; nt++) {
            int colb = n0 + nt * 8 + (lane & 3) * 2;
            float c0 = b2s[colb], c1 = b2s[colb + 1];
            #pragma unroll
            for (int qq = 0; qq < 2; qq++) {
                int gr = nb0 + p * 16 + (lane >> 2) + qq * 8;
                if (gr < n)
                    *(float2*)(h + (size_t)gr * 64 + colb) =
                        make_float2(acc2[nt * 4 + qq * 2] + c0, acc2[nt * 4 + qq * 2 + 1] + c1);
            }
        }
        __syncthreads();
    }
}

// ---------------- edge kernel: quarter-warp/edge, vec4 red (R7 form) ---------
__global__ void edge_kernel(const int* __restrict__ ei, const int* __restrict__ ea,
                            const float* __restrict__ bond, const float* __restrict__ h,
                            const float* __restrict__ rdeg,
                            float* __restrict__ agg, int E)
{
    int idx = blockIdx.x * blockDim.x + threadIdx.x;
    int e = idx >> 4;
    int l = idx & 15;
    bool valid = (e < E);
    int ec = valid ? e : (E - 1);
    int src = ei[ec], dst = ei[E + ec];
    int a0  = ea[2 * ec], a1 = ea[2 * ec + 1];
    float4 hv = *(const float4*)(h + (size_t)src * 64 + 4 * l);
    float4 e0 = *(const float4*)(bond + (size_t)a0 * 64 + 4 * l);
    float s = hv.x * e0.x + hv.y * e0.y + hv.z * e0.z + hv.w * e0.w;
    #pragma unroll
    for (int o = 8; o; o >>= 1) s += __shfl_xor_sync(0xffffffffu, s, o);
    s *= __ldg(&rdeg[dst]);
    float4 ev = *(const float4*)(bond + (size_t)a1 * 64 + 4 * l);
    if (valid) {
        float* ap = agg + (size_t)dst * 64 + 4 * l;
        asm volatile("red.global.add.v4.f32 [%0], {%1,%2,%3,%4};"
                     :: "l"(ap), "f"(s * ev.x), "f"(s * ev.y), "f"(s * ev.z), "f"(s * ev.w)
                     : "memory");
    }
}

// ---------------- node kernel: fragment-order smem, 512 thr -------------------
__global__ void __launch_bounds__(512, 1) node_mma(
    float* __restrict__ agg,
    float* __restrict__ h, int n)
{
    ull* pk  = (ull*)smem_raw;          // [14336]
    ull* h_f = pk + 14336;              // [8][512]
    ull* m_f = h_f + 4096;              // [8][512]
    float* br_s  = (float*)(m_f + 4096);
    float* bz_s  = br_s + 64;
    float* bin_s = bz_s + 64;
    float* bhn_s = bin_s + 64;
    float* cb_s  = bhn_s + 64;

    const int tid  = threadIdx.x;
    const int w    = tid >> 5;
    const int lane = tid & 31;
    const int p    = w & 7;
    const int half = w >> 3;
    const int n0   = half * 32;
    const int arow = p * 16 + (lane >> 2);

    for (int i = tid; i < 14336; i += 512) pk[i] = g_pk_node[i];
    if (tid < 320) br_s[tid] = g_bias_node[tid];
    __syncthreads();

    const int ntiles = (n + 127) >> 7;
    for (int tile = blockIdx.x; tile < ntiles; tile += gridDim.x) {
        const int nb0 = tile << 7;

        // H tile -> fragment-order tf32 smem
        {
            int row = tid >> 2, cbase = (tid & 3) * 16, gr = nb0 + row;
            int strip = row >> 4, rr = row & 15, hlf = rr >> 3, lane4 = (rr & 7) * 4;
            uint32_t* sf = (uint32_t*)(h_f + strip * 512);
            if (gr < n) {
                const float4* pp = (const float4*)(h + (size_t)gr * 64 + cbase);
                #pragma unroll
                for (int c = 0; c < 4; c++) {
                    float4 qv = pp[c];
                    int f = cbase + c * 4;
                    frag_store(sf, f >> 3, hlf, lane4, f & 7, tf32_(qv.x));
                    frag_store(sf, (f + 1) >> 3, hlf, lane4, (f + 1) & 7, tf32_(qv.y));
                    frag_store(sf, (f + 2) >> 3, hlf, lane4, (f + 2) & 7, tf32_(qv.z));
                    frag_store(sf, (f + 3) >> 3, hlf, lane4, (f + 3) & 7, tf32_(qv.w));
                }
            } else {
                #pragma unroll
                for (int d = 0; d < 16; d++) {
                    int f = cbase + d;
                    frag_store(sf, f >> 3, hlf, lane4, f & 7, 0u);
                }
            }
        }
        __syncthreads();

        // prefetch agg (fp32) + zero for next step
        float2 agf[8];
        #pragma unroll
        for (int nt = 0; nt < 4; nt++) {
            int colb = n0 + nt * 8 + (lane & 3) * 2;
            #pragma unroll
            for (int qq = 0; qq < 2; qq++) {
                int gr = nb0 + arow + qq * 8;
                if (gr < n) {
                    float2* ap = (float2*)(agg + (size_t)gr * 64 + colb);
                    agf[nt * 2 + qq] = *ap;
                    *ap = make_float2(0.0f, 0.0f);
                } else {
                    agf[nt * 2 + qq] = make_float2(0.0f, 0.0f);
                }
            }
        }

        const ull* hstrip = h_f + p * 512;
        const ull* mstrip = m_f + p * 512;

        // GEMM1: R = H @ root
        float racc[16];
        #pragma unroll
        for (int t = 0; t < 16; t++) racc[t] = 0.0f;
        #pragma unroll
        for (int kk = 0; kk < 8; kk++) {
            uint32_t a[4];
            load_fragF(a, hstrip, kk, lane);
            #pragma unroll
            for (int nt = 0; nt < 4; nt++)
                mma8(racc + nt * 4, a, pk[A_ROOT * 2048 + half * 1024 + nt * 256 + kk * 32 + lane]);
        }
        // epilogue A: M = leaky(R + agg + cb) -> fragment-order m_f
        {
            uint32_t* mf = (uint32_t*)(m_f + p * 512);
            int lane4 = (lane >> 2) * 4;
            int sub0 = (lane & 3) * 2;
            #pragma unroll
            for (int nt = 0; nt < 4; nt++) {
                int colb = n0 + nt * 8 + (lane & 3) * 2;
                int kk = half * 4 + nt;
                float cb0 = cb_s[colb], cb1 = cb_s[colb + 1];
                #pragma unroll
                for (int qq = 0; qq < 2; qq++) {
                    float2 ag = agf[nt * 2 + qq];
                    frag_store(mf, kk, qq, lane4, sub0,     tf32_(leakyf_(racc[nt * 4 + qq * 2]     + ag.x + cb0)));
                    frag_store(mf, kk, qq, lane4, sub0 + 1, tf32_(leakyf_(racc[nt * 4 + qq * 2 + 1] + ag.y + cb1)));
                }
            }
        }
        __syncthreads();

        // prefetch h_old (fp32, L2-hot)
        float2 hof[8];
        #pragma unroll
        for (int nt = 0; nt < 4; nt++) {
            int colb = n0 + nt * 8 + (lane & 3) * 2;
            #pragma unroll
            for (int qq = 0; qq < 2; qq++) {
                int gr = nb0 + arow + qq * 8;
                hof[nt * 2 + qq] = (gr < n) ? *(const float2*)(h + (size_t)gr * 64 + colb)
                                            : make_float2(0.0f, 0.0f);
            }
        }

        // GEMM2: gates
        float rg[16], zg[16], ig[16], hg[16];
        #pragma unroll
        for (int t = 0; t < 16; t++) { rg[t] = zg[t] = ig[t] = hg[t] = 0.0f; }
        #pragma unroll
        for (int kk = 0; kk < 8; kk++) {
            uint32_t aM[4], aH[4];
            load_fragF(aM, mstrip, kk, lane);
            load_fragF(aH, hstrip, kk, lane);
            int pkb = half * 1024 + kk * 32 + lane;
            #pragma unroll
            for (int nt = 0; nt < 4; nt++) {
                int o = pkb + nt * 256;
                mma8(rg + nt * 4, aM, pk[A_IHR * 2048 + o]);
                mma8(rg + nt * 4, aH, pk[A_HHR * 2048 + o]);
                mma8(zg + nt * 4, aM, pk[A_IHZ * 2048 + o]);
                mma8(zg + nt * 4, aH, pk[A_HHZ * 2048 + o]);
                mma8(ig + nt * 4, aM, pk[A_IHN * 2048 + o]);
                mma8(hg + nt * 4, aH, pk[A_HHN * 2048 + o]);
            }
        }

        // epilogue: GRU gate math
        #pragma unroll
        for (int nt = 0; nt < 4; nt++) {
            int colb = n0 + nt * 8 + (lane & 3) * 2;
            float br0 = br_s[colb], br1 = br_s[colb + 1];
            float bz0 = bz_s[colb], bz1 = bz_s[colb + 1];
            float bi0 = bin_s[colb], bi1 = bin_s[colb + 1];
            float bh0 = bhn_s[colb], bh1 = bhn_s[colb + 1];
            #pragma unroll
            for (int qq = 0; qq < 2; qq++) {
                int gr = nb0 + arow + qq * 8;
                if (gr < n) {
                    int idx = nt * 4 + qq * 2;
                    float2 ho = hof[nt * 2 + qq];
                    float r0v = sigf_(rg[idx]     + br0);
                    float r1v = sigf_(rg[idx + 1] + br1);
                    float z0v = sigf_(zg[idx]     + bz0);
                    float z1v = sigf_(zg[idx + 1] + bz1);
                    float n0v = tanhf_(ig[idx]     + bi0 + r0v * (hg[idx]     + bh0));
                    float n1v = tanhf_(ig[idx + 1] + bi1 + r1v * (hg[idx + 1] + bh1));
                    float2 o;
                    o.x = (1.0f - z0v) * n0v + z0v * ho.x;
                    o.y = (1.0f - z1v) * n1v + z1v * ho.y;
                    *(float2*)(h + (size_t)gr * 64 + colb) = o;
                }
            }
        }
        __syncthreads();
    }
}

// ---------------- pooling ------------------------------------------------------
__global__ void pool_kernel(const float* __restrict__ h, const int* __restrict__ batch,
                            float* __restrict__ out, float* __restrict__ cnt, int n)
{
    int idx = blockIdx.x * blockDim.x + threadIdx.x;
    int nn = idx >> 4, l = idx & 15;
    if (nn >= n) return;
    int g = batch[nn];
    float4 v = *(const float4*)(h + (size_t)nn * 64 + 4 * l);
    float* op = out + (size_t)g * 64 + 4 * l;
    asm volatile("red.global.add.v4.f32 [%0], {%1,%2,%3,%4};"
                 :: "l"(op), "f"(v.x), "f"(v.y), "f"(v.z), "f"(v.w) : "memory");
    if (l == 0) atomicAdd(&cnt[g], 1.0f);
}
__global__ void div_kernel(float* out, const float* __restrict__ cnt, int total)
{
    int i = blockIdx.x * blockDim.x + threadIdx.x;
    if (i < total) out[i] /= fmaxf(cnt[i >> 6], 1.0f);
}

// ---------------- launch --------------------------------------------------------
extern "C" void kernel_launch(void* const* d_in, const int* in_sizes, int n_in,
                              void* d_out, int out_size)
{
    const int*   x        = (const int*)d_in[0];
    const int*   ei       = (const int*)d_in[1];
    const int*   ea       = (const int*)d_in[2];
    const int*   batch    = (const int*)d_in[3];
    const float* vec      = (const float*)d_in[4];
    const float* blockemb = (const float*)d_in[5];
    const float* bondemb  = (const float*)d_in[6];
    const float* w1       = (const float*)d_in[7];
    const float* b1       = (const float*)d_in[8];
    const float* w2       = (const float*)d_in[9];
    const float* b2       = (const float*)d_in[10];
    const float* root     = (const float*)d_in[11];
    const float* cb       = (const float*)d_in[12];
    const float* wih      = (const float*)d_in[13];
    const float* whh      = (const float*)d_in[14];
    const float* bih      = (const float*)d_in[15];
    const float* bhh      = (const float*)d_in[16];

    const int n = in_sizes[0];
    const int E = in_sizes[1] / 2;
    const int G = in_sizes[4] / 64;

    float *h_p, *agg_p, *rdeg_p, *cnt_p;
    cudaGetSymbolAddress((void**)&h_p,    g_h);
    cudaGetSymbolAddress((void**)&agg_p,  g_agg);
    cudaGetSymbolAddress((void**)&rdeg_p, g_rdeg);
    cudaGetSymbolAddress((void**)&cnt_p,  g_cnt);

    cudaFuncSetAttribute(init_mma, cudaFuncAttributeMaxDynamicSharedMemorySize, INIT_SMEM);
    cudaFuncSetAttribute(node_mma, cudaFuncAttributeMaxDynamicSharedMemorySize, NODE_SMEM);

    cudaMemsetAsync(rdeg_p, 0, (size_t)n * sizeof(float));
    cudaMemsetAsync(cnt_p,  0, (size_t)G * sizeof(float));
    cudaMemsetAsync(d_out,  0, (size_t)out_size * sizeof(float));

    pack_kernel<<<42, 512>>>(root, cb, wih, whh, bih, bhh, w1, b1, w2, b2);
    deg_kernel<<<(E + 255) / 256, 256>>>(ei, rdeg_p, E);
    rdeg_kernel<<<(n + 255) / 256, 256>>>(rdeg_p, n);

    init_mma<<<148, 512, INIT_SMEM>>>(x, batch, vec, blockemb, h_p, n);

    for (int s = 0; s < 4; s++) {
        edge_kernel<<<(E * 16 + 255) / 256, 256>>>(ei, ea, bondemb, h_p, rdeg_p, agg_p, E);
        node_mma<<<148, 512, NODE_SMEM>>>(agg_p, h_p, n);
    }

    pool_kernel<<<(n * 16 + 255) / 256, 256>>>(h_p, batch, (float*)d_out, cnt_p, n);
    div_kernel<<<(G * 64 + 255) / 256, 256>>>((float*)d_out, cnt_p, G * 64);
}

// round 11
// speedup vs baseline: 1.2677x; 1.0625x over previous
#include <cuda_runtime.h>
#include <math.h>
#include <stdint.h>

#define MAXN 50000
#define MAXE 100000
#define MAXG 4096

typedef unsigned long long ull;

extern __shared__ __align__(1024) char smem_raw[];

// ---------------- device scratch -------------------------------------------
__device__ float g_h[MAXN * 64];
__device__ float g_sacc[MAXN * 20];   // per-(dst, bond-type) scalar accum; zero invariant
__device__ float g_rdeg[MAXN];
__device__ float g_cnt[MAXG];
__device__ ull   g_pk_node[15104];    // 7 gate arrays (14336) + bond pack (768)
__device__ ull   g_pk_init[6144];
__device__ float g_bias_node[320];
__device__ float g_bias_init[128];

__device__ __forceinline__ float sigf_(float x)   { return 1.0f / (1.0f + __expf(-x)); }
__device__ __forceinline__ float tanhf_(float x)  { return 2.0f * sigf_(2.0f * x) - 1.0f; }
__device__ __forceinline__ float leakyf_(float x) { return x > 0.0f ? x : 0.01f * x; }

__device__ __forceinline__ uint32_t tf32_(float x) {
    uint32_t r; asm("cvt.rna.tf32.f32 %0, %1;" : "=r"(r) : "f"(x)); return r;
}

// m16n8k8 tf32 MMA (portable PTX)
__device__ __forceinline__ void mma8(float* c, const uint32_t* a, ull b) {
    uint32_t b0 = (uint32_t)b, b1 = (uint32_t)(b >> 32);
    asm volatile(
        "mma.sync.aligned.m16n8k8.row.col.f32.tf32.tf32.f32 "
        "{%0,%1,%2,%3}, {%4,%5,%6,%7}, {%8,%9}, {%0,%1,%2,%3};"
        : "+f"(c[0]), "+f"(c[1]), "+f"(c[2]), "+f"(c[3])
        : "r"(a[0]), "r"(a[1]), "r"(a[2]), "r"(a[3]), "r"(b0), "r"(b1));
}

// fragment-order tile helpers (conflict-free warp-contiguous LDS.64)
__device__ __forceinline__ void load_fragF(uint32_t* a, const ull* strip, int kk, int lane) {
    ull p0 = strip[kk * 64 + lane];
    ull p1 = strip[kk * 64 + 32 + lane];
    a[0] = (uint32_t)p0; a[2] = (uint32_t)(p0 >> 32);
    a[1] = (uint32_t)p1; a[3] = (uint32_t)(p1 >> 32);
}
__device__ __forceinline__ void frag_store(uint32_t* sf, int kk, int hlf, int lane4, int sub, uint32_t v) {
    sf[((kk * 2 + hlf) * 32 + lane4 + (sub & 3)) * 2 + (sub >> 2)] = v;
}

#define A_ROOT 0
#define A_IHR  1
#define A_HHR  2
#define A_IHZ  3
#define A_HHZ  4
#define A_IHN  5
#define A_HHN  6
#define BOND_OFF 14336
// node smem: pk 15104 ull | h_f 8*512 | m_f 8*512 | s_f 8*192 | bias 320 f
#define NODE_SMEM   ((15104 + 4096 + 4096 + 1536) * 8 + 320 * 4)
#define INIT_SMEM   ((6144 + 8192 + 4096) * 8 + 128 * 4)

// ---------------- pack kernel ------------------------------------------------
__global__ void pack_kernel(
    const float* __restrict__ root, const float* __restrict__ cb,
    const float* __restrict__ wih, const float* __restrict__ whh,
    const float* __restrict__ bih, const float* __restrict__ bhh,
    const float* __restrict__ w1, const float* __restrict__ b1,
    const float* __restrict__ w2, const float* __restrict__ b2,
    const float* __restrict__ bondemb)
{
    for (int i = blockIdx.x * blockDim.x + threadIdx.x; i < 21696; i += gridDim.x * blockDim.x) {
        if (i < 14336) {
            int arr = i >> 11, rem = i & 2047;
            int hf = rem >> 10, nt = (rem >> 8) & 3, kk = (rem >> 5) & 7, ln = rem & 31;
            int k0 = kk * 8 + (ln & 3), k1 = k0 + 4;
            int nn = hf * 32 + nt * 8 + (ln >> 2);
            float w0, w1v;
            switch (arr) {
                case A_ROOT: w0 = root[k0 * 64 + nn];         w1v = root[k1 * 64 + nn];         break;
                case A_IHR:  w0 = wih[nn * 64 + k0];          w1v = wih[nn * 64 + k1];          break;
                case A_HHR:  w0 = whh[nn * 64 + k0];          w1v = whh[nn * 64 + k1];          break;
                case A_IHZ:  w0 = wih[(64 + nn) * 64 + k0];   w1v = wih[(64 + nn) * 64 + k1];   break;
                case A_HHZ:  w0 = whh[(64 + nn) * 64 + k0];   w1v = whh[(64 + nn) * 64 + k1];   break;
                case A_IHN:  w0 = wih[(128 + nn) * 64 + k0];  w1v = wih[(128 + nn) * 64 + k1];  break;
                default:     w0 = whh[(128 + nn) * 64 + k0];  w1v = whh[(128 + nn) * 64 + k1];  break;
            }
            g_pk_node[i] = (ull)tf32_(w0) | ((ull)tf32_(w1v) << 32);
        } else if (i < 15104) {
            // bond pack: B[n][k] = bondemb[k][n], K padded 20->24
            int j = i - 14336;
            int ln = j & 31, t = j >> 5;        // t in [0,24)
            int kk = t % 3, u = t / 3;          // u in [0,8)
            int nt = u & 3, hf = u >> 2;
            int k0 = kk * 8 + (ln & 3), k1 = k0 + 4;
            int nn = hf * 32 + nt * 8 + (ln >> 2);
            float w0 = (k0 < 20) ? bondemb[k0 * 64 + nn] : 0.0f;
            float w1v = (k1 < 20) ? bondemb[k1 * 64 + nn] : 0.0f;
            g_pk_node[BOND_OFF + j] = (ull)tf32_(w0) | ((ull)tf32_(w1v) << 32);
        } else if (i < 19200) {
            int j = i - 15104;
            int hf = j >> 11, nt = (j >> 9) & 3, kk = (j >> 5) & 15, ln = j & 31;
            int k0 = kk * 8 + (ln & 3), nn = hf * 32 + nt * 8 + (ln >> 2);
            g_pk_init[j] = (ull)tf32_(w1[nn * 128 + k0]) | ((ull)tf32_(w1[nn * 128 + k0 + 4]) << 32);
        } else if (i < 21248) {
            int j = i - 19200;
            int hf = j >> 10, nt = (j >> 8) & 3, kk = (j >> 5) & 7, ln = j & 31;
            int k0 = kk * 8 + (ln & 3), nn = hf * 32 + nt * 8 + (ln >> 2);
            g_pk_init[4096 + j] = (ull)tf32_(w2[nn * 64 + k0]) | ((ull)tf32_(w2[nn * 64 + k0 + 4]) << 32);
        } else if (i < 21568) {
            int j = i - 21248;
            float v;
            if (j < 128)      v = bih[j] + bhh[j];
            else if (j < 192) v = bih[128 + (j - 128)];
            else if (j < 256) v = bhh[128 + (j - 192)];
            else              v = cb[j - 256];
            g_bias_node[j] = v;
        } else {
            int j = i - 21568;
            g_bias_init[j] = (j < 64) ? b1[j] : b2[j - 64];
        }
    }
}

// ---------------- degree / counts --------------------------------------------
__global__ void deg_kernel(const int* __restrict__ ei, float* __restrict__ deg, int E) {
    int e = blockIdx.x * blockDim.x + threadIdx.x;
    if (e < E) atomicAdd(&deg[ei[E + e]], 1.0f);
}
__global__ void rdeg_kernel(float* deg, int n) {
    int i = blockIdx.x * blockDim.x + threadIdx.x;
    if (i < n) deg[i] = 1.0f / fmaxf(deg[i], 1.0f);
}
__global__ void cnt_kernel(const int* __restrict__ batch, float* __restrict__ cnt, int n) {
    int i = blockIdx.x * blockDim.x + threadIdx.x;
    if (i < n) atomicAdd(&cnt[batch[i]], 1.0f);
}

// ---------------- init MLP (unchanged from R10) --------------------------------
__global__ void __launch_bounds__(512, 1) init_mma(
    const int* __restrict__ x, const int* __restrict__ batch,
    const float* __restrict__ vec, const float* __restrict__ blockemb,
    float* __restrict__ h, int n)
{
    ull* pk   = (ull*)smem_raw;
    ull* in_f = pk + 6144;
    ull* o1_f = in_f + 8192;
    float* b1s = (float*)(o1_f + 4096);
    float* b2s = b1s + 64;

    const int tid  = threadIdx.x;
    const int w    = tid >> 5;
    const int lane = tid & 31;
    const int p    = w & 7;
    const int half = w >> 3;
    const int n0   = half * 32;

    for (int i = tid; i < 6144; i += 512) pk[i] = g_pk_init[i];
    if (tid < 128) b1s[tid] = g_bias_init[tid];
    __syncthreads();

    const ull* w1pk = pk;
    const ull* w2pk = pk + 4096;

    const int ntiles = (n + 127) >> 7;
    for (int tile = blockIdx.x; tile < ntiles; tile += gridDim.x) {
        const int nb0 = tile << 7;
        {
            int row = tid >> 2, cpart = (tid & 3) * 32, gr = nb0 + row;
            int strip = row >> 4, rr = row & 15, hlf = rr >> 3, lane4 = (rr & 7) * 4;
            uint32_t* sf = (uint32_t*)(in_f + strip * 1024);
            if (gr < n) {
                const float* src = (cpart < 64)
                    ? (blockemb + (size_t)x[gr] * 64 + cpart)
                    : (vec + (size_t)batch[gr] * 64 + (cpart - 64));
                #pragma unroll
                for (int c = 0; c < 8; c++) {
                    float4 qv = ((const float4*)src)[c];
                    int f = cpart + c * 4;
                    frag_store(sf, f >> 3, hlf, lane4, f & 7, tf32_(qv.x));
                    frag_store(sf, (f + 1) >> 3, hlf, lane4, (f + 1) & 7, tf32_(qv.y));
                    frag_store(sf, (f + 2) >> 3, hlf, lane4, (f + 2) & 7, tf32_(qv.z));
                    frag_store(sf, (f + 3) >> 3, hlf, lane4, (f + 3) & 7, tf32_(qv.w));
                }
            } else {
                #pragma unroll
                for (int d = 0; d < 32; d++) {
                    int f = cpart + d;
                    frag_store(sf, f >> 3, hlf, lane4, f & 7, 0u);
                }
            }
        }
        __syncthreads();

        float racc[16];
        #pragma unroll
        for (int t = 0; t < 16; t++) racc[t] = 0.0f;
        const ull* istrip = in_f + p * 1024;
        #pragma unroll
        for (int kk = 0; kk < 16; kk++) {
            uint32_t a[4];
            load_fragF(a, istrip, kk, lane);
            #pragma unroll
            for (int nt = 0; nt < 4; nt++)
                mma8(racc + nt * 4, a, w1pk[half * 2048 + nt * 512 + kk * 32 + lane]);
        }
        {
            uint32_t* of = (uint32_t*)(o1_f + p * 512);
            int lane4 = (lane >> 2) * 4;
            int sub0 = (lane & 3) * 2;
            #pragma unroll
            for (int nt = 0; nt < 4; nt++) {
                int colb = n0 + nt * 8 + (lane & 3) * 2;
                int kk = half * 4 + nt;
                float c0 = b1s[colb], c1 = b1s[colb + 1];
                #pragma unroll
                for (int qq = 0; qq < 2; qq++) {
                    frag_store(of, kk, qq, lane4, sub0,     tf32_(leakyf_(racc[nt * 4 + qq * 2]     + c0)));
                    frag_store(of, kk, qq, lane4, sub0 + 1, tf32_(leakyf_(racc[nt * 4 + qq * 2 + 1] + c1)));
                }
            }
        }
        __syncthreads();

        float acc2[16];
        #pragma unroll
        for (int t = 0; t < 16; t++) acc2[t] = 0.0f;
        const ull* ostrip = o1_f + p * 512;
        #pragma unroll
        for (int kk = 0; kk < 8; kk++) {
            uint32_t a[4];
            load_fragF(a, ostrip, kk, lane);
            #pragma unroll
            for (int nt = 0; nt < 4; nt++)
                mma8(acc2 + nt * 4, a, w2pk[half * 1024 + nt * 256 + kk * 32 + lane]);
        }
        #pragma unroll
        for (int nt = 0; nt < 4; nt++) {
            int colb = n0 + nt * 8 + (lane & 3) * 2;
            float c0 = b2s[colb], c1 = b2s[colb + 1];
            #pragma unroll
            for (int qq = 0; qq < 2; qq++) {
                int gr = nb0 + p * 16 + (lane >> 2) + qq * 8;
                if (gr < n)
                    *(float2*)(h + (size_t)gr * 64 + colb) =
                        make_float2(acc2[nt * 4 + qq * 2] + c0, acc2[nt * 4 + qq * 2 + 1] + c1);
            }
        }
        __syncthreads();
    }
}

// ---------------- edge kernel: 1 scalar atomic per edge ------------------------
__global__ void edge_kernel(const int* __restrict__ ei, const int* __restrict__ ea,
                            const float* __restrict__ bond, const float* __restrict__ h,
                            const float* __restrict__ rdeg, int E)
{
    int idx = blockIdx.x * blockDim.x + threadIdx.x;
    int e = idx >> 4;
    int l = idx & 15;
    bool valid = (e < E);
    int ec = valid ? e : (E - 1);
    int src = ei[ec], dst = ei[E + ec];
    int a0  = ea[2 * ec], a1 = ea[2 * ec + 1];
    float4 hv = *(const float4*)(h + (size_t)src * 64 + 4 * l);
    float4 e0 = *(const float4*)(bond + (size_t)a0 * 64 + 4 * l);
    float s = hv.x * e0.x + hv.y * e0.y + hv.z * e0.z + hv.w * e0.w;
    #pragma unroll
    for (int o = 8; o; o >>= 1) s += __shfl_xor_sync(0xffffffffu, s, o);
    if (valid && l == 0)
        atomicAdd(&g_sacc[(size_t)dst * 20 + a1], s * __ldg(&rdeg[dst]));
}

// ---------------- node kernel: + S@bond fused, optional pool fusion -----------
__global__ void __launch_bounds__(512, 1) node_mma(
    float* __restrict__ h, const int* __restrict__ batch,
    float* __restrict__ out, int n, int last)
{
    ull* pk  = (ull*)smem_raw;          // [15104]
    ull* h_f = pk + 15104;              // [8][512]
    ull* m_f = h_f + 4096;              // [8][512]
    ull* s_f = m_f + 4096;              // [8][192]
    float* br_s  = (float*)(s_f + 1536);
    float* bz_s  = br_s + 64;
    float* bin_s = bz_s + 64;
    float* bhn_s = bin_s + 64;
    float* cb_s  = bhn_s + 64;

    const int tid  = threadIdx.x;
    const int w    = tid >> 5;
    const int lane = tid & 31;
    const int p    = w & 7;
    const int half = w >> 3;
    const int n0   = half * 32;
    const int arow = p * 16 + (lane >> 2);

    for (int i = tid; i < 15104; i += 512) pk[i] = g_pk_node[i];
    if (tid < 320) br_s[tid] = g_bias_node[tid];
    __syncthreads();

    const int ntiles = (n + 127) >> 7;
    for (int tile = blockIdx.x; tile < ntiles; tile += gridDim.x) {
        const int nb0 = tile << 7;

        // H tile -> fragment-order tf32 smem
        {
            int row = tid >> 2, cbase = (tid & 3) * 16, gr = nb0 + row;
            int strip = row >> 4, rr = row & 15, hlf = rr >> 3, lane4 = (rr & 7) * 4;
            uint32_t* sf = (uint32_t*)(h_f + strip * 512);
            if (gr < n) {
                const float4* pp = (const float4*)(h + (size_t)gr * 64 + cbase);
                #pragma unroll
                for (int c = 0; c < 4; c++) {
                    float4 qv = pp[c];
                    int f = cbase + c * 4;
                    frag_store(sf, f >> 3, hlf, lane4, f & 7, tf32_(qv.x));
                    frag_store(sf, (f + 1) >> 3, hlf, lane4, (f + 1) & 7, tf32_(qv.y));
                    frag_store(sf, (f + 2) >> 3, hlf, lane4, (f + 2) & 7, tf32_(qv.z));
                    frag_store(sf, (f + 3) >> 3, hlf, lane4, (f + 3) & 7, tf32_(qv.w));
                }
            } else {
                #pragma unroll
                for (int d = 0; d < 16; d++) {
                    int f = cbase + d;
                    frag_store(sf, f >> 3, hlf, lane4, f & 7, 0u);
                }
            }
        }
        // S tile (20 cols padded to 24) -> fragment order; zero g_sacc for next step
        {
            int row = tid >> 2, gr = nb0 + row;
            int c0 = (tid & 3) * 6;
            int strip = row >> 4, rr = row & 15, hlf = rr >> 3, lane4 = (rr & 7) * 4;
            uint32_t* sf = (uint32_t*)(s_f + strip * 192);
            float* sp = g_sacc + (size_t)gr * 20;
            #pragma unroll
            for (int d = 0; d < 6; d++) {
                int f = c0 + d;
                float v = 0.0f;
                if (f < 20 && gr < n) { v = sp[f]; sp[f] = 0.0f; }
                frag_store(sf, f >> 3, hlf, lane4, f & 7, tf32_(v));
            }
        }
        __syncthreads();

        const ull* hstrip = h_f + p * 512;
        const ull* mstrip = m_f + p * 512;
        const ull* sstrip = s_f + p * 192;

        // GEMM1: R = H @ root + S @ bond
        float racc[16];
        #pragma unroll
        for (int t = 0; t < 16; t++) racc[t] = 0.0f;
        #pragma unroll
        for (int kk = 0; kk < 8; kk++) {
            uint32_t a[4];
            load_fragF(a, hstrip, kk, lane);
            #pragma unroll
            for (int nt = 0; nt < 4; nt++)
                mma8(racc + nt * 4, a, pk[A_ROOT * 2048 + half * 1024 + nt * 256 + kk * 32 + lane]);
        }
        #pragma unroll
        for (int kk = 0; kk < 3; kk++) {
            uint32_t a[4];
            load_fragF(a, sstrip, kk, lane);
            #pragma unroll
            for (int nt = 0; nt < 4; nt++)
                mma8(racc + nt * 4, a, pk[BOND_OFF + ((half * 4 + nt) * 3 + kk) * 32 + lane]);
        }
        // epilogue A: M = leaky(R + cb) -> fragment-order m_f
        {
            uint32_t* mf = (uint32_t*)(m_f + p * 512);
            int lane4 = (lane >> 2) * 4;
            int sub0 = (lane & 3) * 2;
            #pragma unroll
            for (int nt = 0; nt < 4; nt++) {
                int colb = n0 + nt * 8 + (lane & 3) * 2;
                int kk = half * 4 + nt;
                float cb0 = cb_s[colb], cb1 = cb_s[colb + 1];
                #pragma unroll
                for (int qq = 0; qq < 2; qq++) {
                    frag_store(mf, kk, qq, lane4, sub0,     tf32_(leakyf_(racc[nt * 4 + qq * 2]     + cb0)));
                    frag_store(mf, kk, qq, lane4, sub0 + 1, tf32_(leakyf_(racc[nt * 4 + qq * 2 + 1] + cb1)));
                }
            }
        }
        __syncthreads();

        // prefetch h_old (fp32, L2-hot) + batch for last step
        float2 hof[8];
        int bg[2];
        #pragma unroll
        for (int qq = 0; qq < 2; qq++) {
            int gr = nb0 + arow + qq * 8;
            bg[qq] = (last && gr < n) ? batch[gr] : 0;
        }
        #pragma unroll
        for (int nt = 0; nt < 4; nt++) {
            int colb = n0 + nt * 8 + (lane & 3) * 2;
            #pragma unroll
            for (int qq = 0; qq < 2; qq++) {
                int gr = nb0 + arow + qq * 8;
                hof[nt * 2 + qq] = (gr < n) ? *(const float2*)(h + (size_t)gr * 64 + colb)
                                            : make_float2(0.0f, 0.0f);
            }
        }

        // GEMM2: gates
        float rg[16], zg[16], ig[16], hg[16];
        #pragma unroll
        for (int t = 0; t < 16; t++) { rg[t] = zg[t] = ig[t] = hg[t] = 0.0f; }
        #pragma unroll
        for (int kk = 0; kk < 8; kk++) {
            uint32_t aM[4], aH[4];
            load_fragF(aM, mstrip, kk, lane);
            load_fragF(aH, hstrip, kk, lane);
            int pkb = half * 1024 + kk * 32 + lane;
            #pragma unroll
            for (int nt = 0; nt < 4; nt++) {
                int o = pkb + nt * 256;
                mma8(rg + nt * 4, aM, pk[A_IHR * 2048 + o]);
                mma8(rg + nt * 4, aH, pk[A_HHR * 2048 + o]);
                mma8(zg + nt * 4, aM, pk[A_IHZ * 2048 + o]);
                mma8(zg + nt * 4, aH, pk[A_HHZ * 2048 + o]);
                mma8(ig + nt * 4, aM, pk[A_IHN * 2048 + o]);
                mma8(hg + nt * 4, aH, pk[A_HHN * 2048 + o]);
            }
        }

        // epilogue: GRU gate math; last step pools directly into out
        #pragma unroll
        for (int nt = 0; nt < 4; nt++) {
            int colb = n0 + nt * 8 + (lane & 3) * 2;
            float br0 = br_s[colb], br1 = br_s[colb + 1];
            float bz0 = bz_s[colb], bz1 = bz_s[colb + 1];
            float bi0 = bin_s[colb], bi1 = bin_s[colb + 1];
            float bh0 = bhn_s[colb], bh1 = bhn_s[colb + 1];
            #pragma unroll
            for (int qq = 0; qq < 2; qq++) {
                int gr = nb0 + arow + qq * 8;
                if (gr < n) {
                    int idx = nt * 4 + qq * 2;
                    float2 ho = hof[nt * 2 + qq];
                    float r0v = sigf_(rg[idx]     + br0);
                    float r1v = sigf_(rg[idx + 1] + br1);
                    float z0v = sigf_(zg[idx]     + bz0);
                    float z1v = sigf_(zg[idx + 1] + bz1);
                    float n0v = tanhf_(ig[idx]     + bi0 + r0v * (hg[idx]     + bh0));
                    float n1v = tanhf_(ig[idx + 1] + bi1 + r1v * (hg[idx + 1] + bh1));
                    float ox = (1.0f - z0v) * n0v + z0v * ho.x;
                    float oy = (1.0f - z1v) * n1v + z1v * ho.y;
                    if (last) {
                        float* op = out + (size_t)bg[qq] * 64 + colb;
                        asm volatile("red.global.add.v2.f32 [%0], {%1,%2};"
                                     :: "l"(op), "f"(ox), "f"(oy) : "memory");
                    } else {
                        *(float2*)(h + (size_t)gr * 64 + colb) = make_float2(ox, oy);
                    }
                }
            }
        }
        __syncthreads();
    }
}

// ---------------- div ----------------------------------------------------------
__global__ void div_kernel(float* out, const float* __restrict__ cnt, int total)
{
    int i = blockIdx.x * blockDim.x + threadIdx.x;
    if (i < total) out[i] /= fmaxf(cnt[i >> 6], 1.0f);
}

// ---------------- launch --------------------------------------------------------
extern "C" void kernel_launch(void* const* d_in, const int* in_sizes, int n_in,
                              void* d_out, int out_size)
{
    const int*   x        = (const int*)d_in[0];
    const int*   ei       = (const int*)d_in[1];
    const int*   ea       = (const int*)d_in[2];
    const int*   batch    = (const int*)d_in[3];
    const float* vec      = (const float*)d_in[4];
    const float* blockemb = (const float*)d_in[5];
    const float* bondemb  = (const float*)d_in[6];
    const float* w1       = (const float*)d_in[7];
    const float* b1       = (const float*)d_in[8];
    const float* w2       = (const float*)d_in[9];
    const float* b2       = (const float*)d_in[10];
    const float* root     = (const float*)d_in[11];
    const float* cb       = (const float*)d_in[12];
    const float* wih      = (const float*)d_in[13];
    const float* whh      = (const float*)d_in[14];
    const float* bih      = (const float*)d_in[15];
    const float* bhh      = (const float*)d_in[16];

    const int n = in_sizes[0];
    const int E = in_sizes[1] / 2;
    const int G = in_sizes[4] / 64;

    float *h_p, *rdeg_p, *cnt_p;
    cudaGetSymbolAddress((void**)&h_p,    g_h);
    cudaGetSymbolAddress((void**)&rdeg_p, g_rdeg);
    cudaGetSymbolAddress((void**)&cnt_p,  g_cnt);

    cudaFuncSetAttribute(init_mma, cudaFuncAttributeMaxDynamicSharedMemorySize, INIT_SMEM);
    cudaFuncSetAttribute(node_mma, cudaFuncAttributeMaxDynamicSharedMemorySize, NODE_SMEM);

    cudaMemsetAsync(rdeg_p, 0, (size_t)n * sizeof(float));
    cudaMemsetAsync(cnt_p,  0, (size_t)G * sizeof(float));
    cudaMemsetAsync(d_out,  0, (size_t)out_size * sizeof(float));

    pack_kernel<<<42, 512>>>(root, cb, wih, whh, bih, bhh, w1, b1, w2, b2, bondemb);
    deg_kernel<<<(E + 255) / 256, 256>>>(ei, rdeg_p, E);
    cnt_kernel<<<(n + 255) / 256, 256>>>(batch, cnt_p, n);
    rdeg_kernel<<<(n + 255) / 256, 256>>>(rdeg_p, n);

    init_mma<<<148, 512, INIT_SMEM>>>(x, batch, vec, blockemb, h_p, n);

    for (int s = 0; s < 4; s++) {
        edge_kernel<<<(E * 16 + 255) / 256, 256>>>(ei, ea, bondemb, h_p, rdeg_p, E);
        node_mma<<<148, 512, NODE_SMEM>>>(h_p, batch, (float*)d_out, n, s == 3 ? 1 : 0);
    }

    div_kernel<<<(G * 64 + 255) / 256, 256>>>((float*)d_out, cnt_p, G * 64);
}

// round 12
// speedup vs baseline: 1.4519x; 1.1453x over previous
#include <cuda_runtime.h>
#include <cuda_fp16.h>
#include <math.h>
#include <stdint.h>

#define MAXN 50000
#define MAXE 100000
#define MAXG 4096

typedef unsigned long long ull;

extern __shared__ __align__(1024) char smem_raw[];

// ---------------- device scratch -------------------------------------------
__device__ float g_h[MAXN * 64];
__device__ float g_sacc[MAXN * 20];   // per-(dst, bond-type) accumulator; zero invariant
__device__ float g_rdeg[MAXN];
__device__ float g_cnt[MAXG];
__device__ ull   g_pk_node[7680];     // root/gates 7*1024 + bond 512 (fp16 B-frags)
__device__ ull   g_pk_init[3072];     // w1 2048 + w2 1024
__device__ float g_bias_node[320];
__device__ float g_bias_init[128];

__device__ __forceinline__ float sigf_(float x)   { return 1.0f / (1.0f + __expf(-x)); }
__device__ __forceinline__ float tanhf_(float x)  { return 2.0f * sigf_(2.0f * x) - 1.0f; }
__device__ __forceinline__ float leakyf_(float x) { return x > 0.0f ? x : 0.01f * x; }

__device__ __forceinline__ uint32_t h2_(float a, float b) {
    __half2 h = __floats2half2_rn(a, b);
    return *(uint32_t*)&h;
}

// m16n8k16 fp16 MMA, fp32 accum (portable PTX)
__device__ __forceinline__ void mma16(float* c, const uint32_t* a, ull b) {
    uint32_t b0 = (uint32_t)b, b1 = (uint32_t)(b >> 32);
    asm volatile(
        "mma.sync.aligned.m16n8k16.row.col.f32.f16.f16.f32 "
        "{%0,%1,%2,%3}, {%4,%5,%6,%7}, {%8,%9}, {%0,%1,%2,%3};"
        : "+f"(c[0]), "+f"(c[1]), "+f"(c[2]), "+f"(c[3])
        : "r"(a[0]), "r"(a[1]), "r"(a[2]), "r"(a[3]), "r"(b0), "r"(b1));
}

// A-tile fragment layout: per kk (16 feats), uint4 frag[32]; frag[lane]={a0,a1,a2,a3}.
// One conflict-free LDS.128 per thread per kk.
__device__ __forceinline__ void load_frag16(uint32_t* a, const uint4* sf4, int kk, int lane) {
    uint4 v = sf4[kk * 32 + lane];
    a[0] = v.x; a[1] = v.y; a[2] = v.z; a[3] = v.w;
}
// store half2 (feats f, f+1, f even) of local row rr (0..15) into fragment layout
__device__ __forceinline__ void fstore16(uint32_t* sf32, int rr, int f, uint32_t val) {
    int kk = f >> 4, kf = f & 15;
    int g = rr & 7, jr = (rr >> 3) & 1;
    int t = (kf >> 1) & 3;
    int j = jr + ((kf >= 8) ? 2 : 0);
    sf32[(kk * 32 + g * 4 + t) * 4 + j] = val;
}

#define A_ROOT 0
#define A_IHR  1
#define A_HHR  2
#define A_IHZ  3
#define A_HHZ  4
#define A_IHN  5
#define A_HHN  6
#define BOND_OFF 7168
// node smem: pk 7680 ull | h_f 8*256 | m_f 8*256 | s_f 8*128 | bias 320 f
#define NODE_SMEM   ((7680 + 2048 + 2048 + 1024) * 8 + 320 * 4)
// init smem: pk 3072 | in_f 8*512 | o1_f 8*256 | bias 128 f
#define INIT_SMEM   ((3072 + 4096 + 2048) * 8 + 128 * 4)

// ---------------- pack kernel: fp16 B-fragments --------------------------------
__global__ void pack_kernel(
    const float* __restrict__ root, const float* __restrict__ cb,
    const float* __restrict__ wih, const float* __restrict__ whh,
    const float* __restrict__ bih, const float* __restrict__ bhh,
    const float* __restrict__ w1, const float* __restrict__ b1,
    const float* __restrict__ w2, const float* __restrict__ b2,
    const float* __restrict__ bondemb)
{
    for (int i = blockIdx.x * blockDim.x + threadIdx.x; i < 11200; i += gridDim.x * blockDim.x) {
        if (i < 7168) {
            // root + 6 gates: [arr][hf][nt][kk(4)][lane]
            int arr = i >> 10, rem = i & 1023;
            int hf = rem >> 9, nt = (rem >> 7) & 3, kk = (rem >> 5) & 3, ln = rem & 31;
            int nn = hf * 32 + nt * 8 + (ln >> 2);
            int k0 = kk * 16 + 2 * (ln & 3);
            float v0, v1, v2, v3;
            switch (arr) {
                case A_ROOT:
                    v0 = root[k0 * 64 + nn]; v1 = root[(k0 + 1) * 64 + nn];
                    v2 = root[(k0 + 8) * 64 + nn]; v3 = root[(k0 + 9) * 64 + nn]; break;
                case A_IHR: { const float* W = wih + (size_t)nn * 64;
                    v0 = W[k0]; v1 = W[k0 + 1]; v2 = W[k0 + 8]; v3 = W[k0 + 9]; } break;
                case A_HHR: { const float* W = whh + (size_t)nn * 64;
                    v0 = W[k0]; v1 = W[k0 + 1]; v2 = W[k0 + 8]; v3 = W[k0 + 9]; } break;
                case A_IHZ: { const float* W = wih + (size_t)(64 + nn) * 64;
                    v0 = W[k0]; v1 = W[k0 + 1]; v2 = W[k0 + 8]; v3 = W[k0 + 9]; } break;
                case A_HHZ: { const float* W = whh + (size_t)(64 + nn) * 64;
                    v0 = W[k0]; v1 = W[k0 + 1]; v2 = W[k0 + 8]; v3 = W[k0 + 9]; } break;
                case A_IHN: { const float* W = wih + (size_t)(128 + nn) * 64;
                    v0 = W[k0]; v1 = W[k0 + 1]; v2 = W[k0 + 8]; v3 = W[k0 + 9]; } break;
                default:    { const float* W = whh + (size_t)(128 + nn) * 64;
                    v0 = W[k0]; v1 = W[k0 + 1]; v2 = W[k0 + 8]; v3 = W[k0 + 9]; } break;
            }
            g_pk_node[i] = (ull)h2_(v0, v1) | ((ull)h2_(v2, v3) << 32);
        } else if (i < 7680) {
            // bond: [hf][nt][kk(2)][lane], B[n][k] = bondemb[k*64+n], K pad 20->32
            int j = i - 7168;
            int hf = (j >> 8) & 1, nt = (j >> 6) & 3, kk = (j >> 5) & 1, ln = j & 31;
            int nn = hf * 32 + nt * 8 + (ln >> 2);
            int k0 = kk * 16 + 2 * (ln & 3);
            float v[4];
            #pragma unroll
            for (int d = 0; d < 4; d++) {
                int k = k0 + (d >> 1) * 8 + (d & 1);
                v[d] = (k < 20) ? bondemb[k * 64 + nn] : 0.0f;
            }
            g_pk_node[BOND_OFF + j] = (ull)h2_(v[0], v[1]) | ((ull)h2_(v[2], v[3]) << 32);
        } else if (i < 10752) {
            int j = i - 7680;
            if (j < 2048) {  // w1: [hf][nt][kk(8)][lane], K=128
                int hf = j >> 10, nt = (j >> 8) & 3, kk = (j >> 5) & 7, ln = j & 31;
                int nn = hf * 32 + nt * 8 + (ln >> 2);
                int k0 = kk * 16 + 2 * (ln & 3);
                const float* W = w1 + (size_t)nn * 128;
                g_pk_init[j] = (ull)h2_(W[k0], W[k0 + 1]) | ((ull)h2_(W[k0 + 8], W[k0 + 9]) << 32);
            } else {        // w2: [hf][nt][kk(4)][lane], K=64
                int jj = j - 2048;
                int hf = jj >> 9, nt = (jj >> 7) & 3, kk = (jj >> 5) & 3, ln = jj & 31;
                int nn = hf * 32 + nt * 8 + (ln >> 2);
                int k0 = kk * 16 + 2 * (ln & 3);
                const float* W = w2 + (size_t)nn * 64;
                g_pk_init[j] = (ull)h2_(W[k0], W[k0 + 1]) | ((ull)h2_(W[k0 + 8], W[k0 + 9]) << 32);
            }
        } else if (i < 11072) {
            int j = i - 10752;
            float v;
            if (j < 128)      v = bih[j] + bhh[j];
            else if (j < 192) v = bih[128 + (j - 128)];
            else if (j < 256) v = bhh[128 + (j - 192)];
            else              v = cb[j - 256];
            g_bias_node[j] = v;
        } else {
            int j = i - 11072;
            g_bias_init[j] = (j < 64) ? b1[j] : b2[j - 64];
        }
    }
}

// ---------------- degree / counts ----------------------------------------------
__global__ void deg_kernel(const int* __restrict__ ei, float* __restrict__ deg, int E) {
    int e = blockIdx.x * blockDim.x + threadIdx.x;
    if (e < E) atomicAdd(&deg[ei[E + e]], 1.0f);
}
__global__ void rdeg_kernel(float* deg, int n) {
    int i = blockIdx.x * blockDim.x + threadIdx.x;
    if (i < n) deg[i] = 1.0f / fmaxf(deg[i], 1.0f);
}
__global__ void cnt_kernel(const int* __restrict__ batch, float* __restrict__ cnt, int n) {
    int i = blockIdx.x * blockDim.x + threadIdx.x;
    if (i < n) atomicAdd(&cnt[batch[i]], 1.0f);
}

// ---------------- init MLP: fp16 m16n8k16 ---------------------------------------
__global__ void __launch_bounds__(512, 1) init_mma(
    const int* __restrict__ x, const int* __restrict__ batch,
    const float* __restrict__ vec, const float* __restrict__ blockemb,
    float* __restrict__ h, int n)
{
    ull* pk   = (ull*)smem_raw;        // [3072]
    ull* in_f = pk + 3072;             // [8][512]  (strip = 8kk x 32 uint4)
    ull* o1_f = in_f + 4096;           // [8][256]
    float* b1s = (float*)(o1_f + 2048);
    float* b2s = b1s + 64;

    const int tid  = threadIdx.x;
    const int w    = tid >> 5;
    const int lane = tid & 31;
    const int p    = w & 7;
    const int half = w >> 3;
    const int n0   = half * 32;

    for (int i = tid; i < 3072; i += 512) pk[i] = g_pk_init[i];
    if (tid < 128) b1s[tid] = g_bias_init[tid];
    __syncthreads();

    const ull* w1pk = pk;
    const ull* w2pk = pk + 2048;

    const int ntiles = (n + 127) >> 7;
    for (int tile = blockIdx.x; tile < ntiles; tile += gridDim.x) {
        const int nb0 = tile << 7;

        // gather [emb | vec] -> fp16 fragment smem (128 rows x 128 feats)
        {
            int row = tid >> 2, cpart = (tid & 3) * 32, gr = nb0 + row;
            int strip = row >> 4, rr = row & 15;
            uint32_t* sf = (uint32_t*)(in_f + strip * 512);
            if (gr < n) {
                const float* src = (cpart < 64)
                    ? (blockemb + (size_t)x[gr] * 64 + cpart)
                    : (vec + (size_t)batch[gr] * 64 + (cpart - 64));
                #pragma unroll
                for (int c = 0; c < 8; c++) {
                    float4 qv = ((const float4*)src)[c];
                    int f = cpart + c * 4;
                    fstore16(sf, rr, f,     h2_(qv.x, qv.y));
                    fstore16(sf, rr, f + 2, h2_(qv.z, qv.w));
                }
            } else {
                #pragma unroll
                for (int c = 0; c < 16; c++)
                    fstore16(sf, rr, cpart + c * 2, 0u);
            }
        }
        __syncthreads();

        // GEMM1: o1 = leaky(in @ w1^T + b1); per warp 16x32, 8 kk x 4 nt
        float racc[16];
        #pragma unroll
        for (int t = 0; t < 16; t++) racc[t] = 0.0f;
        const uint4* istrip = (const uint4*)(in_f + p * 512);
        #pragma unroll
        for (int kk = 0; kk < 8; kk++) {
            uint32_t a[4];
            load_frag16(a, istrip, kk, lane);
            #pragma unroll
            for (int nt = 0; nt < 4; nt++)
                mma16(racc + nt * 4, a, w1pk[half * 1024 + nt * 256 + kk * 32 + lane]);
        }
        {
            uint32_t* of = (uint32_t*)(o1_f + p * 256);
            int rr0 = lane >> 2;
            #pragma unroll
            for (int nt = 0; nt < 4; nt++) {
                int colb = n0 + nt * 8 + (lane & 3) * 2;
                float c0 = b1s[colb], c1 = b1s[colb + 1];
                #pragma unroll
                for (int qq = 0; qq < 2; qq++)
                    fstore16(of, rr0 + qq * 8, colb,
                             h2_(leakyf_(racc[nt * 4 + qq * 2] + c0),
                                 leakyf_(racc[nt * 4 + qq * 2 + 1] + c1)));
            }
        }
        __syncthreads();

        // GEMM2: h0 = o1 @ w2^T + b2; 4 kk x 4 nt
        float acc2[16];
        #pragma unroll
        for (int t = 0; t < 16; t++) acc2[t] = 0.0f;
        const uint4* ostrip = (const uint4*)(o1_f + p * 256);
        #pragma unroll
        for (int kk = 0; kk < 4; kk++) {
            uint32_t a[4];
            load_frag16(a, ostrip, kk, lane);
            #pragma unroll
            for (int nt = 0; nt < 4; nt++)
                mma16(acc2 + nt * 4, a, w2pk[half * 512 + nt * 128 + kk * 32 + lane]);
        }
        #pragma unroll
        for (int nt = 0; nt < 4; nt++) {
            int colb = n0 + nt * 8 + (lane & 3) * 2;
            float c0 = b2s[colb], c1 = b2s[colb + 1];
            #pragma unroll
            for (int qq = 0; qq < 2; qq++) {
                int gr = nb0 + p * 16 + (lane >> 2) + qq * 8;
                if (gr < n)
                    *(float2*)(h + (size_t)gr * 64 + colb) =
                        make_float2(acc2[nt * 4 + qq * 2] + c0, acc2[nt * 4 + qq * 2 + 1] + c1);
            }
        }
        __syncthreads();
    }
}

// ---------------- edge kernel: 1 scalar atomic per edge -------------------------
__global__ void edge_kernel(const int* __restrict__ ei, const int* __restrict__ ea,
                            const float* __restrict__ bond, const float* __restrict__ h,
                            const float* __restrict__ rdeg, int E)
{
    int idx = blockIdx.x * blockDim.x + threadIdx.x;
    int e = idx >> 4;
    int l = idx & 15;
    bool valid = (e < E);
    int ec = valid ? e : (E - 1);
    int src = ei[ec], dst = ei[E + ec];
    int a0  = ea[2 * ec], a1 = ea[2 * ec + 1];
    float4 hv = *(const float4*)(h + (size_t)src * 64 + 4 * l);
    float4 e0 = *(const float4*)(bond + (size_t)a0 * 64 + 4 * l);
    float s = hv.x * e0.x + hv.y * e0.y + hv.z * e0.z + hv.w * e0.w;
    #pragma unroll
    for (int o = 8; o; o >>= 1) s += __shfl_xor_sync(0xffffffffu, s, o);
    if (valid && l == 0)
        atomicAdd(&g_sacc[(size_t)dst * 20 + a1], s * __ldg(&rdeg[dst]));
}

// ---------------- node kernel: fp16 m16n8k16, S@bond fused, pool fusion ---------
__global__ void __launch_bounds__(512, 1) node_mma(
    float* __restrict__ h, const int* __restrict__ batch,
    float* __restrict__ out, int n, int last)
{
    ull* pk  = (ull*)smem_raw;          // [7680]
    ull* h_f = pk + 7680;               // [8][256]
    ull* m_f = h_f + 2048;              // [8][256]
    ull* s_f = m_f + 2048;              // [8][128]
    float* br_s  = (float*)(s_f + 1024);
    float* bz_s  = br_s + 64;
    float* bin_s = bz_s + 64;
    float* bhn_s = bin_s + 64;
    float* cb_s  = bhn_s + 64;

    const int tid  = threadIdx.x;
    const int w    = tid >> 5;
    const int lane = tid & 31;
    const int p    = w & 7;
    const int half = w >> 3;
    const int n0   = half * 32;
    const int arow = p * 16 + (lane >> 2);

    for (int i = tid; i < 7680; i += 512) pk[i] = g_pk_node[i];
    if (tid < 320) br_s[tid] = g_bias_node[tid];
    __syncthreads();

    const int ntiles = (n + 127) >> 7;
    for (int tile = blockIdx.x; tile < ntiles; tile += gridDim.x) {
        const int nb0 = tile << 7;

        // H tile -> fp16 fragment smem
        {
            int row = tid >> 2, cbase = (tid & 3) * 16, gr = nb0 + row;
            int strip = row >> 4, rr = row & 15;
            uint32_t* sf = (uint32_t*)(h_f + strip * 256);
            if (gr < n) {
                const float4* pp = (const float4*)(h + (size_t)gr * 64 + cbase);
                #pragma unroll
                for (int c = 0; c < 4; c++) {
                    float4 qv = pp[c];
                    int f = cbase + c * 4;
                    fstore16(sf, rr, f,     h2_(qv.x, qv.y));
                    fstore16(sf, rr, f + 2, h2_(qv.z, qv.w));
                }
            } else {
                #pragma unroll
                for (int c = 0; c < 8; c++)
                    fstore16(sf, rr, cbase + c * 2, 0u);
            }
        }
        // S tile (20 -> pad 32) -> fp16 fragment smem; zero g_sacc for next step
        {
            int row = tid >> 2, gr = nb0 + row;
            int c0 = (tid & 3) * 8;
            int strip = row >> 4, rr = row & 15;
            uint32_t* sf = (uint32_t*)(s_f + strip * 128);
            float* sp = g_sacc + (size_t)gr * 20;
            #pragma unroll
            for (int c = 0; c < 4; c++) {
                int f = c0 + 2 * c;
                float va = 0.0f, vb = 0.0f;
                if (gr < n) {
                    if (f < 20)     { va = sp[f];     sp[f] = 0.0f; }
                    if (f + 1 < 20) { vb = sp[f + 1]; sp[f + 1] = 0.0f; }
                }
                fstore16(sf, rr, f, h2_(va, vb));
            }
        }
        __syncthreads();

        const uint4* hstrip = (const uint4*)(h_f + p * 256);
        const uint4* mstrip = (const uint4*)(m_f + p * 256);
        const uint4* sstrip = (const uint4*)(s_f + p * 128);

        // GEMM1: R = H @ root (4 kk) + S @ bond (2 kk)
        float racc[16];
        #pragma unroll
        for (int t = 0; t < 16; t++) racc[t] = 0.0f;
        #pragma unroll
        for (int kk = 0; kk < 4; kk++) {
            uint32_t a[4];
            load_frag16(a, hstrip, kk, lane);
            #pragma unroll
            for (int nt = 0; nt < 4; nt++)
                mma16(racc + nt * 4, a, pk[A_ROOT * 1024 + half * 512 + nt * 128 + kk * 32 + lane]);
        }
        #pragma unroll
        for (int kk = 0; kk < 2; kk++) {
            uint32_t a[4];
            load_frag16(a, sstrip, kk, lane);
            #pragma unroll
            for (int nt = 0; nt < 4; nt++)
                mma16(racc + nt * 4, a, pk[BOND_OFF + half * 256 + nt * 64 + kk * 32 + lane]);
        }
        // epilogue A: M = leaky(R + cb) -> fp16 fragment m_f
        {
            uint32_t* mf = (uint32_t*)(m_f + p * 256);
            int rr0 = lane >> 2;
            #pragma unroll
            for (int nt = 0; nt < 4; nt++) {
                int colb = n0 + nt * 8 + (lane & 3) * 2;
                float cb0 = cb_s[colb], cb1 = cb_s[colb + 1];
                #pragma unroll
                for (int qq = 0; qq < 2; qq++)
                    fstore16(mf, rr0 + qq * 8, colb,
                             h2_(leakyf_(racc[nt * 4 + qq * 2] + cb0),
                                 leakyf_(racc[nt * 4 + qq * 2 + 1] + cb1)));
            }
        }
        __syncthreads();

        // prefetch h_old (fp32) + batch ids for last step
        float2 hof[8];
        int bg[2];
        #pragma unroll
        for (int qq = 0; qq < 2; qq++) {
            int gr = nb0 + arow + qq * 8;
            bg[qq] = (last && gr < n) ? batch[gr] : 0;
        }
        #pragma unroll
        for (int nt = 0; nt < 4; nt++) {
            int colb = n0 + nt * 8 + (lane & 3) * 2;
            #pragma unroll
            for (int qq = 0; qq < 2; qq++) {
                int gr = nb0 + arow + qq * 8;
                hof[nt * 2 + qq] = (gr < n) ? *(const float2*)(h + (size_t)gr * 64 + colb)
                                            : make_float2(0.0f, 0.0f);
            }
        }

        // GEMM2: gates, 4 kk x 6 arrays x 4 nt
        float rg[16], zg[16], ig[16], hg[16];
        #pragma unroll
        for (int t = 0; t < 16; t++) { rg[t] = zg[t] = ig[t] = hg[t] = 0.0f; }
        #pragma unroll
        for (int kk = 0; kk < 4; kk++) {
            uint32_t aM[4], aH[4];
            load_frag16(aM, mstrip, kk, lane);
            load_frag16(aH, hstrip, kk, lane);
            int pkb = half * 512 + kk * 32 + lane;
            #pragma unroll
            for (int nt = 0; nt < 4; nt++) {
                int o = pkb + nt * 128;
                mma16(rg + nt * 4, aM, pk[A_IHR * 1024 + o]);
                mma16(rg + nt * 4, aH, pk[A_HHR * 1024 + o]);
                mma16(zg + nt * 4, aM, pk[A_IHZ * 1024 + o]);
                mma16(zg + nt * 4, aH, pk[A_HHZ * 1024 + o]);
                mma16(ig + nt * 4, aM, pk[A_IHN * 1024 + o]);
                mma16(hg + nt * 4, aH, pk[A_HHN * 1024 + o]);
            }
        }

        // epilogue: GRU gate math; last step pools into out
        #pragma unroll
        for (int nt = 0; nt < 4; nt++) {
            int colb = n0 + nt * 8 + (lane & 3) * 2;
            float br0 = br_s[colb], br1 = br_s[colb + 1];
            float bz0 = bz_s[colb], bz1 = bz_s[colb + 1];
            float bi0 = bin_s[colb], bi1 = bin_s[colb + 1];
            float bh0 = bhn_s[colb], bh1 = bhn_s[colb + 1];
            #pragma unroll
            for (int qq = 0; qq < 2; qq++) {
                int gr = nb0 + arow + qq * 8;
                if (gr < n) {
                    int idx = nt * 4 + qq * 2;
                    float2 ho = hof[nt * 2 + qq];
                    float r0v = sigf_(rg[idx]     + br0);
                    float r1v = sigf_(rg[idx + 1] + br1);
                    float z0v = sigf_(zg[idx]     + bz0);
                    float z1v = sigf_(zg[idx + 1] + bz1);
                    float n0v = tanhf_(ig[idx]     + bi0 + r0v * (hg[idx]     + bh0));
                    float n1v = tanhf_(ig[idx + 1] + bi1 + r1v * (hg[idx + 1] + bh1));
                    float ox = (1.0f - z0v) * n0v + z0v * ho.x;
                    float oy = (1.0f - z1v) * n1v + z1v * ho.y;
                    if (last) {
                        float* op = out + (size_t)bg[qq] * 64 + colb;
                        asm volatile("red.global.add.v2.f32 [%0], {%1,%2};"
                                     :: "l"(op), "f"(ox), "f"(oy) : "memory");
                    } else {
                        *(float2*)(h + (size_t)gr * 64 + colb) = make_float2(ox, oy);
                    }
                }
            }
        }
        __syncthreads();
    }
}

// ---------------- div ------------------------------------------------------------
__global__ void div_kernel(float* out, const float* __restrict__ cnt, int total)
{
    int i = blockIdx.x * blockDim.x + threadIdx.x;
    if (i < total) out[i] /= fmaxf(cnt[i >> 6], 1.0f);
}

// ---------------- launch ----------------------------------------------------------
extern "C" void kernel_launch(void* const* d_in, const int* in_sizes, int n_in,
                              void* d_out, int out_size)
{
    const int*   x        = (const int*)d_in[0];
    const int*   ei       = (const int*)d_in[1];
    const int*   ea       = (const int*)d_in[2];
    const int*   batch    = (const int*)d_in[3];
    const float* vec      = (const float*)d_in[4];
    const float* blockemb = (const float*)d_in[5];
    const float* bondemb  = (const float*)d_in[6];
    const float* w1       = (const float*)d_in[7];
    const float* b1       = (const float*)d_in[8];
    const float* w2       = (const float*)d_in[9];
    const float* b2       = (const float*)d_in[10];
    const float* root     = (const float*)d_in[11];
    const float* cb       = (const float*)d_in[12];
    const float* wih      = (const float*)d_in[13];
    const float* whh      = (const float*)d_in[14];
    const float* bih      = (const float*)d_in[15];
    const float* bhh      = (const float*)d_in[16];

    const int n = in_sizes[0];
    const int E = in_sizes[1] / 2;
    const int G = in_sizes[4] / 64;

    float *h_p, *rdeg_p, *cnt_p;
    cudaGetSymbolAddress((void**)&h_p,    g_h);
    cudaGetSymbolAddress((void**)&rdeg_p, g_rdeg);
    cudaGetSymbolAddress((void**)&cnt_p,  g_cnt);

    cudaFuncSetAttribute(init_mma, cudaFuncAttributeMaxDynamicSharedMemorySize, INIT_SMEM);
    cudaFuncSetAttribute(node_mma, cudaFuncAttributeMaxDynamicSharedMemorySize, NODE_SMEM);

    cudaMemsetAsync(rdeg_p, 0, (size_t)n * sizeof(float));
    cudaMemsetAsync(cnt_p,  0, (size_t)G * sizeof(float));
    cudaMemsetAsync(d_out,  0, (size_t)out_size * sizeof(float));

    pack_kernel<<<22, 512>>>(root, cb, wih, whh, bih, bhh, w1, b1, w2, b2, bondemb);
    deg_kernel<<<(E + 255) / 256, 256>>>(ei, rdeg_p, E);
    cnt_kernel<<<(n + 255) / 256, 256>>>(batch, cnt_p, n);
    rdeg_kernel<<<(n + 255) / 256, 256>>>(rdeg_p, n);

    init_mma<<<148, 512, INIT_SMEM>>>(x, batch, vec, blockemb, h_p, n);

    for (int s = 0; s < 4; s++) {
        edge_kernel<<<(E * 16 + 255) / 256, 256>>>(ei, ea, bondemb, h_p, rdeg_p, E);
        node_mma<<<148, 512, NODE_SMEM>>>(h_p, batch, (float*)d_out, n, s == 3 ? 1 : 0);
    }

    div_kernel<<<(G * 64 + 255) / 256, 256>>>((float*)d_out, cnt_p, G * 64);
}

// round 13
// speedup vs baseline: 1.5051x; 1.0366x over previous
#include <cuda_runtime.h>
#include <cuda_fp16.h>
#include <math.h>
#include <stdint.h>

#define MAXN 50000
#define MAXE 100000
#define MAXG 4096

typedef unsigned long long ull;

extern __shared__ __align__(1024) char smem_raw[];

// ---------------- device scratch -------------------------------------------
__device__ float g_h[MAXN * 64];
__device__ float g_sacc[MAXN * 20];   // zero invariant (node_mma re-zeroes)
__device__ float g_deg[MAXN];         // zero invariant (recip re-zeroes)
__device__ float g_cntb[MAXG];        // zero invariant (recip re-zeroes)
__device__ float g_rdeg[MAXN];
__device__ float g_rcnt[MAXG];
__device__ ull   g_pk_node[7680];
__device__ ull   g_pk_init[3072];
__device__ float g_bias_node[320];
__device__ float g_bias_init[128];

__device__ __forceinline__ float sigf_(float x)   { return 1.0f / (1.0f + __expf(-x)); }
__device__ __forceinline__ float tanhf_(float x)  { return 2.0f * sigf_(2.0f * x) - 1.0f; }
__device__ __forceinline__ float leakyf_(float x) { return x > 0.0f ? x : 0.01f * x; }

__device__ __forceinline__ uint32_t h2_(float a, float b) {
    __half2 h = __floats2half2_rn(a, b);
    return *(uint32_t*)&h;
}

// m16n8k16 fp16 MMA, fp32 accum (portable PTX)
__device__ __forceinline__ void mma16(float* c, const uint32_t* a, ull b) {
    uint32_t b0 = (uint32_t)b, b1 = (uint32_t)(b >> 32);
    asm volatile(
        "mma.sync.aligned.m16n8k16.row.col.f32.f16.f16.f32 "
        "{%0,%1,%2,%3}, {%4,%5,%6,%7}, {%8,%9}, {%0,%1,%2,%3};"
        : "+f"(c[0]), "+f"(c[1]), "+f"(c[2]), "+f"(c[3])
        : "r"(a[0]), "r"(a[1]), "r"(a[2]), "r"(a[3]), "r"(b0), "r"(b1));
}

__device__ __forceinline__ void load_frag16(uint32_t* a, const uint4* sf4, int kk, int lane) {
    uint4 v = sf4[kk * 32 + lane];
    a[0] = v.x; a[1] = v.y; a[2] = v.z; a[3] = v.w;
}
__device__ __forceinline__ void fstore16(uint32_t* sf32, int rr, int f, uint32_t val) {
    int kk = f >> 4, kf = f & 15;
    int g = rr & 7, jr = (rr >> 3) & 1;
    int t = (kf >> 1) & 3;
    int j = jr + ((kf >= 8) ? 2 : 0);
    sf32[(kk * 32 + g * 4 + t) * 4 + j] = val;
}

#define A_ROOT 0
#define A_IHR  1
#define A_HHR  2
#define A_IHZ  3
#define A_HHZ  4
#define A_IHN  5
#define A_HHN  6
#define BOND_OFF 7168
#define NODE_SMEM   ((7680 + 2048 + 2048 + 1024) * 8 + 320 * 4)
#define INIT_SMEM   ((3072 + 4096 + 2048) * 8 + 128 * 4)

// ---------------- fused prologue: pack weights + deg + cnt atomics -------------
__global__ void prep_kernel(
    const float* __restrict__ root, const float* __restrict__ cb,
    const float* __restrict__ wih, const float* __restrict__ whh,
    const float* __restrict__ bih, const float* __restrict__ bhh,
    const float* __restrict__ w1, const float* __restrict__ b1,
    const float* __restrict__ w2, const float* __restrict__ b2,
    const float* __restrict__ bondemb,
    const int* __restrict__ ei, const int* __restrict__ batch,
    int E, int n)
{
    int total = 11200 + E + n;
    for (int i = blockIdx.x * blockDim.x + threadIdx.x; i < total; i += gridDim.x * blockDim.x) {
        if (i < 7168) {
            int arr = i >> 10, rem = i & 1023;
            int hf = rem >> 9, nt = (rem >> 7) & 3, kk = (rem >> 5) & 3, ln = rem & 31;
            int nn = hf * 32 + nt * 8 + (ln >> 2);
            int k0 = kk * 16 + 2 * (ln & 3);
            float v0, v1, v2, v3;
            switch (arr) {
                case A_ROOT:
                    v0 = root[k0 * 64 + nn]; v1 = root[(k0 + 1) * 64 + nn];
                    v2 = root[(k0 + 8) * 64 + nn]; v3 = root[(k0 + 9) * 64 + nn]; break;
                case A_IHR: { const float* W = wih + (size_t)nn * 64;
                    v0 = W[k0]; v1 = W[k0 + 1]; v2 = W[k0 + 8]; v3 = W[k0 + 9]; } break;
                case A_HHR: { const float* W = whh + (size_t)nn * 64;
                    v0 = W[k0]; v1 = W[k0 + 1]; v2 = W[k0 + 8]; v3 = W[k0 + 9]; } break;
                case A_IHZ: { const float* W = wih + (size_t)(64 + nn) * 64;
                    v0 = W[k0]; v1 = W[k0 + 1]; v2 = W[k0 + 8]; v3 = W[k0 + 9]; } break;
                case A_HHZ: { const float* W = whh + (size_t)(64 + nn) * 64;
                    v0 = W[k0]; v1 = W[k0 + 1]; v2 = W[k0 + 8]; v3 = W[k0 + 9]; } break;
                case A_IHN: { const float* W = wih + (size_t)(128 + nn) * 64;
                    v0 = W[k0]; v1 = W[k0 + 1]; v2 = W[k0 + 8]; v3 = W[k0 + 9]; } break;
                default:    { const float* W = whh + (size_t)(128 + nn) * 64;
                    v0 = W[k0]; v1 = W[k0 + 1]; v2 = W[k0 + 8]; v3 = W[k0 + 9]; } break;
            }
            g_pk_node[i] = (ull)h2_(v0, v1) | ((ull)h2_(v2, v3) << 32);
        } else if (i < 7680) {
            int j = i - 7168;
            int hf = (j >> 8) & 1, nt = (j >> 6) & 3, kk = (j >> 5) & 1, ln = j & 31;
            int nn = hf * 32 + nt * 8 + (ln >> 2);
            int k0 = kk * 16 + 2 * (ln & 3);
            float v[4];
            #pragma unroll
            for (int d = 0; d < 4; d++) {
                int k = k0 + (d >> 1) * 8 + (d & 1);
                v[d] = (k < 20) ? bondemb[k * 64 + nn] : 0.0f;
            }
            g_pk_node[BOND_OFF + j] = (ull)h2_(v[0], v[1]) | ((ull)h2_(v[2], v[3]) << 32);
        } else if (i < 10752) {
            int j = i - 7680;
            if (j < 2048) {
                int hf = j >> 10, nt = (j >> 8) & 3, kk = (j >> 5) & 7, ln = j & 31;
                int nn = hf * 32 + nt * 8 + (ln >> 2);
                int k0 = kk * 16 + 2 * (ln & 3);
                const float* W = w1 + (size_t)nn * 128;
                g_pk_init[j] = (ull)h2_(W[k0], W[k0 + 1]) | ((ull)h2_(W[k0 + 8], W[k0 + 9]) << 32);
            } else {
                int jj = j - 2048;
                int hf = jj >> 9, nt = (jj >> 7) & 3, kk = (jj >> 5) & 3, ln = jj & 31;
                int nn = hf * 32 + nt * 8 + (ln >> 2);
                int k0 = kk * 16 + 2 * (ln & 3);
                const float* W = w2 + (size_t)nn * 64;
                g_pk_init[j] = (ull)h2_(W[k0], W[k0 + 1]) | ((ull)h2_(W[k0 + 8], W[k0 + 9]) << 32);
            }
        } else if (i < 11072) {
            int j = i - 10752;
            float v;
            if (j < 128)      v = bih[j] + bhh[j];
            else if (j < 192) v = bih[128 + (j - 128)];
            else if (j < 256) v = bhh[128 + (j - 192)];
            else              v = cb[j - 256];
            g_bias_node[j] = v;
        } else if (i < 11200) {
            int j = i - 11072;
            g_bias_init[j] = (j < 64) ? b1[j] : b2[j - 64];
        } else if (i < 11200 + E) {
            atomicAdd(&g_deg[ei[E + (i - 11200)]], 1.0f);
        } else {
            atomicAdd(&g_cntb[batch[i - 11200 - E]], 1.0f);
        }
    }
}

// ---------------- reciprocal kernel: rdeg/rcnt + re-zero deg/cnt ---------------
__global__ void recip_kernel(int n, int G) {
    int i = blockIdx.x * blockDim.x + threadIdx.x;
    if (i < n) {
        g_rdeg[i] = 1.0f / fmaxf(g_deg[i], 1.0f);
        g_deg[i] = 0.0f;
    }
    if (i < G) {
        g_rcnt[i] = 1.0f / fmaxf(g_cntb[i], 1.0f);
        g_cntb[i] = 0.0f;
    }
}

// ---------------- init MLP: fp16 m16n8k16 ---------------------------------------
__global__ void __launch_bounds__(512, 1) init_mma(
    const int* __restrict__ x, const int* __restrict__ batch,
    const float* __restrict__ vec, const float* __restrict__ blockemb,
    float* __restrict__ h, int n)
{
    ull* pk   = (ull*)smem_raw;
    ull* in_f = pk + 3072;
    ull* o1_f = in_f + 4096;
    float* b1s = (float*)(o1_f + 2048);
    float* b2s = b1s + 64;

    const int tid  = threadIdx.x;
    const int w    = tid >> 5;
    const int lane = tid & 31;
    const int p    = w & 7;
    const int half = w >> 3;
    const int n0   = half * 32;

    for (int i = tid; i < 3072; i += 512) pk[i] = g_pk_init[i];
    if (tid < 128) b1s[tid] = g_bias_init[tid];
    __syncthreads();

    const ull* w1pk = pk;
    const ull* w2pk = pk + 2048;

    const int ntiles = (n + 127) >> 7;
    for (int tile = blockIdx.x; tile < ntiles; tile += gridDim.x) {
        const int nb0 = tile << 7;
        {
            int row = tid >> 2, cpart = (tid & 3) * 32, gr = nb0 + row;
            int strip = row >> 4, rr = row & 15;
            uint32_t* sf = (uint32_t*)(in_f + strip * 512);
            if (gr < n) {
                const float* src = (cpart < 64)
                    ? (blockemb + (size_t)x[gr] * 64 + cpart)
                    : (vec + (size_t)batch[gr] * 64 + (cpart - 64));
                #pragma unroll
                for (int c = 0; c < 8; c++) {
                    float4 qv = ((const float4*)src)[c];
                    int f = cpart + c * 4;
                    fstore16(sf, rr, f,     h2_(qv.x, qv.y));
                    fstore16(sf, rr, f + 2, h2_(qv.z, qv.w));
                }
            } else {
                #pragma unroll
                for (int c = 0; c < 16; c++)
                    fstore16(sf, rr, cpart + c * 2, 0u);
            }
        }
        __syncthreads();

        float racc[16];
        #pragma unroll
        for (int t = 0; t < 16; t++) racc[t] = 0.0f;
        const uint4* istrip = (const uint4*)(in_f + p * 512);
        #pragma unroll
        for (int kk = 0; kk < 8; kk++) {
            uint32_t a[4];
            load_frag16(a, istrip, kk, lane);
            #pragma unroll
            for (int nt = 0; nt < 4; nt++)
                mma16(racc + nt * 4, a, w1pk[half * 1024 + nt * 256 + kk * 32 + lane]);
        }
        {
            uint32_t* of = (uint32_t*)(o1_f + p * 256);
            int rr0 = lane >> 2;
            #pragma unroll
            for (int nt = 0; nt < 4; nt++) {
                int colb = n0 + nt * 8 + (lane & 3) * 2;
                float c0 = b1s[colb], c1 = b1s[colb + 1];
                #pragma unroll
                for (int qq = 0; qq < 2; qq++)
                    fstore16(of, rr0 + qq * 8, colb,
                             h2_(leakyf_(racc[nt * 4 + qq * 2] + c0),
                                 leakyf_(racc[nt * 4 + qq * 2 + 1] + c1)));
            }
        }
        __syncthreads();

        float acc2[16];
        #pragma unroll
        for (int t = 0; t < 16; t++) acc2[t] = 0.0f;
        const uint4* ostrip = (const uint4*)(o1_f + p * 256);
        #pragma unroll
        for (int kk = 0; kk < 4; kk++) {
            uint32_t a[4];
            load_frag16(a, ostrip, kk, lane);
            #pragma unroll
            for (int nt = 0; nt < 4; nt++)
                mma16(acc2 + nt * 4, a, w2pk[half * 512 + nt * 128 + kk * 32 + lane]);
        }
        #pragma unroll
        for (int nt = 0; nt < 4; nt++) {
            int colb = n0 + nt * 8 + (lane & 3) * 2;
            float c0 = b2s[colb], c1 = b2s[colb + 1];
            #pragma unroll
            for (int qq = 0; qq < 2; qq++) {
                int gr = nb0 + p * 16 + (lane >> 2) + qq * 8;
                if (gr < n)
                    *(float2*)(h + (size_t)gr * 64 + colb) =
                        make_float2(acc2[nt * 4 + qq * 2] + c0, acc2[nt * 4 + qq * 2 + 1] + c1);
            }
        }
        __syncthreads();
    }
}

// ---------------- edge kernel: 1 scalar atomic per edge -------------------------
__global__ void edge_kernel(const int* __restrict__ ei, const int* __restrict__ ea,
                            const float* __restrict__ bond, const float* __restrict__ h,
                            int E)
{
    int idx = blockIdx.x * blockDim.x + threadIdx.x;
    int e = idx >> 4;
    int l = idx & 15;
    bool valid = (e < E);
    int ec = valid ? e : (E - 1);
    int src = ei[ec], dst = ei[E + ec];
    int a0  = ea[2 * ec], a1 = ea[2 * ec + 1];
    float4 hv = *(const float4*)(h + (size_t)src * 64 + 4 * l);
    float4 e0 = *(const float4*)(bond + (size_t)a0 * 64 + 4 * l);
    float s = hv.x * e0.x + hv.y * e0.y + hv.z * e0.z + hv.w * e0.w;
    #pragma unroll
    for (int o = 8; o; o >>= 1) s += __shfl_xor_sync(0xffffffffu, s, o);
    if (valid && l == 0)
        atomicAdd(&g_sacc[(size_t)dst * 20 + a1], s * __ldg(&g_rdeg[dst]));
}

// ---------------- node kernel: fp16 mma, S@bond + pool*rcnt fused ---------------
__global__ void __launch_bounds__(512, 1) node_mma(
    float* __restrict__ h, const int* __restrict__ batch,
    float* __restrict__ out, int n, int last)
{
    ull* pk  = (ull*)smem_raw;
    ull* h_f = pk + 7680;
    ull* m_f = h_f + 2048;
    ull* s_f = m_f + 2048;
    float* br_s  = (float*)(s_f + 1024);
    float* bz_s  = br_s + 64;
    float* bin_s = bz_s + 64;
    float* bhn_s = bin_s + 64;
    float* cb_s  = bhn_s + 64;

    const int tid  = threadIdx.x;
    const int w    = tid >> 5;
    const int lane = tid & 31;
    const int p    = w & 7;
    const int half = w >> 3;
    const int n0   = half * 32;
    const int arow = p * 16 + (lane >> 2);

    for (int i = tid; i < 7680; i += 512) pk[i] = g_pk_node[i];
    if (tid < 320) br_s[tid] = g_bias_node[tid];
    __syncthreads();

    const int ntiles = (n + 127) >> 7;
    for (int tile = blockIdx.x; tile < ntiles; tile += gridDim.x) {
        const int nb0 = tile << 7;

        // H tile -> fp16 fragment smem
        {
            int row = tid >> 2, cbase = (tid & 3) * 16, gr = nb0 + row;
            int strip = row >> 4, rr = row & 15;
            uint32_t* sf = (uint32_t*)(h_f + strip * 256);
            if (gr < n) {
                const float4* pp = (const float4*)(h + (size_t)gr * 64 + cbase);
                #pragma unroll
                for (int c = 0; c < 4; c++) {
                    float4 qv = pp[c];
                    int f = cbase + c * 4;
                    fstore16(sf, rr, f,     h2_(qv.x, qv.y));
                    fstore16(sf, rr, f + 2, h2_(qv.z, qv.w));
                }
            } else {
                #pragma unroll
                for (int c = 0; c < 8; c++)
                    fstore16(sf, rr, cbase + c * 2, 0u);
            }
        }
        // S tile (20 -> pad 32); zero g_sacc for next step
        {
            int row = tid >> 2, gr = nb0 + row;
            int c0 = (tid & 3) * 8;
            int strip = row >> 4, rr = row & 15;
            uint32_t* sf = (uint32_t*)(s_f + strip * 128);
            float* sp = g_sacc + (size_t)gr * 20;
            #pragma unroll
            for (int c = 0; c < 4; c++) {
                int f = c0 + 2 * c;
                float va = 0.0f, vb = 0.0f;
                if (gr < n) {
                    if (f < 20)     { va = sp[f];     sp[f] = 0.0f; }
                    if (f + 1 < 20) { vb = sp[f + 1]; sp[f + 1] = 0.0f; }
                }
                fstore16(sf, rr, f, h2_(va, vb));
            }
        }
        __syncthreads();

        // early prefetch: h_old (fp32), batch ids + rcnt (last step) — hides under GEMM1
        float2 hof[8];
        float rc[2];
        int bg[2];
        #pragma unroll
        for (int qq = 0; qq < 2; qq++) {
            int gr = nb0 + arow + qq * 8;
            bg[qq] = (last && gr < n) ? batch[gr] : 0;
            rc[qq] = last ? __ldg(&g_rcnt[bg[qq]]) : 1.0f;
        }
        #pragma unroll
        for (int nt = 0; nt < 4; nt++) {
            int colb = n0 + nt * 8 + (lane & 3) * 2;
            #pragma unroll
            for (int qq = 0; qq < 2; qq++) {
                int gr = nb0 + arow + qq * 8;
                hof[nt * 2 + qq] = (gr < n) ? *(const float2*)(h + (size_t)gr * 64 + colb)
                                            : make_float2(0.0f, 0.0f);
            }
        }

        const uint4* hstrip = (const uint4*)(h_f + p * 256);
        const uint4* mstrip = (const uint4*)(m_f + p * 256);
        const uint4* sstrip = (const uint4*)(s_f + p * 128);

        // GEMM1: R = H @ root (4 kk) + S @ bond (2 kk)
        float racc[16];
        #pragma unroll
        for (int t = 0; t < 16; t++) racc[t] = 0.0f;
        #pragma unroll
        for (int kk = 0; kk < 4; kk++) {
            uint32_t a[4];
            load_frag16(a, hstrip, kk, lane);
            #pragma unroll
            for (int nt = 0; nt < 4; nt++)
                mma16(racc + nt * 4, a, pk[A_ROOT * 1024 + half * 512 + nt * 128 + kk * 32 + lane]);
        }
        #pragma unroll
        for (int kk = 0; kk < 2; kk++) {
            uint32_t a[4];
            load_frag16(a, sstrip, kk, lane);
            #pragma unroll
            for (int nt = 0; nt < 4; nt++)
                mma16(racc + nt * 4, a, pk[BOND_OFF + half * 256 + nt * 64 + kk * 32 + lane]);
        }
        // epilogue A: M = leaky(R + cb) -> fp16 fragment m_f
        {
            uint32_t* mf = (uint32_t*)(m_f + p * 256);
            int rr0 = lane >> 2;
            #pragma unroll
            for (int nt = 0; nt < 4; nt++) {
                int colb = n0 + nt * 8 + (lane & 3) * 2;
                float cb0 = cb_s[colb], cb1 = cb_s[colb + 1];
                #pragma unroll
                for (int qq = 0; qq < 2; qq++)
                    fstore16(mf, rr0 + qq * 8, colb,
                             h2_(leakyf_(racc[nt * 4 + qq * 2] + cb0),
                                 leakyf_(racc[nt * 4 + qq * 2 + 1] + cb1)));
            }
        }
        __syncthreads();

        // GEMM2: gates
        float rg[16], zg[16], ig[16], hg[16];
        #pragma unroll
        for (int t = 0; t < 16; t++) { rg[t] = zg[t] = ig[t] = hg[t] = 0.0f; }
        #pragma unroll
        for (int kk = 0; kk < 4; kk++) {
            uint32_t aM[4], aH[4];
            load_frag16(aM, mstrip, kk, lane);
            load_frag16(aH, hstrip, kk, lane);
            int pkb = half * 512 + kk * 32 + lane;
            #pragma unroll
            for (int nt = 0; nt < 4; nt++) {
                int o = pkb + nt * 128;
                mma16(rg + nt * 4, aM, pk[A_IHR * 1024 + o]);
                mma16(rg + nt * 4, aH, pk[A_HHR * 1024 + o]);
                mma16(zg + nt * 4, aM, pk[A_IHZ * 1024 + o]);
                mma16(zg + nt * 4, aH, pk[A_HHZ * 1024 + o]);
                mma16(ig + nt * 4, aM, pk[A_IHN * 1024 + o]);
                mma16(hg + nt * 4, aH, pk[A_HHN * 1024 + o]);
            }
        }

        // epilogue: GRU gate math; last step pools (h*rcnt) into out
        #pragma unroll
        for (int nt = 0; nt < 4; nt++) {
            int colb = n0 + nt * 8 + (lane & 3) * 2;
            float br0 = br_s[colb], br1 = br_s[colb + 1];
            float bz0 = bz_s[colb], bz1 = bz_s[colb + 1];
            float bi0 = bin_s[colb], bi1 = bin_s[colb + 1];
            float bh0 = bhn_s[colb], bh1 = bhn_s[colb + 1];
            #pragma unroll
            for (int qq = 0; qq < 2; qq++) {
                int gr = nb0 + arow + qq * 8;
                if (gr < n) {
                    int idx = nt * 4 + qq * 2;
                    float2 ho = hof[nt * 2 + qq];
                    float r0v = sigf_(rg[idx]     + br0);
                    float r1v = sigf_(rg[idx + 1] + br1);
                    float z0v = sigf_(zg[idx]     + bz0);
                    float z1v = sigf_(zg[idx + 1] + bz1);
                    float n0v = tanhf_(ig[idx]     + bi0 + r0v * (hg[idx]     + bh0));
                    float n1v = tanhf_(ig[idx + 1] + bi1 + r1v * (hg[idx + 1] + bh1));
                    float ox = (1.0f - z0v) * n0v + z0v * ho.x;
                    float oy = (1.0f - z1v) * n1v + z1v * ho.y;
                    if (last) {
                        float* op = out + (size_t)bg[qq] * 64 + colb;
                        asm volatile("red.global.add.v2.f32 [%0], {%1,%2};"
                                     :: "l"(op), "f"(ox * rc[qq]), "f"(oy * rc[qq]) : "memory");
                    } else {
                        *(float2*)(h + (size_t)gr * 64 + colb) = make_float2(ox, oy);
                    }
                }
            }
        }
        __syncthreads();
    }
}

// ---------------- launch ----------------------------------------------------------
extern "C" void kernel_launch(void* const* d_in, const int* in_sizes, int n_in,
                              void* d_out, int out_size)
{
    const int*   x        = (const int*)d_in[0];
    const int*   ei       = (const int*)d_in[1];
    const int*   ea       = (const int*)d_in[2];
    const int*   batch    = (const int*)d_in[3];
    const float* vec      = (const float*)d_in[4];
    const float* blockemb = (const float*)d_in[5];
    const float* bondemb  = (const float*)d_in[6];
    const float* w1       = (const float*)d_in[7];
    const float* b1       = (const float*)d_in[8];
    const float* w2       = (const float*)d_in[9];
    const float* b2       = (const float*)d_in[10];
    const float* root     = (const float*)d_in[11];
    const float* cb       = (const float*)d_in[12];
    const float* wih      = (const float*)d_in[13];
    const float* whh      = (const float*)d_in[14];
    const float* bih      = (const float*)d_in[15];
    const float* bhh      = (const float*)d_in[16];

    const int n = in_sizes[0];
    const int E = in_sizes[1] / 2;
    const int G = in_sizes[4] / 64;

    float* h_p;
    cudaGetSymbolAddress((void**)&h_p, g_h);

    cudaFuncSetAttribute(init_mma, cudaFuncAttributeMaxDynamicSharedMemorySize, INIT_SMEM);
    cudaFuncSetAttribute(node_mma, cudaFuncAttributeMaxDynamicSharedMemorySize, NODE_SMEM);

    cudaMemsetAsync(d_out, 0, (size_t)out_size * sizeof(float));

    prep_kernel<<<296, 512>>>(root, cb, wih, whh, bih, bhh, w1, b1, w2, b2,
                              bondemb, ei, batch, E, n);
    recip_kernel<<<(n + 255) / 256, 256>>>(n, G);

    init_mma<<<148, 512, INIT_SMEM>>>(x, batch, vec, blockemb, h_p, n);

    for (int s = 0; s < 4; s++) {
        edge_kernel<<<(E * 16 + 255) / 256, 256>>>(ei, ea, bondemb, h_p, E);
        node_mma<<<148, 512, NODE_SMEM>>>(h_p, batch, (float*)d_out, n, s == 3 ? 1 : 0);
    }
}

// round 14
// speedup vs baseline: 1.5947x; 1.0596x over previous
#include <cuda_runtime.h>
#include <cuda_fp16.h>
#include <math.h>
#include <stdint.h>

#define MAXN 50000
#define MAXE 100000
#define MAXG 4096

typedef unsigned long long ull;

extern __shared__ __align__(1024) char smem_raw[];

// ---------------- device scratch -------------------------------------------
__device__ float g_h[MAXN * 64];
__device__ float g_P[MAXN * 20];      // P[v,t] = h[v] . bond[t]
__device__ float g_sacc[MAXN * 20];   // zero invariant (node_mma re-zeroes)
__device__ float g_deg[MAXN];         // zero invariant (recip re-zeroes)
__device__ float g_cntb[MAXG];        // zero invariant (recip re-zeroes)
__device__ float g_rdeg[MAXN];
__device__ float g_rcnt[MAXG];
__device__ ull   g_pk_node[8064];     // gates 7168 | bond-S 512 | bond-P 384
__device__ ull   g_pk_init[3072];
__device__ float g_bias_node[320];
__device__ float g_bias_init[128];

__device__ __forceinline__ float sigf_(float x)   { return 1.0f / (1.0f + __expf(-x)); }
__device__ __forceinline__ float tanhf_(float x)  { return 2.0f * sigf_(2.0f * x) - 1.0f; }
__device__ __forceinline__ float leakyf_(float x) { return x > 0.0f ? x : 0.01f * x; }

__device__ __forceinline__ uint32_t h2_(float a, float b) {
    __half2 h = __floats2half2_rn(a, b);
    return *(uint32_t*)&h;
}

// m16n8k16 fp16 MMA, fp32 accum (portable PTX)
__device__ __forceinline__ void mma16(float* c, const uint32_t* a, ull b) {
    uint32_t b0 = (uint32_t)b, b1 = (uint32_t)(b >> 32);
    asm volatile(
        "mma.sync.aligned.m16n8k16.row.col.f32.f16.f16.f32 "
        "{%0,%1,%2,%3}, {%4,%5,%6,%7}, {%8,%9}, {%0,%1,%2,%3};"
        : "+f"(c[0]), "+f"(c[1]), "+f"(c[2]), "+f"(c[3])
        : "r"(a[0]), "r"(a[1]), "r"(a[2]), "r"(a[3]), "r"(b0), "r"(b1));
}

__device__ __forceinline__ void load_frag16(uint32_t* a, const uint4* sf4, int kk, int lane) {
    uint4 v = sf4[kk * 32 + lane];
    a[0] = v.x; a[1] = v.y; a[2] = v.z; a[3] = v.w;
}
__device__ __forceinline__ void fstore16(uint32_t* sf32, int rr, int f, uint32_t val) {
    int kk = f >> 4, kf = f & 15;
    int g = rr & 7, jr = (rr >> 3) & 1;
    int t = (kf >> 1) & 3;
    int j = jr + ((kf >= 8) ? 2 : 0);
    sf32[(kk * 32 + g * 4 + t) * 4 + j] = val;
}

#define A_ROOT 0
#define A_IHR  1
#define A_HHR  2
#define A_IHZ  3
#define A_HHZ  4
#define A_IHN  5
#define A_HHN  6
#define BOND_OFF 7168
#define PB_OFF   7680
#define NODE_SMEM   ((8064 + 2048 + 2048 + 1024) * 8 + 320 * 4)
#define INIT_SMEM   ((3456 + 4096 + 2048) * 8 + 128 * 4)

// ---------------- fused prologue: pack weights + deg + cnt ----------------------
__global__ void prep_kernel(
    const float* __restrict__ root, const float* __restrict__ cb,
    const float* __restrict__ wih, const float* __restrict__ whh,
    const float* __restrict__ bih, const float* __restrict__ bhh,
    const float* __restrict__ w1, const float* __restrict__ b1,
    const float* __restrict__ w2, const float* __restrict__ b2,
    const float* __restrict__ bondemb,
    const int* __restrict__ ei, const int* __restrict__ batch,
    int E, int n)
{
    int total = 11584 + E + n;
    for (int i = blockIdx.x * blockDim.x + threadIdx.x; i < total; i += gridDim.x * blockDim.x) {
        if (i < 7168) {
            int arr = i >> 10, rem = i & 1023;
            int hf = rem >> 9, nt = (rem >> 7) & 3, kk = (rem >> 5) & 3, ln = rem & 31;
            int nn = hf * 32 + nt * 8 + (ln >> 2);
            int k0 = kk * 16 + 2 * (ln & 3);
            float v0, v1, v2, v3;
            switch (arr) {
                case A_ROOT:
                    v0 = root[k0 * 64 + nn]; v1 = root[(k0 + 1) * 64 + nn];
                    v2 = root[(k0 + 8) * 64 + nn]; v3 = root[(k0 + 9) * 64 + nn]; break;
                case A_IHR: { const float* W = wih + (size_t)nn * 64;
                    v0 = W[k0]; v1 = W[k0 + 1]; v2 = W[k0 + 8]; v3 = W[k0 + 9]; } break;
                case A_HHR: { const float* W = whh + (size_t)nn * 64;
                    v0 = W[k0]; v1 = W[k0 + 1]; v2 = W[k0 + 8]; v3 = W[k0 + 9]; } break;
                case A_IHZ: { const float* W = wih + (size_t)(64 + nn) * 64;
                    v0 = W[k0]; v1 = W[k0 + 1]; v2 = W[k0 + 8]; v3 = W[k0 + 9]; } break;
                case A_HHZ: { const float* W = whh + (size_t)(64 + nn) * 64;
                    v0 = W[k0]; v1 = W[k0 + 1]; v2 = W[k0 + 8]; v3 = W[k0 + 9]; } break;
                case A_IHN: { const float* W = wih + (size_t)(128 + nn) * 64;
                    v0 = W[k0]; v1 = W[k0 + 1]; v2 = W[k0 + 8]; v3 = W[k0 + 9]; } break;
                default:    { const float* W = whh + (size_t)(128 + nn) * 64;
                    v0 = W[k0]; v1 = W[k0 + 1]; v2 = W[k0 + 8]; v3 = W[k0 + 9]; } break;
            }
            g_pk_node[i] = (ull)h2_(v0, v1) | ((ull)h2_(v2, v3) << 32);
        } else if (i < 7680) {
            // bond-S: B[n=64][k=20 pad 32] = bondemb[k*64+n]
            int j = i - 7168;
            int hf = (j >> 8) & 1, nt = (j >> 6) & 3, kk = (j >> 5) & 1, ln = j & 31;
            int nn = hf * 32 + nt * 8 + (ln >> 2);
            int k0 = kk * 16 + 2 * (ln & 3);
            float v[4];
            #pragma unroll
            for (int d = 0; d < 4; d++) {
                int k = k0 + (d >> 1) * 8 + (d & 1);
                v[d] = (k < 20) ? bondemb[k * 64 + nn] : 0.0f;
            }
            g_pk_node[BOND_OFF + j] = (ull)h2_(v[0], v[1]) | ((ull)h2_(v[2], v[3]) << 32);
        } else if (i < 10752) {
            int j = i - 7680;
            if (j < 2048) {
                int hf = j >> 10, nt = (j >> 8) & 3, kk = (j >> 5) & 7, ln = j & 31;
                int nn = hf * 32 + nt * 8 + (ln >> 2);
                int k0 = kk * 16 + 2 * (ln & 3);
                const float* W = w1 + (size_t)nn * 128;
                g_pk_init[j] = (ull)h2_(W[k0], W[k0 + 1]) | ((ull)h2_(W[k0 + 8], W[k0 + 9]) << 32);
            } else {
                int jj = j - 2048;
                int hf = jj >> 9, nt = (jj >> 7) & 3, kk = (jj >> 5) & 3, ln = jj & 31;
                int nn = hf * 32 + nt * 8 + (ln >> 2);
                int k0 = kk * 16 + 2 * (ln & 3);
                const float* W = w2 + (size_t)nn * 64;
                g_pk_init[j] = (ull)h2_(W[k0], W[k0 + 1]) | ((ull)h2_(W[k0 + 8], W[k0 + 9]) << 32);
            }
        } else if (i < 11072) {
            int j = i - 10752;
            float v;
            if (j < 128)      v = bih[j] + bhh[j];
            else if (j < 192) v = bih[128 + (j - 128)];
            else if (j < 256) v = bhh[128 + (j - 192)];
            else              v = cb[j - 256];
            g_bias_node[j] = v;
        } else if (i < 11200) {
            int j = i - 11072;
            g_bias_init[j] = (j < 64) ? b1[j] : b2[j - 64];
        } else if (i < 11584) {
            // bond-P: B[n=20 pad 24][k=64] = bondemb[n*64+k]; [ntg(3)][kk(4)][lane]
            int j = i - 11200;
            int ntg = j >> 7, kk = (j >> 5) & 3, ln = j & 31;
            int nn = ntg * 8 + (ln >> 2);
            int k0 = kk * 16 + 2 * (ln & 3);
            float v[4];
            #pragma unroll
            for (int d = 0; d < 4; d++) {
                int k = k0 + (d >> 1) * 8 + (d & 1);
                v[d] = (nn < 20) ? bondemb[nn * 64 + k] : 0.0f;
            }
            g_pk_node[PB_OFF + j] = (ull)h2_(v[0], v[1]) | ((ull)h2_(v[2], v[3]) << 32);
        } else if (i < 11584 + E) {
            atomicAdd(&g_deg[ei[E + (i - 11584)]], 1.0f);
        } else {
            atomicAdd(&g_cntb[batch[i - 11584 - E]], 1.0f);
        }
    }
}

__global__ void recip_kernel(int n, int G) {
    int i = blockIdx.x * blockDim.x + threadIdx.x;
    if (i < n) {
        g_rdeg[i] = 1.0f / fmaxf(g_deg[i], 1.0f);
        g_deg[i] = 0.0f;
    }
    if (i < G) {
        g_rcnt[i] = 1.0f / fmaxf(g_cntb[i], 1.0f);
        g_cntb[i] = 0.0f;
    }
}

// ---- shared P-pass helper: compute P strip from fragment tile, store to g_P ----
__device__ __forceinline__ void p_pass(const uint4* strip, const ull* pkP,
                                       int half, int lane, int nb0, int p, int n)
{
    float pacc[8];
    #pragma unroll
    for (int t = 0; t < 8; t++) pacc[t] = 0.0f;
    const int nnt = (half == 0) ? 2 : 1;
    #pragma unroll
    for (int kk = 0; kk < 4; kk++) {
        uint32_t a[4];
        load_frag16(a, strip, kk, lane);
        for (int t = 0; t < nnt; t++) {
            int ntg = half * 2 + t;
            mma16(pacc + t * 4, a, pkP[ntg * 128 + kk * 32 + lane]);
        }
    }
    int arow = p * 16 + (lane >> 2);
    for (int t = 0; t < nnt; t++) {
        int ntg = half * 2 + t;
        int colp = ntg * 8 + (lane & 3) * 2;
        if (colp < 20) {
            #pragma unroll
            for (int qq = 0; qq < 2; qq++) {
                int gr = nb0 + arow + qq * 8;
                if (gr < n)
                    *(float2*)(g_P + (size_t)gr * 20 + colp) =
                        make_float2(pacc[t * 4 + qq * 2], pacc[t * 4 + qq * 2 + 1]);
            }
        }
    }
}

// ---------------- init MLP + P ---------------------------------------------------
__global__ void __launch_bounds__(512, 1) init_mma(
    const int* __restrict__ x, const int* __restrict__ batch,
    const float* __restrict__ vec, const float* __restrict__ blockemb,
    float* __restrict__ h, int n)
{
    ull* pk   = (ull*)smem_raw;        // [3456]: w1 2048 | w2 1024 | bond-P 384
    ull* in_f = pk + 3456;             // [8][512]
    ull* o1_f = in_f + 4096;           // [8][256]
    float* b1s = (float*)(o1_f + 2048);
    float* b2s = b1s + 64;

    const int tid  = threadIdx.x;
    const int w    = tid >> 5;
    const int lane = tid & 31;
    const int p    = w & 7;
    const int half = w >> 3;
    const int n0   = half * 32;

    for (int i = tid; i < 3072; i += 512) pk[i] = g_pk_init[i];
    for (int i = tid; i < 384; i += 512)  pk[3072 + i] = g_pk_node[PB_OFF + i];
    if (tid < 128) b1s[tid] = g_bias_init[tid];
    __syncthreads();

    const ull* w1pk = pk;
    const ull* w2pk = pk + 2048;
    const ull* pkP  = pk + 3072;

    const int ntiles = (n + 127) >> 7;
    for (int tile = blockIdx.x; tile < ntiles; tile += gridDim.x) {
        const int nb0 = tile << 7;
        {
            int row = tid >> 2, cpart = (tid & 3) * 32, gr = nb0 + row;
            int strip = row >> 4, rr = row & 15;
            uint32_t* sf = (uint32_t*)(in_f + strip * 512);
            if (gr < n) {
                const float* src = (cpart < 64)
                    ? (blockemb + (size_t)x[gr] * 64 + cpart)
                    : (vec + (size_t)batch[gr] * 64 + (cpart - 64));
                #pragma unroll
                for (int c = 0; c < 8; c++) {
                    float4 qv = ((const float4*)src)[c];
                    int f = cpart + c * 4;
                    fstore16(sf, rr, f,     h2_(qv.x, qv.y));
                    fstore16(sf, rr, f + 2, h2_(qv.z, qv.w));
                }
            } else {
                #pragma unroll
                for (int c = 0; c < 16; c++)
                    fstore16(sf, rr, cpart + c * 2, 0u);
            }
        }
        __syncthreads();

        float racc[16];
        #pragma unroll
        for (int t = 0; t < 16; t++) racc[t] = 0.0f;
        const uint4* istrip = (const uint4*)(in_f + p * 512);
        #pragma unroll
        for (int kk = 0; kk < 8; kk++) {
            uint32_t a[4];
            load_frag16(a, istrip, kk, lane);
            #pragma unroll
            for (int nt = 0; nt < 4; nt++)
                mma16(racc + nt * 4, a, w1pk[half * 1024 + nt * 256 + kk * 32 + lane]);
        }
        {
            uint32_t* of = (uint32_t*)(o1_f + p * 256);
            int rr0 = lane >> 2;
            #pragma unroll
            for (int nt = 0; nt < 4; nt++) {
                int colb = n0 + nt * 8 + (lane & 3) * 2;
                float c0 = b1s[colb], c1 = b1s[colb + 1];
                #pragma unroll
                for (int qq = 0; qq < 2; qq++)
                    fstore16(of, rr0 + qq * 8, colb,
                             h2_(leakyf_(racc[nt * 4 + qq * 2] + c0),
                                 leakyf_(racc[nt * 4 + qq * 2 + 1] + c1)));
            }
        }
        __syncthreads();

        float acc2[16];
        #pragma unroll
        for (int t = 0; t < 16; t++) acc2[t] = 0.0f;
        const uint4* ostrip = (const uint4*)(o1_f + p * 256);
        #pragma unroll
        for (int kk = 0; kk < 4; kk++) {
            uint32_t a[4];
            load_frag16(a, ostrip, kk, lane);
            #pragma unroll
            for (int nt = 0; nt < 4; nt++)
                mma16(acc2 + nt * 4, a, w2pk[half * 512 + nt * 128 + kk * 32 + lane]);
        }
        // h0 = acc2 + bias -> gmem; also stash for P pass
        #pragma unroll
        for (int nt = 0; nt < 4; nt++) {
            int colb = n0 + nt * 8 + (lane & 3) * 2;
            float c0 = b2s[colb], c1 = b2s[colb + 1];
            acc2[nt * 4 + 0] += c0; acc2[nt * 4 + 1] += c1;
            acc2[nt * 4 + 2] += c0; acc2[nt * 4 + 3] += c1;
            #pragma unroll
            for (int qq = 0; qq < 2; qq++) {
                int gr = nb0 + p * 16 + (lane >> 2) + qq * 8;
                if (gr < n)
                    *(float2*)(h + (size_t)gr * 64 + colb) =
                        make_float2(acc2[nt * 4 + qq * 2], acc2[nt * 4 + qq * 2 + 1]);
            }
        }
        __syncthreads();   // o1_f reads done block-wide; safe to overwrite
        {
            uint32_t* of = (uint32_t*)(o1_f + p * 256);
            int rr0 = lane >> 2;
            #pragma unroll
            for (int nt = 0; nt < 4; nt++) {
                int colb = n0 + nt * 8 + (lane & 3) * 2;
                #pragma unroll
                for (int qq = 0; qq < 2; qq++)
                    fstore16(of, rr0 + qq * 8, colb,
                             h2_(acc2[nt * 4 + qq * 2], acc2[nt * 4 + qq * 2 + 1]));
            }
        }
        __syncthreads();
        p_pass(ostrip, pkP, half, lane, nb0, p, n);
        __syncthreads();
    }
}

// ---------------- edge kernel: 1 thread/edge, scalar P lookup -------------------
__global__ void edge_kernel(const int* __restrict__ ei, const int* __restrict__ ea, int E)
{
    int e = blockIdx.x * blockDim.x + threadIdx.x;
    if (e >= E) return;
    int src = ei[e], dst = ei[E + e];
    int2 a = ((const int2*)ea)[e];
    float s = __ldg(&g_P[(size_t)src * 20 + a.x]) * __ldg(&g_rdeg[dst]);
    atomicAdd(&g_sacc[(size_t)dst * 20 + a.y], s);
}

// ---------------- node kernel ----------------------------------------------------
__global__ void __launch_bounds__(512, 1) node_mma(
    float* __restrict__ h, const int* __restrict__ batch,
    float* __restrict__ out, int n, int last)
{
    ull* pk  = (ull*)smem_raw;          // [8064]
    ull* h_f = pk + 8064;
    ull* m_f = h_f + 2048;
    ull* s_f = m_f + 2048;
    float* br_s  = (float*)(s_f + 1024);
    float* bz_s  = br_s + 64;
    float* bin_s = bz_s + 64;
    float* bhn_s = bin_s + 64;
    float* cb_s  = bhn_s + 64;

    const int tid  = threadIdx.x;
    const int w    = tid >> 5;
    const int lane = tid & 31;
    const int p    = w & 7;
    const int half = w >> 3;
    const int n0   = half * 32;
    const int arow = p * 16 + (lane >> 2);

    for (int i = tid; i < 8064; i += 512) pk[i] = g_pk_node[i];
    if (tid < 320) br_s[tid] = g_bias_node[tid];
    __syncthreads();

    const int ntiles = (n + 127) >> 7;
    for (int tile = blockIdx.x; tile < ntiles; tile += gridDim.x) {
        const int nb0 = tile << 7;

        {
            int row = tid >> 2, cbase = (tid & 3) * 16, gr = nb0 + row;
            int strip = row >> 4, rr = row & 15;
            uint32_t* sf = (uint32_t*)(h_f + strip * 256);
            if (gr < n) {
                const float4* pp = (const float4*)(h + (size_t)gr * 64 + cbase);
                #pragma unroll
                for (int c = 0; c < 4; c++) {
                    float4 qv = pp[c];
                    int f = cbase + c * 4;
                    fstore16(sf, rr, f,     h2_(qv.x, qv.y));
                    fstore16(sf, rr, f + 2, h2_(qv.z, qv.w));
                }
            } else {
                #pragma unroll
                for (int c = 0; c < 8; c++)
                    fstore16(sf, rr, cbase + c * 2, 0u);
            }
        }
        {
            int row = tid >> 2, gr = nb0 + row;
            int c0 = (tid & 3) * 8;
            int strip = row >> 4, rr = row & 15;
            uint32_t* sf = (uint32_t*)(s_f + strip * 128);
            float* sp = g_sacc + (size_t)gr * 20;
            #pragma unroll
            for (int c = 0; c < 4; c++) {
                int f = c0 + 2 * c;
                float va = 0.0f, vb = 0.0f;
                if (gr < n) {
                    if (f < 20)     { va = sp[f];     sp[f] = 0.0f; }
                    if (f + 1 < 20) { vb = sp[f + 1]; sp[f + 1] = 0.0f; }
                }
                fstore16(sf, rr, f, h2_(va, vb));
            }
        }
        __syncthreads();

        // early prefetch
        float2 hof[8];
        float rc[2];
        int bg[2];
        #pragma unroll
        for (int qq = 0; qq < 2; qq++) {
            int gr = nb0 + arow + qq * 8;
            bg[qq] = (last && gr < n) ? batch[gr] : 0;
            rc[qq] = last ? __ldg(&g_rcnt[bg[qq]]) : 1.0f;
        }
        #pragma unroll
        for (int nt = 0; nt < 4; nt++) {
            int colb = n0 + nt * 8 + (lane & 3) * 2;
            #pragma unroll
            for (int qq = 0; qq < 2; qq++) {
                int gr = nb0 + arow + qq * 8;
                hof[nt * 2 + qq] = (gr < n) ? *(const float2*)(h + (size_t)gr * 64 + colb)
                                            : make_float2(0.0f, 0.0f);
            }
        }

        const uint4* hstrip = (const uint4*)(h_f + p * 256);
        const uint4* mstrip = (const uint4*)(m_f + p * 256);
        const uint4* sstrip = (const uint4*)(s_f + p * 128);

        // GEMM1: R = H @ root + S @ bond
        float racc[16];
        #pragma unroll
        for (int t = 0; t < 16; t++) racc[t] = 0.0f;
        #pragma unroll
        for (int kk = 0; kk < 4; kk++) {
            uint32_t a[4];
            load_frag16(a, hstrip, kk, lane);
            #pragma unroll
            for (int nt = 0; nt < 4; nt++)
                mma16(racc + nt * 4, a, pk[A_ROOT * 1024 + half * 512 + nt * 128 + kk * 32 + lane]);
        }
        #pragma unroll
        for (int kk = 0; kk < 2; kk++) {
            uint32_t a[4];
            load_frag16(a, sstrip, kk, lane);
            #pragma unroll
            for (int nt = 0; nt < 4; nt++)
                mma16(racc + nt * 4, a, pk[BOND_OFF + half * 256 + nt * 64 + kk * 32 + lane]);
        }
        {
            uint32_t* mf = (uint32_t*)(m_f + p * 256);
            int rr0 = lane >> 2;
            #pragma unroll
            for (int nt = 0; nt < 4; nt++) {
                int colb = n0 + nt * 8 + (lane & 3) * 2;
                float cb0 = cb_s[colb], cb1 = cb_s[colb + 1];
                #pragma unroll
                for (int qq = 0; qq < 2; qq++)
                    fstore16(mf, rr0 + qq * 8, colb,
                             h2_(leakyf_(racc[nt * 4 + qq * 2] + cb0),
                                 leakyf_(racc[nt * 4 + qq * 2 + 1] + cb1)));
            }
        }
        __syncthreads();

        // GEMM2: gates
        float rg[16], zg[16], ig[16], hg[16];
        #pragma unroll
        for (int t = 0; t < 16; t++) { rg[t] = zg[t] = ig[t] = hg[t] = 0.0f; }
        #pragma unroll
        for (int kk = 0; kk < 4; kk++) {
            uint32_t aM[4], aH[4];
            load_frag16(aM, mstrip, kk, lane);
            load_frag16(aH, hstrip, kk, lane);
            int pkb = half * 512 + kk * 32 + lane;
            #pragma unroll
            for (int nt = 0; nt < 4; nt++) {
                int o = pkb + nt * 128;
                mma16(rg + nt * 4, aM, pk[A_IHR * 1024 + o]);
                mma16(rg + nt * 4, aH, pk[A_HHR * 1024 + o]);
                mma16(zg + nt * 4, aM, pk[A_IHZ * 1024 + o]);
                mma16(zg + nt * 4, aH, pk[A_HHZ * 1024 + o]);
                mma16(ig + nt * 4, aM, pk[A_IHN * 1024 + o]);
                mma16(hg + nt * 4, aH, pk[A_HHN * 1024 + o]);
            }
        }

        // epilogue: GRU gate math; write h (or pool); keep h_new for P pass
        float o2[16];
        #pragma unroll
        for (int nt = 0; nt < 4; nt++) {
            int colb = n0 + nt * 8 + (lane & 3) * 2;
            float br0 = br_s[colb], br1 = br_s[colb + 1];
            float bz0 = bz_s[colb], bz1 = bz_s[colb + 1];
            float bi0 = bin_s[colb], bi1 = bin_s[colb + 1];
            float bh0 = bhn_s[colb], bh1 = bhn_s[colb + 1];
            #pragma unroll
            for (int qq = 0; qq < 2; qq++) {
                int gr = nb0 + arow + qq * 8;
                int idx = nt * 4 + qq * 2;
                float2 ho = hof[nt * 2 + qq];
                float r0v = sigf_(rg[idx]     + br0);
                float r1v = sigf_(rg[idx + 1] + br1);
                float z0v = sigf_(zg[idx]     + bz0);
                float z1v = sigf_(zg[idx + 1] + bz1);
                float n0v = tanhf_(ig[idx]     + bi0 + r0v * (hg[idx]     + bh0));
                float n1v = tanhf_(ig[idx + 1] + bi1 + r1v * (hg[idx + 1] + bh1));
                float ox = (1.0f - z0v) * n0v + z0v * ho.x;
                float oy = (1.0f - z1v) * n1v + z1v * ho.y;
                o2[idx] = ox; o2[idx + 1] = oy;
                if (gr < n) {
                    if (last) {
                        float* op = out + (size_t)bg[qq] * 64 + colb;
                        asm volatile("red.global.add.v2.f32 [%0], {%1,%2};"
                                     :: "l"(op), "f"(ox * rc[qq]), "f"(oy * rc[qq]) : "memory");
                    } else {
                        *(float2*)(h + (size_t)gr * 64 + colb) = make_float2(ox, oy);
                    }
                }
            }
        }

        if (!last) {
            __syncthreads();   // all GEMM2 reads of h_f done
            {
                uint32_t* sf = (uint32_t*)(h_f + p * 256);
                int rr0 = lane >> 2;
                #pragma unroll
                for (int nt = 0; nt < 4; nt++) {
                    int colb = n0 + nt * 8 + (lane & 3) * 2;
                    #pragma unroll
                    for (int qq = 0; qq < 2; qq++)
                        fstore16(sf, rr0 + qq * 8, colb,
                                 h2_(o2[nt * 4 + qq * 2], o2[nt * 4 + qq * 2 + 1]));
                }
            }
            __syncthreads();
            p_pass(hstrip, pk + PB_OFF, half, lane, nb0, p, n);
        }
        __syncthreads();
    }
}

// ---------------- launch ----------------------------------------------------------
extern "C" void kernel_launch(void* const* d_in, const int* in_sizes, int n_in,
                              void* d_out, int out_size)
{
    const int*   x        = (const int*)d_in[0];
    const int*   ei       = (const int*)d_in[1];
    const int*   ea       = (const int*)d_in[2];
    const int*   batch    = (const int*)d_in[3];
    const float* vec      = (const float*)d_in[4];
    const float* blockemb = (const float*)d_in[5];
    const float* bondemb  = (const float*)d_in[6];
    const float* w1       = (const float*)d_in[7];
    const float* b1       = (const float*)d_in[8];
    const float* w2       = (const float*)d_in[9];
    const float* b2       = (const float*)d_in[10];
    const float* root     = (const float*)d_in[11];
    const float* cb       = (const float*)d_in[12];
    const float* wih      = (const float*)d_in[13];
    const float* whh      = (const float*)d_in[14];
    const float* bih      = (const float*)d_in[15];
    const float* bhh      = (const float*)d_in[16];

    const int n = in_sizes[0];
    const int E = in_sizes[1] / 2;
    const int G = in_sizes[4] / 64;

    float* h_p;
    cudaGetSymbolAddress((void**)&h_p, g_h);

    cudaFuncSetAttribute(init_mma, cudaFuncAttributeMaxDynamicSharedMemorySize, INIT_SMEM);
    cudaFuncSetAttribute(node_mma, cudaFuncAttributeMaxDynamicSharedMemorySize, NODE_SMEM);

    cudaMemsetAsync(d_out, 0, (size_t)out_size * sizeof(float));

    prep_kernel<<<296, 512>>>(root, cb, wih, whh, bih, bhh, w1, b1, w2, b2,
                              bondemb, ei, batch, E, n);
    recip_kernel<<<(n + 255) / 256, 256>>>(n, G);

    init_mma<<<148, 512, INIT_SMEM>>>(x, batch, vec, blockemb, h_p, n);

    for (int s = 0; s < 4; s++) {
        edge_kernel<<<(E + 255) / 256, 256>>>(ei, ea, E);
        node_mma<<<148, 512, NODE_SMEM>>>(h_p, batch, (float*)d_out, n, s == 3 ? 1 : 0);
    }
}

// round 15
// speedup vs baseline: 1.6499x; 1.0346x over previous
#include <cuda_runtime.h>
#include <cuda_fp16.h>
#include <math.h>
#include <stdint.h>

#define MAXN 50000
#define MAXE 100000
#define MAXG 4096

typedef unsigned long long ull;

extern __shared__ __align__(1024) char smem_raw[];

// ---------------- device scratch -------------------------------------------
__device__ uint32_t g_h16[MAXN * 32]; // h as packed half2 pairs, row-major
__device__ float g_P[MAXN * 20];      // P[v,t] = h[v] . bond[t]
__device__ float g_sacc[MAXN * 20];   // zero invariant (node_mma re-zeroes)
__device__ float g_deg[MAXN];         // zero invariant (recip re-zeroes)
__device__ float g_cntb[MAXG];        // zero invariant (recip re-zeroes)
__device__ float g_rdeg[MAXN];
__device__ float g_rcnt[MAXG];
__device__ ull   g_pk_node[8064];     // gates 7168 | bond-S 512 | bond-P 384
__device__ ull   g_pk_init[3072];
__device__ float g_bias_node[320];
__device__ float g_bias_init[128];

__device__ __forceinline__ float sigf_(float x)   { return 1.0f / (1.0f + __expf(-x)); }
__device__ __forceinline__ float tanhf_(float x)  { return 2.0f * sigf_(2.0f * x) - 1.0f; }
__device__ __forceinline__ float leakyf_(float x) { return x > 0.0f ? x : 0.01f * x; }

__device__ __forceinline__ uint32_t h2_(float a, float b) {
    __half2 h = __floats2half2_rn(a, b);
    return *(uint32_t*)&h;
}
__device__ __forceinline__ float2 h2f_(uint32_t u) {
    __half2 h = *(__half2*)&u;
    return __half22float2(h);
}

// m16n8k16 fp16 MMA, fp32 accum (portable PTX)
__device__ __forceinline__ void mma16(float* c, const uint32_t* a, ull b) {
    uint32_t b0 = (uint32_t)b, b1 = (uint32_t)(b >> 32);
    asm volatile(
        "mma.sync.aligned.m16n8k16.row.col.f32.f16.f16.f32 "
        "{%0,%1,%2,%3}, {%4,%5,%6,%7}, {%8,%9}, {%0,%1,%2,%3};"
        : "+f"(c[0]), "+f"(c[1]), "+f"(c[2]), "+f"(c[3])
        : "r"(a[0]), "r"(a[1]), "r"(a[2]), "r"(a[3]), "r"(b0), "r"(b1));
}

__device__ __forceinline__ void load_frag16(uint32_t* a, const uint4* sf4, int kk, int lane) {
    uint4 v = sf4[kk * 32 + lane];
    a[0] = v.x; a[1] = v.y; a[2] = v.z; a[3] = v.w;
}
__device__ __forceinline__ void fstore16(uint32_t* sf32, int rr, int f, uint32_t val) {
    int kk = f >> 4, kf = f & 15;
    int g = rr & 7, jr = (rr >> 3) & 1;
    int t = (kf >> 1) & 3;
    int j = jr + ((kf >= 8) ? 2 : 0);
    sf32[(kk * 32 + g * 4 + t) * 4 + j] = val;
}

#define A_ROOT 0
#define A_IHR  1
#define A_HHR  2
#define A_IHZ  3
#define A_HHZ  4
#define A_IHN  5
#define A_HHN  6
#define BOND_OFF 7168
#define PB_OFF   7680
#define NODE_SMEM   ((8064 + 2048 + 2048 + 1024) * 8 + 320 * 4)
#define INIT_SMEM   ((3456 + 4096 + 2048) * 8 + 128 * 4)

// ---------------- fused prologue: pack weights + deg + cnt ----------------------
__global__ void prep_kernel(
    const float* __restrict__ root, const float* __restrict__ cb,
    const float* __restrict__ wih, const float* __restrict__ whh,
    const float* __restrict__ bih, const float* __restrict__ bhh,
    const float* __restrict__ w1, const float* __restrict__ b1,
    const float* __restrict__ w2, const float* __restrict__ b2,
    const float* __restrict__ bondemb,
    const int* __restrict__ ei, const int* __restrict__ batch,
    int E, int n)
{
    int total = 11584 + E + n;
    for (int i = blockIdx.x * blockDim.x + threadIdx.x; i < total; i += gridDim.x * blockDim.x) {
        if (i < 7168) {
            int arr = i >> 10, rem = i & 1023;
            int hf = rem >> 9, nt = (rem >> 7) & 3, kk = (rem >> 5) & 3, ln = rem & 31;
            int nn = hf * 32 + nt * 8 + (ln >> 2);
            int k0 = kk * 16 + 2 * (ln & 3);
            float v0, v1, v2, v3;
            switch (arr) {
                case A_ROOT:
                    v0 = root[k0 * 64 + nn]; v1 = root[(k0 + 1) * 64 + nn];
                    v2 = root[(k0 + 8) * 64 + nn]; v3 = root[(k0 + 9) * 64 + nn]; break;
                case A_IHR: { const float* W = wih + (size_t)nn * 64;
                    v0 = W[k0]; v1 = W[k0 + 1]; v2 = W[k0 + 8]; v3 = W[k0 + 9]; } break;
                case A_HHR: { const float* W = whh + (size_t)nn * 64;
                    v0 = W[k0]; v1 = W[k0 + 1]; v2 = W[k0 + 8]; v3 = W[k0 + 9]; } break;
                case A_IHZ: { const float* W = wih + (size_t)(64 + nn) * 64;
                    v0 = W[k0]; v1 = W[k0 + 1]; v2 = W[k0 + 8]; v3 = W[k0 + 9]; } break;
                case A_HHZ: { const float* W = whh + (size_t)(64 + nn) * 64;
                    v0 = W[k0]; v1 = W[k0 + 1]; v2 = W[k0 + 8]; v3 = W[k0 + 9]; } break;
                case A_IHN: { const float* W = wih + (size_t)(128 + nn) * 64;
                    v0 = W[k0]; v1 = W[k0 + 1]; v2 = W[k0 + 8]; v3 = W[k0 + 9]; } break;
                default:    { const float* W = whh + (size_t)(128 + nn) * 64;
                    v0 = W[k0]; v1 = W[k0 + 1]; v2 = W[k0 + 8]; v3 = W[k0 + 9]; } break;
            }
            g_pk_node[i] = (ull)h2_(v0, v1) | ((ull)h2_(v2, v3) << 32);
        } else if (i < 7680) {
            int j = i - 7168;
            int hf = (j >> 8) & 1, nt = (j >> 6) & 3, kk = (j >> 5) & 1, ln = j & 31;
            int nn = hf * 32 + nt * 8 + (ln >> 2);
            int k0 = kk * 16 + 2 * (ln & 3);
            float v[4];
            #pragma unroll
            for (int d = 0; d < 4; d++) {
                int k = k0 + (d >> 1) * 8 + (d & 1);
                v[d] = (k < 20) ? bondemb[k * 64 + nn] : 0.0f;
            }
            g_pk_node[BOND_OFF + j] = (ull)h2_(v[0], v[1]) | ((ull)h2_(v[2], v[3]) << 32);
        } else if (i < 10752) {
            int j = i - 7680;
            if (j < 2048) {
                int hf = j >> 10, nt = (j >> 8) & 3, kk = (j >> 5) & 7, ln = j & 31;
                int nn = hf * 32 + nt * 8 + (ln >> 2);
                int k0 = kk * 16 + 2 * (ln & 3);
                const float* W = w1 + (size_t)nn * 128;
                g_pk_init[j] = (ull)h2_(W[k0], W[k0 + 1]) | ((ull)h2_(W[k0 + 8], W[k0 + 9]) << 32);
            } else {
                int jj = j - 2048;
                int hf = jj >> 9, nt = (jj >> 7) & 3, kk = (jj >> 5) & 3, ln = jj & 31;
                int nn = hf * 32 + nt * 8 + (ln >> 2);
                int k0 = kk * 16 + 2 * (ln & 3);
                const float* W = w2 + (size_t)nn * 64;
                g_pk_init[j] = (ull)h2_(W[k0], W[k0 + 1]) | ((ull)h2_(W[k0 + 8], W[k0 + 9]) << 32);
            }
        } else if (i < 11072) {
            int j = i - 10752;
            float v;
            if (j < 128)      v = bih[j] + bhh[j];
            else if (j < 192) v = bih[128 + (j - 128)];
            else if (j < 256) v = bhh[128 + (j - 192)];
            else              v = cb[j - 256];
            g_bias_node[j] = v;
        } else if (i < 11200) {
            int j = i - 11072;
            g_bias_init[j] = (j < 64) ? b1[j] : b2[j - 64];
        } else if (i < 11584) {
            int j = i - 11200;
            int ntg = j >> 7, kk = (j >> 5) & 3, ln = j & 31;
            int nn = ntg * 8 + (ln >> 2);
            int k0 = kk * 16 + 2 * (ln & 3);
            float v[4];
            #pragma unroll
            for (int d = 0; d < 4; d++) {
                int k = k0 + (d >> 1) * 8 + (d & 1);
                v[d] = (nn < 20) ? bondemb[nn * 64 + k] : 0.0f;
            }
            g_pk_node[PB_OFF + j] = (ull)h2_(v[0], v[1]) | ((ull)h2_(v[2], v[3]) << 32);
        } else if (i < 11584 + E) {
            atomicAdd(&g_deg[ei[E + (i - 11584)]], 1.0f);
        } else {
            atomicAdd(&g_cntb[batch[i - 11584 - E]], 1.0f);
        }
    }
}

__global__ void recip_kernel(int n, int G) {
    int i = blockIdx.x * blockDim.x + threadIdx.x;
    if (i < n) {
        g_rdeg[i] = 1.0f / fmaxf(g_deg[i], 1.0f);
        g_deg[i] = 0.0f;
    }
    if (i < G) {
        g_rcnt[i] = 1.0f / fmaxf(g_cntb[i], 1.0f);
        g_cntb[i] = 0.0f;
    }
}

// ---- P-pass: P strip from fragment tile -> g_P ----
__device__ __forceinline__ void p_pass(const uint4* strip, const ull* pkP,
                                       int half, int lane, int nb0, int p, int n)
{
    float pacc[8];
    #pragma unroll
    for (int t = 0; t < 8; t++) pacc[t] = 0.0f;
    const int nnt = (half == 0) ? 2 : 1;
    #pragma unroll
    for (int kk = 0; kk < 4; kk++) {
        uint32_t a[4];
        load_frag16(a, strip, kk, lane);
        for (int t = 0; t < nnt; t++) {
            int ntg = half * 2 + t;
            mma16(pacc + t * 4, a, pkP[ntg * 128 + kk * 32 + lane]);
        }
    }
    int arow = p * 16 + (lane >> 2);
    for (int t = 0; t < nnt; t++) {
        int ntg = half * 2 + t;
        int colp = ntg * 8 + (lane & 3) * 2;
        if (colp < 20) {
            #pragma unroll
            for (int qq = 0; qq < 2; qq++) {
                int gr = nb0 + arow + qq * 8;
                if (gr < n)
                    *(float2*)(g_P + (size_t)gr * 20 + colp) =
                        make_float2(pacc[t * 4 + qq * 2], pacc[t * 4 + qq * 2 + 1]);
            }
        }
    }
}

// ---------------- init MLP + P ---------------------------------------------------
__global__ void __launch_bounds__(512, 1) init_mma(
    const int* __restrict__ x, const int* __restrict__ batch,
    const float* __restrict__ vec, const float* __restrict__ blockemb, int n)
{
    ull* pk   = (ull*)smem_raw;        // [3456]: w1 2048 | w2 1024 | bond-P 384
    ull* in_f = pk + 3456;             // [8][512]
    ull* o1_f = in_f + 4096;           // [8][256]
    float* b1s = (float*)(o1_f + 2048);
    float* b2s = b1s + 64;

    const int tid  = threadIdx.x;
    const int w    = tid >> 5;
    const int lane = tid & 31;
    const int p    = w & 7;
    const int half = w >> 3;
    const int n0   = half * 32;

    for (int i = tid; i < 3072; i += 512) pk[i] = g_pk_init[i];
    for (int i = tid; i < 384; i += 512)  pk[3072 + i] = g_pk_node[PB_OFF + i];
    if (tid < 128) b1s[tid] = g_bias_init[tid];
    __syncthreads();

    const ull* w1pk = pk;
    const ull* w2pk = pk + 2048;
    const ull* pkP  = pk + 3072;

    const int ntiles = (n + 127) >> 7;
    for (int tile = blockIdx.x; tile < ntiles; tile += gridDim.x) {
        const int nb0 = tile << 7;
        {
            int row = tid >> 2, cpart = (tid & 3) * 32, gr = nb0 + row;
            int strip = row >> 4, rr = row & 15;
            uint32_t* sf = (uint32_t*)(in_f + strip * 512);
            if (gr < n) {
                const float* src = (cpart < 64)
                    ? (blockemb + (size_t)x[gr] * 64 + cpart)
                    : (vec + (size_t)batch[gr] * 64 + (cpart - 64));
                #pragma unroll
                for (int c = 0; c < 8; c++) {
                    float4 qv = ((const float4*)src)[c];
                    int f = cpart + c * 4;
                    fstore16(sf, rr, f,     h2_(qv.x, qv.y));
                    fstore16(sf, rr, f + 2, h2_(qv.z, qv.w));
                }
            } else {
                #pragma unroll
                for (int c = 0; c < 16; c++)
                    fstore16(sf, rr, cpart + c * 2, 0u);
            }
        }
        __syncthreads();

        float racc[16];
        #pragma unroll
        for (int t = 0; t < 16; t++) racc[t] = 0.0f;
        const uint4* istrip = (const uint4*)(in_f + p * 512);
        #pragma unroll
        for (int kk = 0; kk < 8; kk++) {
            uint32_t a[4];
            load_frag16(a, istrip, kk, lane);
            #pragma unroll
            for (int nt = 0; nt < 4; nt++)
                mma16(racc + nt * 4, a, w1pk[half * 1024 + nt * 256 + kk * 32 + lane]);
        }
        {
            uint32_t* of = (uint32_t*)(o1_f + p * 256);
            int rr0 = lane >> 2;
            #pragma unroll
            for (int nt = 0; nt < 4; nt++) {
                int colb = n0 + nt * 8 + (lane & 3) * 2;
                float c0 = b1s[colb], c1 = b1s[colb + 1];
                #pragma unroll
                for (int qq = 0; qq < 2; qq++)
                    fstore16(of, rr0 + qq * 8, colb,
                             h2_(leakyf_(racc[nt * 4 + qq * 2] + c0),
                                 leakyf_(racc[nt * 4 + qq * 2 + 1] + c1)));
            }
        }
        __syncthreads();

        float acc2[16];
        #pragma unroll
        for (int t = 0; t < 16; t++) acc2[t] = 0.0f;
        const uint4* ostrip = (const uint4*)(o1_f + p * 256);
        #pragma unroll
        for (int kk = 0; kk < 4; kk++) {
            uint32_t a[4];
            load_frag16(a, ostrip, kk, lane);
            #pragma unroll
            for (int nt = 0; nt < 4; nt++)
                mma16(acc2 + nt * 4, a, w2pk[half * 512 + nt * 128 + kk * 32 + lane]);
        }
        // h0 = acc2 + bias -> g_h16 (packed h2); stash h2 for P pass
        uint32_t hh[8];
        #pragma unroll
        for (int nt = 0; nt < 4; nt++) {
            int colb = n0 + nt * 8 + (lane & 3) * 2;
            float c0 = b2s[colb], c1 = b2s[colb + 1];
            #pragma unroll
            for (int qq = 0; qq < 2; qq++) {
                int gr = nb0 + p * 16 + (lane >> 2) + qq * 8;
                uint32_t u = h2_(acc2[nt * 4 + qq * 2] + c0, acc2[nt * 4 + qq * 2 + 1] + c1);
                hh[nt * 2 + qq] = u;
                if (gr < n) g_h16[(size_t)gr * 32 + (colb >> 1)] = u;
            }
        }
        __syncthreads();
        {
            uint32_t* of = (uint32_t*)(o1_f + p * 256);
            int rr0 = lane >> 2;
            #pragma unroll
            for (int nt = 0; nt < 4; nt++) {
                int colb = n0 + nt * 8 + (lane & 3) * 2;
                #pragma unroll
                for (int qq = 0; qq < 2; qq++)
                    fstore16(of, rr0 + qq * 8, colb, hh[nt * 2 + qq]);
            }
        }
        __syncthreads();
        p_pass(ostrip, pkP, half, lane, nb0, p, n);
        __syncthreads();
    }
}

// ---------------- edge kernel: 2 edges/thread, scalar P lookup ------------------
__global__ void edge_kernel(const int* __restrict__ ei, const int* __restrict__ ea, int E)
{
    int idx = blockIdx.x * blockDim.x + threadIdx.x;
    int halfE = (E + 1) >> 1;
    #pragma unroll
    for (int r = 0; r < 2; r++) {
        int e = idx + r * halfE;
        if (e < E) {
            int src = ei[e], dst = ei[E + e];
            int2 a = ((const int2*)ea)[e];
            float s = __ldg(&g_P[(size_t)src * 20 + a.x]) * __ldg(&g_rdeg[dst]);
            atomicAdd(&g_sacc[(size_t)dst * 20 + a.y], s);
        }
    }
}

// ---------------- node kernel ----------------------------------------------------
__global__ void __launch_bounds__(512, 1) node_mma(
    const int* __restrict__ batch,
    float* __restrict__ out, int n, int last)
{
    ull* pk  = (ull*)smem_raw;          // [8064]
    ull* h_f = pk + 8064;
    ull* m_f = h_f + 2048;
    ull* s_f = m_f + 2048;
    float* br_s  = (float*)(s_f + 1024);
    float* bz_s  = br_s + 64;
    float* bin_s = bz_s + 64;
    float* bhn_s = bin_s + 64;
    float* cb_s  = bhn_s + 64;

    const int tid  = threadIdx.x;
    const int w    = tid >> 5;
    const int lane = tid & 31;
    // GEMM1 / P-pass mapping
    const int p    = w & 7;
    const int half = w >> 3;
    const int n0   = half * 32;
    // GEMM2 mapping: 32 rows x 16 cols per warp
    const int rs   = w & 3;
    const int cq   = w >> 2;
    const int hfq  = cq >> 1;
    const int ntb  = (cq & 1) * 2;

    for (int i = tid; i < 8064; i += 512) pk[i] = g_pk_node[i];
    if (tid < 320) br_s[tid] = g_bias_node[tid];
    __syncthreads();

    const int ntiles = (n + 127) >> 7;
    for (int tile = blockIdx.x; tile < ntiles; tile += gridDim.x) {
        const int nb0 = tile << 7;

        // H tile from g_h16 -> fragment smem (no cvt)
        {
            int row = tid >> 2, gr = nb0 + row;
            int strip = row >> 4, rr = row & 15;
            int c8 = (tid & 3) * 8;   // uint32 index base within row
            uint32_t* sf = (uint32_t*)(h_f + strip * 256);
            if (gr < n) {
                const uint4* hp = (const uint4*)(g_h16 + (size_t)gr * 32 + c8);
                uint4 u0 = hp[0], u1 = hp[1];
                int f = c8 * 2;
                fstore16(sf, rr, f,      u0.x); fstore16(sf, rr, f + 2,  u0.y);
                fstore16(sf, rr, f + 4,  u0.z); fstore16(sf, rr, f + 6,  u0.w);
                fstore16(sf, rr, f + 8,  u1.x); fstore16(sf, rr, f + 10, u1.y);
                fstore16(sf, rr, f + 12, u1.z); fstore16(sf, rr, f + 14, u1.w);
            } else {
                #pragma unroll
                for (int c = 0; c < 8; c++)
                    fstore16(sf, rr, c8 * 2 + c * 2, 0u);
            }
        }
        // S tile (20 -> pad 32); zero g_sacc for next step
        {
            int row = tid >> 2, gr = nb0 + row;
            int c0 = (tid & 3) * 8;
            int strip = row >> 4, rr = row & 15;
            uint32_t* sf = (uint32_t*)(s_f + strip * 128);
            float* sp = g_sacc + (size_t)gr * 20;
            #pragma unroll
            for (int c = 0; c < 4; c++) {
                int f = c0 + 2 * c;
                float va = 0.0f, vb = 0.0f;
                if (gr < n) {
                    if (f < 20)     { va = sp[f];     sp[f] = 0.0f; }
                    if (f + 1 < 20) { vb = sp[f + 1]; sp[f + 1] = 0.0f; }
                }
                fstore16(sf, rr, f, h2_(va, vb));
            }
        }
        __syncthreads();

        // early prefetch for GEMM2 mapping: h_old (fp16), batch, rcnt
        uint32_t hofu[8];
        float rc[4];
        int bg[4];
        #pragma unroll
        for (int rf = 0; rf < 2; rf++) {
            #pragma unroll
            for (int qq = 0; qq < 2; qq++) {
                int gr = nb0 + rs * 32 + rf * 16 + (lane >> 2) + qq * 8;
                int gi = rf * 2 + qq;
                bg[gi] = (last && gr < n) ? batch[gr] : 0;
                rc[gi] = last ? __ldg(&g_rcnt[bg[gi]]) : 1.0f;
                #pragma unroll
                for (int t = 0; t < 2; t++) {
                    int colb = cq * 16 + t * 8 + (lane & 3) * 2;
                    hofu[rf * 4 + t * 2 + qq] = (gr < n)
                        ? __ldg(&g_h16[(size_t)gr * 32 + (colb >> 1)]) : 0u;
                }
            }
        }

        const uint4* hstrip = (const uint4*)(h_f + p * 256);
        const uint4* sstrip = (const uint4*)(s_f + p * 128);

        // GEMM1: R = H @ root + S @ bond (old mapping: 16r x 32c)
        float racc[16];
        #pragma unroll
        for (int t = 0; t < 16; t++) racc[t] = 0.0f;
        #pragma unroll
        for (int kk = 0; kk < 4; kk++) {
            uint32_t a[4];
            load_frag16(a, hstrip, kk, lane);
            #pragma unroll
            for (int nt = 0; nt < 4; nt++)
                mma16(racc + nt * 4, a, pk[A_ROOT * 1024 + half * 512 + nt * 128 + kk * 32 + lane]);
        }
        #pragma unroll
        for (int kk = 0; kk < 2; kk++) {
            uint32_t a[4];
            load_frag16(a, sstrip, kk, lane);
            #pragma unroll
            for (int nt = 0; nt < 4; nt++)
                mma16(racc + nt * 4, a, pk[BOND_OFF + half * 256 + nt * 64 + kk * 32 + lane]);
        }
        {
            uint32_t* mf = (uint32_t*)(m_f + p * 256);
            int rr0 = lane >> 2;
            #pragma unroll
            for (int nt = 0; nt < 4; nt++) {
                int colb = n0 + nt * 8 + (lane & 3) * 2;
                float cb0 = cb_s[colb], cb1 = cb_s[colb + 1];
                #pragma unroll
                for (int qq = 0; qq < 2; qq++)
                    fstore16(mf, rr0 + qq * 8, colb,
                             h2_(leakyf_(racc[nt * 4 + qq * 2] + cb0),
                                 leakyf_(racc[nt * 4 + qq * 2 + 1] + cb1)));
            }
        }
        __syncthreads();

        // GEMM2: gates, 32r x 16c warp tile (halved B-fragment traffic)
        float rg[16], zg[16], ig[16], hg[16];
        #pragma unroll
        for (int t = 0; t < 16; t++) { rg[t] = zg[t] = ig[t] = hg[t] = 0.0f; }
        #pragma unroll
        for (int kk = 0; kk < 4; kk++) {
            uint32_t aM[2][4], aH[2][4];
            #pragma unroll
            for (int rf = 0; rf < 2; rf++) {
                load_frag16(aM[rf], (const uint4*)(m_f + (2 * rs + rf) * 256), kk, lane);
                load_frag16(aH[rf], (const uint4*)(h_f + (2 * rs + rf) * 256), kk, lane);
            }
            #pragma unroll
            for (int t = 0; t < 2; t++) {
                int o = hfq * 512 + (ntb + t) * 128 + kk * 32 + lane;
                ull bir = pk[A_IHR * 1024 + o], bhr = pk[A_HHR * 1024 + o];
                ull biz = pk[A_IHZ * 1024 + o], bhz = pk[A_HHZ * 1024 + o];
                ull bin = pk[A_IHN * 1024 + o], bhn = pk[A_HHN * 1024 + o];
                #pragma unroll
                for (int rf = 0; rf < 2; rf++) {
                    float* rgp = rg + rf * 8 + t * 4;
                    float* zgp = zg + rf * 8 + t * 4;
                    float* igp = ig + rf * 8 + t * 4;
                    float* hgp = hg + rf * 8 + t * 4;
                    mma16(rgp, aM[rf], bir); mma16(rgp, aH[rf], bhr);
                    mma16(zgp, aM[rf], biz); mma16(zgp, aH[rf], bhz);
                    mma16(igp, aM[rf], bin); mma16(hgp, aH[rf], bhn);
                }
            }
        }

        // epilogue: GRU gate math (GEMM2 mapping); write h16 (or pool)
        uint32_t o2h[8];
        #pragma unroll
        for (int rf = 0; rf < 2; rf++) {
            #pragma unroll
            for (int t = 0; t < 2; t++) {
                int colb = cq * 16 + t * 8 + (lane & 3) * 2;
                float br0 = br_s[colb], br1 = br_s[colb + 1];
                float bz0 = bz_s[colb], bz1 = bz_s[colb + 1];
                float bi0 = bin_s[colb], bi1 = bin_s[colb + 1];
                float bh0 = bhn_s[colb], bh1 = bhn_s[colb + 1];
                #pragma unroll
                for (int qq = 0; qq < 2; qq++) {
                    int gr = nb0 + rs * 32 + rf * 16 + (lane >> 2) + qq * 8;
                    int idx = rf * 8 + t * 4 + qq * 2;
                    int gi = rf * 2 + qq;
                    float2 ho = h2f_(hofu[rf * 4 + t * 2 + qq]);
                    float r0v = sigf_(rg[idx]     + br0);
                    float r1v = sigf_(rg[idx + 1] + br1);
                    float z0v = sigf_(zg[idx]     + bz0);
                    float z1v = sigf_(zg[idx + 1] + bz1);
                    float n0v = tanhf_(ig[idx]     + bi0 + r0v * (hg[idx]     + bh0));
                    float n1v = tanhf_(ig[idx + 1] + bi1 + r1v * (hg[idx + 1] + bh1));
                    float ox = (1.0f - z0v) * n0v + z0v * ho.x;
                    float oy = (1.0f - z1v) * n1v + z1v * ho.y;
                    uint32_t u = h2_(ox, oy);
                    o2h[rf * 4 + t * 2 + qq] = u;
                    if (gr < n) {
                        if (last) {
                            float* op = out + (size_t)bg[gi] * 64 + colb;
                            asm volatile("red.global.add.v2.f32 [%0], {%1,%2};"
                                         :: "l"(op), "f"(ox * rc[gi]), "f"(oy * rc[gi]) : "memory");
                        } else {
                            g_h16[(size_t)gr * 32 + (colb >> 1)] = u;
                        }
                    }
                }
            }
        }

        if (!last) {
            __syncthreads();   // all GEMM2 reads of h_f done
            {
                #pragma unroll
                for (int rf = 0; rf < 2; rf++) {
                    uint32_t* sf = (uint32_t*)(h_f + (2 * rs + rf) * 256);
                    int rr0 = lane >> 2;
                    #pragma unroll
                    for (int t = 0; t < 2; t++) {
                        int colb = cq * 16 + t * 8 + (lane & 3) * 2;
                        #pragma unroll
                        for (int qq = 0; qq < 2; qq++)
                            fstore16(sf, rr0 + qq * 8, colb, o2h[rf * 4 + t * 2 + qq]);
                    }
                }
            }
            __syncthreads();
            p_pass(hstrip, pk + PB_OFF, half, lane, nb0, p, n);
        }
        __syncthreads();
    }
}

// ---------------- launch ----------------------------------------------------------
extern "C" void kernel_launch(void* const* d_in, const int* in_sizes, int n_in,
                              void* d_out, int out_size)
{
    const int*   x        = (const int*)d_in[0];
    const int*   ei       = (const int*)d_in[1];
    const int*   ea       = (const int*)d_in[2];
    const int*   batch    = (const int*)d_in[3];
    const float* vec      = (const float*)d_in[4];
    const float* blockemb = (const float*)d_in[5];
    const float* bondemb  = (const float*)d_in[6];
    const float* w1       = (const float*)d_in[7];
    const float* b1       = (const float*)d_in[8];
    const float* w2       = (const float*)d_in[9];
    const float* b2       = (const float*)d_in[10];
    const float* root     = (const float*)d_in[11];
    const float* cb       = (const float*)d_in[12];
    const float* wih      = (const float*)d_in[13];
    const float* whh      = (const float*)d_in[14];
    const float* bih      = (const float*)d_in[15];
    const float* bhh      = (const float*)d_in[16];

    const int n = in_sizes[0];
    const int E = in_sizes[1] / 2;
    const int G = in_sizes[4] / 64;

    cudaFuncSetAttribute(init_mma, cudaFuncAttributeMaxDynamicSharedMemorySize, INIT_SMEM);
    cudaFuncSetAttribute(node_mma, cudaFuncAttributeMaxDynamicSharedMemorySize, NODE_SMEM);

    cudaMemsetAsync(d_out, 0, (size_t)out_size * sizeof(float));

    prep_kernel<<<296, 512>>>(root, cb, wih, whh, bih, bhh, w1, b1, w2, b2,
                              bondemb, ei, batch, E, n);
    recip_kernel<<<(n + 255) / 256, 256>>>(n, G);

    init_mma<<<148, 512, INIT_SMEM>>>(x, batch, vec, blockemb, n);

    const int halfE = (E + 1) / 2;
    for (int s = 0; s < 4; s++) {
        edge_kernel<<<(halfE + 255) / 256, 256>>>(ei, ea, E);
        node_mma<<<148, 512, NODE_SMEM>>>(batch, (float*)d_out, n, s == 3 ? 1 : 0);
    }
}